// round 7
// baseline (speedup 1.0000x reference)
#include <cuda_runtime.h>
#include <cstdint>

#define NNODES 20000
#define NEDGES 320000
#define DM 128
#define PREDL 24

// ---------------- device scratch ----------------------------------------------
__device__ float g_h[NNODES * DM];
__device__ float g_e[(size_t)NEDGES * DM];
__device__ float g_agg[NNODES * DM];
__device__ float g_cnt[NNODES];
__device__ float g_hs[NNODES * DM];   // h @ Wp_s  (per current layer)
__device__ float g_hr[NNODES * DM];   // h @ Wp_r
__device__ float g_wt[85 * 4096];     // fragment-layout weights (tf32-rounded)

// weight blob offsets (in 4096-float chunks)
#define C_WPE  0     // edge proj  2 x 12  (per layer: 0-3 = Wpe, 4-7 = Wps, 8-11 = Wpr)
#define C_WPN  24    // node proj  2 x 8
#define C_WME  40    // edge mlp   4 x 4
#define C_WMN  56    // node mlp   4 x 4
#define C_WOUT 72    // out mlp    4
#define C_WEMB 76    // node emb   9

// ---------------- smem float offsets -------------------------------------------
#define F_IDX 0                 // 256 ints (snd|rcv) or 128 inv floats
#define F_SUM 256               // 512 (4 warps per row)
#define F_SQ  768               // 512
#define F_PAR 1280              // up to 896 per-col params
#define F_SW  2176              // 2 x 4096 W double buffer
#define F_SG  (F_SW + 8192)     // 2 x 4096 gather double buffer
#define F_ET  (F_SG + 8192)     // 4 x 4096 residual / scratch tile (exact f32)
#define F_XT  (F_ET + 16384)    // 4 x 4096 activation tile
#define SMEMB ((F_XT + 16384) * 4)   // 205312 bytes

// ---------------- helpers ------------------------------------------------------
__device__ __forceinline__ uint32_t tfr(float x) {
    uint32_t r;
    asm("cvt.rna.tf32.f32 %0, %1;" : "=r"(r) : "f"(x));
    return r;
}
__device__ __forceinline__ float tff(float x) { return __uint_as_float(tfr(x)); }

__device__ __forceinline__ uint32_t smem_u32(const void* p) {
    uint32_t a;
    asm("{ .reg .u64 t; cvta.to.shared.u64 t, %1; cvt.u32.u64 %0, t; }"
        : "=r"(a) : "l"(p));
    return a;
}

__device__ __forceinline__ void mma8(float c[4], uint32_t a0, uint32_t a1,
                                     uint32_t a2, uint32_t a3,
                                     uint32_t b0, uint32_t b1) {
    asm volatile(
        "mma.sync.aligned.m16n8k8.row.col.f32.tf32.tf32.f32 "
        "{%0,%1,%2,%3}, {%4,%5,%6,%7}, {%8,%9}, {%0,%1,%2,%3};"
        : "+f"(c[0]), "+f"(c[1]), "+f"(c[2]), "+f"(c[3])
        : "r"(a0), "r"(a1), "r"(a2), "r"(a3), "r"(b0), "r"(b1));
}

__device__ __forceinline__ float geluf(float x) {
    float x3 = x * x * x;
    return 0.5f * x * (1.0f + tanhf(0.7978845608028654f * (x + 0.044715f * x3)));
}

__device__ __forceinline__ int fAg(int g) { return (g ^ (g >> 2)) & 3; }

// A-fragment index within a 4096-float chunk, for (row 0..127, k_local 0..31)
__device__ __forceinline__ int aidx(int row, int kl) {
    int wm = row >> 5, mm = (row >> 4) & 1, r8 = (row >> 3) & 1, g = row & 7;
    int kk = kl >> 3, k4 = (kl >> 2) & 1, tig = kl & 3;
    return (((kk * 4 + wm) * 2 + mm) << 7) + ((g * 4 + (tig ^ fAg(g))) << 2)
           + r8 + (k4 << 1);
}
// B-fragment index (16-warp layout): wn = n>>5 (4 warps x 32 cols)
__device__ __forceinline__ int bidx(int kl, int n) {
    int kk = kl >> 3, k4 = (kl >> 2) & 1, tig = kl & 3;
    int wn = n >> 5, ntp = (n >> 4) & 1, ntb = (n >> 3) & 1, gq = n & 7;
    return (((kk * 4 + wn) * 2 + ntp) << 7) + ((gq * 4 + tig) << 2)
           + ntb * 2 + k4;
}

// cp.async 16B helpers
#define CP16(daddr, src) asm volatile( \
    "cp.async.cg.shared.global [%0], [%1], 16;" :: "r"(daddr), "l"(src))
#define CP_COMMIT() asm volatile("cp.async.commit_group;" ::: "memory")
#define CP_WAIT0()  asm volatile("cp.async.wait_group 0;" ::: "memory")

// async-stage one 16KB pre-fragmented W chunk (512 threads x 32B)
__device__ __forceinline__ void copy_w_async(uint32_t dsts,
                                             const float* __restrict__ src,
                                             int tid) {
    CP16(dsts + tid * 16, src + tid * 4);
    CP16(dsts + (tid + 512) * 16, src + (tid + 512) * 4);
}

// one 32-wide K chunk; warp covers 32 rows x 32 cols
__device__ __forceinline__ void chunk_mma(const float* __restrict__ sA,
                                          const float* __restrict__ sW,
                                          float C[2][4][4], int wm, int wn,
                                          int lane, int pl4) {
#pragma unroll
    for (int kk = 0; kk < 4; kk++) {
        float4 b0 = *(const float4*)(sW + (((kk * 4 + wn) * 2 + 0) << 7)
                                     + (lane << 2));
        float4 b1 = *(const float4*)(sW + (((kk * 4 + wn) * 2 + 1) << 7)
                                     + (lane << 2));
#pragma unroll
        for (int mm = 0; mm < 2; mm++) {
            float4 av = *(const float4*)(sA + (((kk * 4 + wm) * 2 + mm) << 7) + pl4);
            uint32_t a0 = __float_as_uint(av.x), a1 = __float_as_uint(av.y);
            uint32_t a2 = __float_as_uint(av.z), a3 = __float_as_uint(av.w);
            mma8(C[mm][0], a0, a1, a2, a3,
                 __float_as_uint(b0.x), __float_as_uint(b0.y));
            mma8(C[mm][1], a0, a1, a2, a3,
                 __float_as_uint(b0.z), __float_as_uint(b0.w));
            mma8(C[mm][2], a0, a1, a2, a3,
                 __float_as_uint(b1.x), __float_as_uint(b1.y));
            mma8(C[mm][3], a0, a1, a2, a3,
                 __float_as_uint(b1.z), __float_as_uint(b1.w));
        }
    }
}

// stage 8 gathered floats (row r, kl = q4*8..+7) into A-frag chunk, tf32
__device__ __forceinline__ void stage_Af8(float* chunk, const float* __restrict__ src,
                                          int r, int q4) {
    float4 v0 = *(const float4*)(src);
    float4 v1 = *(const float4*)(src + 4);
    chunk[aidx(r, q4 * 8 + 0)] = tff(v0.x);
    chunk[aidx(r, q4 * 8 + 1)] = tff(v0.y);
    chunk[aidx(r, q4 * 8 + 2)] = tff(v0.z);
    chunk[aidx(r, q4 * 8 + 3)] = tff(v0.w);
    chunk[aidx(r, q4 * 8 + 4)] = tff(v1.x);
    chunk[aidx(r, q4 * 8 + 5)] = tff(v1.y);
    chunk[aidx(r, q4 * 8 + 6)] = tff(v1.z);
    chunk[aidx(r, q4 * 8 + 7)] = tff(v1.w);
}
__device__ __forceinline__ void stage_Af8s(float* chunk, const float* __restrict__ src,
                                           int r, int q4, float sc) {
    float4 v0 = *(const float4*)(src);
    float4 v1 = *(const float4*)(src + 4);
    chunk[aidx(r, q4 * 8 + 0)] = tff(v0.x * sc);
    chunk[aidx(r, q4 * 8 + 1)] = tff(v0.y * sc);
    chunk[aidx(r, q4 * 8 + 2)] = tff(v0.z * sc);
    chunk[aidx(r, q4 * 8 + 3)] = tff(v0.w * sc);
    chunk[aidx(r, q4 * 8 + 4)] = tff(v1.x * sc);
    chunk[aidx(r, q4 * 8 + 5)] = tff(v1.y * sc);
    chunk[aidx(r, q4 * 8 + 6)] = tff(v1.z * sc);
    chunk[aidx(r, q4 * 8 + 7)] = tff(v1.w * sc);
}

// stage 32 cols (one chunk) of a 128-wide row EXACT into A-frag chunk
__device__ __forceinline__ void stage_E32(float* chunk, const float* __restrict__ src,
                                          int r) {
#pragma unroll
    for (int i = 0; i < 8; i++) {
        float4 v = *(const float4*)(src + i * 4);
        chunk[aidx(r, i * 4 + 0)] = v.x;
        chunk[aidx(r, i * 4 + 1)] = v.y;
        chunk[aidx(r, i * 4 + 2)] = v.z;
        chunk[aidx(r, i * 4 + 3)] = v.w;
    }
}

// write C fragments into tile at fbase (cvt: 1 = tf32 round, 0 = exact)
__device__ __forceinline__ void write_T(float C[2][4][4], float* smf, int fbase,
                                        int wm, int wn, int lane, int cvt) {
    int g = lane >> 2, q = lane & 3;
#pragma unroll
    for (int mm = 0; mm < 2; mm++)
#pragma unroll
        for (int hx = 0; hx < 2; hx++) {
            int row = wm * 32 + mm * 16 + hx * 8 + g;
#pragma unroll
            for (int nt = 0; nt < 4; nt++)
#pragma unroll
                for (int s = 0; s < 2; s++) {
                    int col = wn * 32 + nt * 8 + q * 2 + s;
                    float v = C[mm][nt][hx * 2 + s];
                    smf[fbase + (col >> 5) * 4096 + aidx(row, col & 31)] =
                        cvt ? tff(v) : v;
                }
        }
}

// gelu + LayerNorm over 128-wide rows (4 warps per row combine via smem)
__device__ __forceinline__ void gelu_ln_ep(float C[2][4][4], float* smf,
                                           int wm, int wn, int lane,
                                           int pb, int pg, int pbe) {
    int g = lane >> 2, q = lane & 3;
    float* sSum = smf + F_SUM;
    float* sSq  = smf + F_SQ;
#pragma unroll
    for (int mm = 0; mm < 2; mm++)
#pragma unroll
        for (int hx = 0; hx < 2; hx++) {
            float ps = 0.f, pq = 0.f;
#pragma unroll
            for (int nt = 0; nt < 4; nt++)
#pragma unroll
                for (int s = 0; s < 2; s++) {
                    int col = wn * 32 + nt * 8 + q * 2 + s;
                    float v = geluf(C[mm][nt][hx * 2 + s] + smf[pb + col]);
                    C[mm][nt][hx * 2 + s] = v;
                    ps += v; pq += v * v;
                }
            ps += __shfl_xor_sync(0xffffffffu, ps, 1);
            ps += __shfl_xor_sync(0xffffffffu, ps, 2);
            pq += __shfl_xor_sync(0xffffffffu, pq, 1);
            pq += __shfl_xor_sync(0xffffffffu, pq, 2);
            if (q == 0) {
                int row = wm * 32 + mm * 16 + hx * 8 + g;
                sSum[row * 4 + wn] = ps;
                sSq[row * 4 + wn]  = pq;
            }
        }
    __syncthreads();
#pragma unroll
    for (int mm = 0; mm < 2; mm++)
#pragma unroll
        for (int hx = 0; hx < 2; hx++) {
            int row = wm * 32 + mm * 16 + hx * 8 + g;
            float m = (sSum[row * 4] + sSum[row * 4 + 1]
                       + sSum[row * 4 + 2] + sSum[row * 4 + 3]) * (1.0f / 128.0f);
            float qv = (sSq[row * 4] + sSq[row * 4 + 1]
                        + sSq[row * 4 + 2] + sSq[row * 4 + 3]) * (1.0f / 128.0f);
            float rs = rsqrtf(qv - m * m + 1e-5f);
#pragma unroll
            for (int nt = 0; nt < 4; nt++)
#pragma unroll
                for (int s = 0; s < 2; s++) {
                    int col = wn * 32 + nt * 8 + q * 2 + s;
                    C[mm][nt][hx * 2 + s] =
                        (C[mm][nt][hx * 2 + s] - m) * rs * smf[pg + col] + smf[pbe + col];
                }
        }
}

#define ZERO_C() do { \
    _Pragma("unroll") for (int _m = 0; _m < 2; _m++) \
    _Pragma("unroll") for (int _n = 0; _n < 4; _n++) \
    _Pragma("unroll") for (int _s = 0; _s < 4; _s++) C[_m][_n][_s] = 0.f; } while (0)

// K=128 GEMM with A at tile abase (4 chunks), W async-streamed double-buffered
__device__ __forceinline__ void gemm_T4(float* smf, uint32_t swb,
                                        const float* __restrict__ W,
                                        float C[2][4][4], int tid, int abase,
                                        int wm, int wn, int lane, int pl4) {
    copy_w_async(swb, W, tid); CP_COMMIT();
    CP_WAIT0(); __syncthreads();
#pragma unroll 1
    for (int c = 0; c < 4; c++) {
        if (c < 3) {
            copy_w_async(swb + ((c + 1) & 1) * 16384, W + (c + 1) * 4096, tid);
            CP_COMMIT();
        }
        chunk_mma(smf + abase + c * 4096, smf + F_SW + (c & 1) * 4096,
                  C, wm, wn, lane, pl4);
        CP_WAIT0();
        __syncthreads();
    }
}

// row-major readback base for A-frag reads
#define ROWBASE(r, rb, fg) \
    int rb = ((((r) >> 5) * 2 + (((r) >> 4) & 1)) << 7) + (((r) & 7) << 4) \
             + (((r) >> 3) & 1); \
    int fg = fAg((r) & 7)
#define AFIDX(rb, fg, j) \
    (((j) >> 3) * 1024 + (rb) + ((((j) & 3) ^ (fg)) << 2) + ((((j) >> 2) & 1) << 1))

#define RED4(p, f4) asm volatile( \
    "red.global.add.v4.f32 [%0], {%1,%2,%3,%4};" \
    :: "l"(p), "f"((f4).x), "f"((f4).y), "f"((f4).z), "f"((f4).w) : "memory")

// project current tile (XT, tf32) through W, write rows to gout (if in range)
__device__ __forceinline__ void tail_proj(float* smf, uint32_t swb,
                                          const float* __restrict__ W,
                                          float* __restrict__ gout,
                                          int tid, int wm, int wn, int lane,
                                          int pl4, int r, int q4, int rb, int fg,
                                          int inr, int base) {
    float C[2][4][4];
    ZERO_C();
    gemm_T4(smf, swb, W, C, tid, F_XT, wm, wn, lane, pl4);
    write_T(C, smf, F_ET, wm, wn, lane, 0);
    __syncthreads();
    if (inr) {
        const float* E = smf + F_ET + q4 * 4096;
        float* go = gout + (size_t)(base + r) * DM + q4 * 32;
#pragma unroll
        for (int qq = 0; qq < 8; qq++) {
            float4 f4;
            f4.x = E[AFIDX(rb, fg, qq * 4 + 0)];
            f4.y = E[AFIDX(rb, fg, qq * 4 + 1)];
            f4.z = E[AFIDX(rb, fg, qq * 4 + 2)];
            f4.w = E[AFIDX(rb, fg, qq * 4 + 3)];
            *(float4*)(go + qq * 4) = f4;
        }
    }
}

// ---------------- weight prep: W[K,128] -> B-frag chunks (tf32) ---------------
__global__ void prep_w(const float* __restrict__ W, float* __restrict__ dst) {
    int c = blockIdx.x, tid = threadIdx.x;
    int kl = tid >> 3, n0 = (tid & 7) * 16;
#pragma unroll
    for (int j = 0; j < 16; j++) {
        int n = n0 + j;
        dst[c * 4096 + bidx(kl, n)] = tff(W[(c * 32 + kl) * 128 + n]);
    }
}

// ---------------- edge kernel --------------------------------------------------
// e += MLP(e@Wpe + hs[snd] + hr[rcv] + bp); agg += e_new
__global__ __launch_bounds__(512, 1) void edge_k(
    float* __restrict__ e,
    const int* __restrict__ snd, const int* __restrict__ rcv,
    const float* __restrict__ hs, const float* __restrict__ hr,
    const float* __restrict__ wPe, const float* __restrict__ bp,
    const float* __restrict__ wM0, const float* __restrict__ b0,
    const float* __restrict__ g0, const float* __restrict__ be0,
    const float* __restrict__ wM1, const float* __restrict__ b1,
    const float* __restrict__ g1, const float* __restrict__ be1,
    float* __restrict__ agg)
{
    extern __shared__ float smf[];
    uint32_t swb = smem_u32(smf) + F_SW * 4;
    int tid = threadIdx.x, lane = tid & 31, wid = tid >> 5;
    int wm = wid & 3, wn = wid >> 2;
    int g = lane >> 2, tig = lane & 3;
    int pl4 = (g * 4 + (tig ^ fAg(g))) << 2;
    int base = blockIdx.x * 128;
    int r = tid >> 2, q4 = tid & 3;
    int* sI = (int*)smf;
    if (tid < 128) sI[tid] = snd[base + tid];
    else if (tid < 256) sI[tid] = rcv[base + tid - 128];
    if (tid < 128) {
        float* p = smf + F_PAR;
        p[tid] = bp[tid];        p[128 + tid] = b0[tid];
        p[256 + tid] = g0[tid];  p[384 + tid] = be0[tid];
        p[512 + tid] = b1[tid];  p[640 + tid] = g1[tid];
        p[768 + tid] = be1[tid];
    }
    stage_E32(smf + F_ET + q4 * 4096, e + (size_t)(base + r) * DM + q4 * 32, r);

    float C[2][4][4];
    ZERO_C();
    // GEMM1: e @ Wpe (K=128, A = ET exact; HW truncates to tf32)
    gemm_T4(smf, swb, wPe, C, tid, F_ET, wm, wn, lane, pl4);
    write_T(C, smf, F_XT, wm, wn, lane, 0);
    __syncthreads();
    // add gathered hs[snd], hr[rcv] + bias; tf32-round into XT
    ROWBASE(r, rb, fg);
    {
        const float* hsr = hs + (size_t)sI[r] * DM + q4 * 32;
        const float* hrr = hr + (size_t)sI[128 + r] * DM + q4 * 32;
        const float* bq  = smf + F_PAR + q4 * 32;
        float* X = smf + F_XT + q4 * 4096;
#pragma unroll
        for (int qq = 0; qq < 8; qq++) {
            float4 a = *(const float4*)(hsr + qq * 4);
            float4 b = *(const float4*)(hrr + qq * 4);
            int j0 = qq * 4;
            X[AFIDX(rb, fg, j0 + 0)] =
                tff(X[AFIDX(rb, fg, j0 + 0)] + a.x + b.x + bq[j0 + 0]);
            X[AFIDX(rb, fg, j0 + 1)] =
                tff(X[AFIDX(rb, fg, j0 + 1)] + a.y + b.y + bq[j0 + 1]);
            X[AFIDX(rb, fg, j0 + 2)] =
                tff(X[AFIDX(rb, fg, j0 + 2)] + a.z + b.z + bq[j0 + 2]);
            X[AFIDX(rb, fg, j0 + 3)] =
                tff(X[AFIDX(rb, fg, j0 + 3)] + a.w + b.w + bq[j0 + 3]);
        }
    }
    ZERO_C();
    gemm_T4(smf, swb, wM0, C, tid, F_XT, wm, wn, lane, pl4);   // MLP layer 0
    gelu_ln_ep(C, smf, wm, wn, lane, F_PAR + 128, F_PAR + 256, F_PAR + 384);
    write_T(C, smf, F_XT, wm, wn, lane, 1);
    ZERO_C();
    gemm_T4(smf, swb, wM1, C, tid, F_XT, wm, wn, lane, pl4);   // MLP layer 1
    gelu_ln_ep(C, smf, wm, wn, lane, F_PAR + 512, F_PAR + 640, F_PAR + 768);
    write_T(C, smf, F_XT, wm, wn, lane, 0);                    // exact
    __syncthreads();

    // residual + store + vector scatter (thread owns row r, chunk q4)
    {
        const float* X = smf + F_XT + q4 * 4096;
        const float* E = smf + F_ET + q4 * 4096;
        float* eo = e + (size_t)(base + r) * DM + q4 * 32;
        float* ag = agg + (size_t)sI[128 + r] * DM + q4 * 32;
#pragma unroll
        for (int qq = 0; qq < 8; qq++) {
            float4 f4;
            f4.x = X[AFIDX(rb, fg, qq * 4 + 0)] + E[AFIDX(rb, fg, qq * 4 + 0)];
            f4.y = X[AFIDX(rb, fg, qq * 4 + 1)] + E[AFIDX(rb, fg, qq * 4 + 1)];
            f4.z = X[AFIDX(rb, fg, qq * 4 + 2)] + E[AFIDX(rb, fg, qq * 4 + 2)];
            f4.w = X[AFIDX(rb, fg, qq * 4 + 3)] + E[AFIDX(rb, fg, qq * 4 + 3)];
            *(float4*)(eo + qq * 4) = f4;
            RED4(ag + qq * 4, f4);
        }
    }
}

// ---------------- node kernel --------------------------------------------------
// h += MLP(concat(h, agg/cnt)@Wpn + bp); optionally emit hs/hr for next layer
__global__ __launch_bounds__(512, 1) void node_k(
    float* __restrict__ h, const float* __restrict__ agg,
    const float* __restrict__ cnt,
    const float* __restrict__ wP, const float* __restrict__ bp,
    const float* __restrict__ wM0, const float* __restrict__ b0,
    const float* __restrict__ g0, const float* __restrict__ be0,
    const float* __restrict__ wM1, const float* __restrict__ b1,
    const float* __restrict__ g1, const float* __restrict__ be1,
    float* __restrict__ hs, float* __restrict__ hr,
    const float* __restrict__ wPs, const float* __restrict__ wPr,
    int tail)
{
    extern __shared__ float smf[];
    uint32_t swb = smem_u32(smf) + F_SW * 4;
    int tid = threadIdx.x, lane = tid & 31, wid = tid >> 5;
    int wm = wid & 3, wn = wid >> 2;
    int g = lane >> 2, tig = lane & 3;
    int pl4 = (g * 4 + (tig ^ fAg(g))) << 2;
    int base = blockIdx.x * 128;
    int r = tid >> 2, q4 = tid & 3;
    if (tid < 128) {
        int n = min(base + tid, NNODES - 1);
        smf[tid] = 1.0f / fmaxf(cnt[n], 1.0f);
        float* p = smf + F_PAR;
        p[tid] = bp[tid];        p[128 + tid] = b0[tid];
        p[256 + tid] = g0[tid];  p[384 + tid] = be0[tid];
        p[512 + tid] = b1[tid];  p[640 + tid] = g1[tid];
        p[768 + tid] = be1[tid];
    }
    int nr = min(base + r, NNODES - 1);
    stage_E32(smf + F_ET + q4 * 4096, h + (size_t)nr * DM + q4 * 32, r);

    float C[2][4][4];
    ZERO_C();
    // GEMM1: K=256 (chunks 0-3 = h exact from ET, 4-7 = agg/cnt staged)
    copy_w_async(swb, wP, tid); CP_COMMIT();
    CP_WAIT0(); __syncthreads();
#pragma unroll 1
    for (int c = 0; c < 8; c++) {
        if (c < 7) {
            int cn = c + 1;
            copy_w_async(swb + (cn & 1) * 16384, wP + cn * 4096, tid); CP_COMMIT();
            if (cn >= 4)
                stage_Af8s(smf + F_SG + (cn & 1) * 4096,
                           agg + (size_t)nr * DM + ((cn & 3) << 5) + q4 * 8,
                           r, q4, smf[r]);
        }
        const float* As = (c < 4) ? smf + F_ET + c * 4096
                                  : smf + F_SG + (c & 1) * 4096;
        chunk_mma(As, smf + F_SW + (c & 1) * 4096, C, wm, wn, lane, pl4);
        CP_WAIT0();
        __syncthreads();
    }
    // + bias -> XT (tf32)
    {
        int gq = lane & 3;
#pragma unroll
        for (int mm = 0; mm < 2; mm++)
#pragma unroll
            for (int hx = 0; hx < 2; hx++) {
                int row = wm * 32 + mm * 16 + hx * 8 + g;
#pragma unroll
                for (int nt = 0; nt < 4; nt++)
#pragma unroll
                    for (int s = 0; s < 2; s++) {
                        int col = wn * 32 + nt * 8 + gq * 2 + s;
                        smf[F_XT + (col >> 5) * 4096 + aidx(row, col & 31)] =
                            tff(C[mm][nt][hx * 2 + s] + smf[F_PAR + col]);
                    }
            }
    }
    ZERO_C();
    gemm_T4(smf, swb, wM0, C, tid, F_XT, wm, wn, lane, pl4);
    gelu_ln_ep(C, smf, wm, wn, lane, F_PAR + 128, F_PAR + 256, F_PAR + 384);
    write_T(C, smf, F_XT, wm, wn, lane, 1);
    ZERO_C();
    gemm_T4(smf, swb, wM1, C, tid, F_XT, wm, wn, lane, pl4);
    gelu_ln_ep(C, smf, wm, wn, lane, F_PAR + 512, F_PAR + 640, F_PAR + 768);
    write_T(C, smf, F_XT, wm, wn, lane, 0);
    __syncthreads();

    // new h = XT + ET -> global h; restore tf32(new h) into XT for tail GEMMs
    ROWBASE(r, rb, fg);
    int inr = (base + r < NNODES);
    {
        float* X = smf + F_XT + q4 * 4096;
        const float* E = smf + F_ET + q4 * 4096;
        float* ho = h + (size_t)(base + r) * DM + q4 * 32;
#pragma unroll
        for (int qq = 0; qq < 8; qq++) {
            float4 f4;
            f4.x = X[AFIDX(rb, fg, qq * 4 + 0)] + E[AFIDX(rb, fg, qq * 4 + 0)];
            f4.y = X[AFIDX(rb, fg, qq * 4 + 1)] + E[AFIDX(rb, fg, qq * 4 + 1)];
            f4.z = X[AFIDX(rb, fg, qq * 4 + 2)] + E[AFIDX(rb, fg, qq * 4 + 2)];
            f4.w = X[AFIDX(rb, fg, qq * 4 + 3)] + E[AFIDX(rb, fg, qq * 4 + 3)];
            if (inr) *(float4*)(ho + qq * 4) = f4;
            if (tail) {
                X[AFIDX(rb, fg, qq * 4 + 0)] = tff(f4.x);
                X[AFIDX(rb, fg, qq * 4 + 1)] = tff(f4.y);
                X[AFIDX(rb, fg, qq * 4 + 2)] = tff(f4.z);
                X[AFIDX(rb, fg, qq * 4 + 3)] = tff(f4.w);
            }
        }
    }
    if (tail) {
        __syncthreads();
        tail_proj(smf, swb, wPs, hs, tid, wm, wn, lane, pl4, r, q4, rb, fg, inr, base);
        tail_proj(smf, swb, wPr, hr, tid, wm, wn, lane, pl4, r, q4, rb, fg, inr, base);
    }
}

// ---------------- node embedding (+ hs/hr for layer 0) -------------------------
__global__ __launch_bounds__(512, 1) void emb_k(
    const float* __restrict__ nodes, const float* __restrict__ wE,
    const float* __restrict__ bias, float* __restrict__ h,
    float* __restrict__ hs, float* __restrict__ hr,
    const float* __restrict__ wPs, const float* __restrict__ wPr)
{
    extern __shared__ float smf[];
    uint32_t swb = smem_u32(smf) + F_SW * 4;
    int tid = threadIdx.x, lane = tid & 31, wid = tid >> 5;
    int wm = wid & 3, wn = wid >> 2;
    int g = lane >> 2, tig = lane & 3;
    int pl4 = (g * 4 + (tig ^ fAg(g))) << 2;
    int base = blockIdx.x * 128;
    int r = tid >> 2, q4 = tid & 3;
    if (tid < 128) smf[F_PAR + tid] = bias[tid];
    int nr = min(base + r, NNODES - 1);
    const float* src = nodes + (size_t)nr * 288;

    float C[2][4][4];
    ZERO_C();
    copy_w_async(swb, wE, tid); CP_COMMIT();
    stage_Af8(smf + F_SG, src + q4 * 8, r, q4);
    CP_WAIT0(); __syncthreads();
#pragma unroll 1
    for (int c = 0; c < 9; c++) {
        if (c < 8) {
            int cn = c + 1;
            copy_w_async(swb + (cn & 1) * 16384, wE + cn * 4096, tid); CP_COMMIT();
            stage_Af8(smf + F_SG + (cn & 1) * 4096, src + cn * 32 + q4 * 8, r, q4);
        }
        chunk_mma(smf + F_SG + (c & 1) * 4096, smf + F_SW + (c & 1) * 4096,
                  C, wm, wn, lane, pl4);
        CP_WAIT0();
        __syncthreads();
    }
    write_T(C, smf, F_XT, wm, wn, lane, 0);
    __syncthreads();
    ROWBASE(r, rb, fg);
    int inr = (base + r < NNODES);
    {
        float* X = smf + F_XT + q4 * 4096;
        const float* B = smf + F_PAR + q4 * 32;
        float* ho = h + (size_t)(base + r) * DM + q4 * 32;
#pragma unroll
        for (int qq = 0; qq < 8; qq++) {
            float4 f4;
            f4.x = X[AFIDX(rb, fg, qq * 4 + 0)] + B[qq * 4 + 0];
            f4.y = X[AFIDX(rb, fg, qq * 4 + 1)] + B[qq * 4 + 1];
            f4.z = X[AFIDX(rb, fg, qq * 4 + 2)] + B[qq * 4 + 2];
            f4.w = X[AFIDX(rb, fg, qq * 4 + 3)] + B[qq * 4 + 3];
            if (inr) *(float4*)(ho + qq * 4) = f4;
            X[AFIDX(rb, fg, qq * 4 + 0)] = tff(f4.x);
            X[AFIDX(rb, fg, qq * 4 + 1)] = tff(f4.y);
            X[AFIDX(rb, fg, qq * 4 + 2)] = tff(f4.z);
            X[AFIDX(rb, fg, qq * 4 + 3)] = tff(f4.w);
        }
    }
    __syncthreads();
    tail_proj(smf, swb, wPs, hs, tid, wm, wn, lane, pl4, r, q4, rb, fg, inr, base);
    tail_proj(smf, swb, wPr, hr, tid, wm, wn, lane, pl4, r, q4, rb, fg, inr, base);
}

// ---------------- output kernel ------------------------------------------------
__global__ __launch_bounds__(512, 1) void out_k(
    const float* __restrict__ h, const float* __restrict__ wO,
    const float* __restrict__ bias, const float* __restrict__ gg,
    const float* __restrict__ bb, const float* __restrict__ pw,
    const float* __restrict__ pb, float* __restrict__ out)
{
    extern __shared__ float smf[];
    uint32_t swb = smem_u32(smf) + F_SW * 4;
    int tid = threadIdx.x, lane = tid & 31, wid = tid >> 5;
    int wm = wid & 3, wn = wid >> 2;
    int g = lane >> 2, tig = lane & 3;
    int pl4 = (g * 4 + (tig ^ fAg(g))) << 2;
    int base = blockIdx.x * 128;
    int r = tid >> 2, q4 = tid & 3;
    if (tid < 128) {
        smf[F_PAR + tid] = bias[tid];
        smf[F_PAR + 128 + tid] = gg[tid];
        smf[F_PAR + 256 + tid] = bb[tid];
    }
    int nr = min(base + r, NNODES - 1);
    const float* src = h + (size_t)nr * DM;

    float C[2][4][4];
    ZERO_C();
    copy_w_async(swb, wO, tid); CP_COMMIT();
    stage_Af8(smf + F_SG, src + q4 * 8, r, q4);
    CP_WAIT0(); __syncthreads();
#pragma unroll 1
    for (int c = 0; c < 4; c++) {
        if (c < 3) {
            int cn = c + 1;
            copy_w_async(swb + (cn & 1) * 16384, wO + cn * 4096, tid); CP_COMMIT();
            stage_Af8(smf + F_SG + (cn & 1) * 4096, src + cn * 32 + q4 * 8, r, q4);
        }
        chunk_mma(smf + F_SG + (c & 1) * 4096, smf + F_SW + (c & 1) * 4096,
                  C, wm, wn, lane, pl4);
        CP_WAIT0();
        __syncthreads();
    }
    gelu_ln_ep(C, smf, wm, wn, lane, F_PAR, F_PAR + 128, F_PAR + 256);
    write_T(C, smf, F_XT, wm, wn, lane, 0);
    // projection weights into ET region
    float* sPw = smf + F_ET;
    for (int i = tid; i < 128 * PREDL; i += 512) sPw[i] = pw[i];
    if (tid < PREDL) smf[F_ET + 128 * PREDL + tid] = pb[tid];
    __syncthreads();

    if (base + r < NNODES) {
        ROWBASE(r, rb, fg);
        float acc[6];
#pragma unroll
        for (int j = 0; j < 6; j++) acc[j] = smf[F_ET + 128 * PREDL + q4 * 6 + j];
#pragma unroll 1
        for (int ch = 0; ch < 4; ch++) {
            const float* X = smf + F_XT + ch * 4096;
#pragma unroll
            for (int j = 0; j < 32; j++) {
                float xv = X[AFIDX(rb, fg, j)];
                const float* pr = sPw + (ch * 32 + j) * PREDL + q4 * 6;
#pragma unroll
                for (int o = 0; o < 6; o++) acc[o] = fmaf(xv, pr[o], acc[o]);
            }
        }
        float* op = out + (size_t)(base + r) * PREDL + q4 * 6;
#pragma unroll
        for (int j = 0; j < 6; j++) op[j] = acc[j];
    }
}

// ---------------- small kernels -------------------------------------------------
__global__ void emb_edge_kernel(const float* __restrict__ edges,
                                const float* __restrict__ W,
                                const float* __restrict__ bias,
                                float* __restrict__ e)
{
    int idx = blockIdx.x * 256 + threadIdx.x;
    if (idx >= NEDGES * 32) return;
    int ei = idx >> 5, c4 = idx & 31;
    float x0 = edges[2 * ei], x1 = edges[2 * ei + 1];
    float4 w0 = *(const float4*)(W + c4 * 4);
    float4 w1 = *(const float4*)(W + DM + c4 * 4);
    float4 b  = *(const float4*)(bias + c4 * 4);
    float4 o;
    o.x = fmaf(x0, w0.x, fmaf(x1, w1.x, b.x));
    o.y = fmaf(x0, w0.y, fmaf(x1, w1.y, b.y));
    o.z = fmaf(x0, w0.z, fmaf(x1, w1.z, b.z));
    o.w = fmaf(x0, w0.w, fmaf(x1, w1.w, b.w));
    *(float4*)(e + (size_t)ei * DM + c4 * 4) = o;
}

__global__ void count_kernel(const int* __restrict__ receivers,
                             float* __restrict__ cnt)
{
    int i = blockIdx.x * 256 + threadIdx.x;
    if (i < NEDGES) atomicAdd(&cnt[receivers[i]], 1.0f);
}

// ---------------- launch ------------------------------------------------------
extern "C" void kernel_launch(void* const* d_in, const int* in_sizes, int n_in,
                              void* d_out, int out_size)
{
    const float* nodes        = (const float*)d_in[0];
    const float* edges        = (const float*)d_in[1];
    const int*   senders      = (const int*)d_in[2];
    const int*   receivers    = (const int*)d_in[3];
    const float* w_node_emb   = (const float*)d_in[4];
    const float* b_node_emb   = (const float*)d_in[5];
    const float* w_edge_emb   = (const float*)d_in[6];
    const float* b_edge_emb   = (const float*)d_in[7];
    const float* edge_proj_w  = (const float*)d_in[8];
    const float* edge_proj_b  = (const float*)d_in[9];
    const float* node_proj_w  = (const float*)d_in[10];
    const float* node_proj_b  = (const float*)d_in[11];
    const float* edge_mlp_w   = (const float*)d_in[12];
    const float* edge_mlp_b   = (const float*)d_in[13];
    const float* edge_ln_g    = (const float*)d_in[14];
    const float* edge_ln_b    = (const float*)d_in[15];
    const float* node_mlp_w   = (const float*)d_in[16];
    const float* node_mlp_b   = (const float*)d_in[17];
    const float* node_ln_g    = (const float*)d_in[18];
    const float* node_ln_b    = (const float*)d_in[19];
    const float* mlp_out_w    = (const float*)d_in[20];
    const float* mlp_out_b    = (const float*)d_in[21];
    const float* mlp_out_g    = (const float*)d_in[22];
    const float* mlp_out_beta = (const float*)d_in[23];
    const float* proj_w       = (const float*)d_in[24];
    const float* proj_b       = (const float*)d_in[25];
    float* out = (float*)d_out;

    float *h, *e, *agg, *cnt, *wt, *hs, *hr;
    cudaGetSymbolAddress((void**)&h,   g_h);
    cudaGetSymbolAddress((void**)&e,   g_e);
    cudaGetSymbolAddress((void**)&agg, g_agg);
    cudaGetSymbolAddress((void**)&cnt, g_cnt);
    cudaGetSymbolAddress((void**)&wt,  g_wt);
    cudaGetSymbolAddress((void**)&hs,  g_hs);
    cudaGetSymbolAddress((void**)&hr,  g_hr);

    cudaFuncSetAttribute(edge_k, cudaFuncAttributeMaxDynamicSharedMemorySize, SMEMB);
    cudaFuncSetAttribute(node_k, cudaFuncAttributeMaxDynamicSharedMemorySize, SMEMB);
    cudaFuncSetAttribute(emb_k,  cudaFuncAttributeMaxDynamicSharedMemorySize, SMEMB);
    cudaFuncSetAttribute(out_k,  cudaFuncAttributeMaxDynamicSharedMemorySize, SMEMB);

    // weight prep into fragment layout
    prep_w<<<24, 256>>>(edge_proj_w, wt + C_WPE * 4096);
    prep_w<<<16, 256>>>(node_proj_w, wt + C_WPN * 4096);
    prep_w<<<16, 256>>>(edge_mlp_w,  wt + C_WME * 4096);
    prep_w<<<16, 256>>>(node_mlp_w,  wt + C_WMN * 4096);
    prep_w<<<4,  256>>>(mlp_out_w,   wt + C_WOUT * 4096);
    prep_w<<<9,  256>>>(w_node_emb,  wt + C_WEMB * 4096);

    int nblk = (NNODES + 127) / 128;  // 157

    cudaMemsetAsync(cnt, 0, NNODES * sizeof(float));
    emb_k<<<nblk, 512, SMEMB>>>(nodes, wt + C_WEMB * 4096, b_node_emb, h,
                                hs, hr,
                                wt + (C_WPE + 4) * 4096,   // layer-0 Wps
                                wt + (C_WPE + 8) * 4096);  // layer-0 Wpr
    emb_edge_kernel<<<NEDGES * 32 / 256, 256>>>(edges, w_edge_emb, b_edge_emb, e);
    count_kernel<<<(NEDGES + 255) / 256, 256>>>(receivers, cnt);

    for (int l = 0; l < 2; l++) {
        cudaMemsetAsync(agg, 0, (size_t)NNODES * DM * sizeof(float));
        edge_k<<<NEDGES / 128, 512, SMEMB>>>(
            e, senders, receivers, hs, hr,
            wt + (C_WPE + l * 12) * 4096, edge_proj_b + l * 128,
            wt + (C_WME + (l * 2 + 0) * 4) * 4096, edge_mlp_b + (l * 2 + 0) * 128,
            edge_ln_g + (l * 2 + 0) * 128, edge_ln_b + (l * 2 + 0) * 128,
            wt + (C_WME + (l * 2 + 1) * 4) * 4096, edge_mlp_b + (l * 2 + 1) * 128,
            edge_ln_g + (l * 2 + 1) * 128, edge_ln_b + (l * 2 + 1) * 128,
            agg);
        node_k<<<nblk, 512, SMEMB>>>(
            h, agg, cnt,
            wt + (C_WPN + l * 8) * 4096, node_proj_b + l * 128,
            wt + (C_WMN + (l * 2 + 0) * 4) * 4096, node_mlp_b + (l * 2 + 0) * 128,
            node_ln_g + (l * 2 + 0) * 128, node_ln_b + (l * 2 + 0) * 128,
            wt + (C_WMN + (l * 2 + 1) * 4) * 4096, node_mlp_b + (l * 2 + 1) * 128,
            node_ln_g + (l * 2 + 1) * 128, node_ln_b + (l * 2 + 1) * 128,
            hs, hr,
            wt + (C_WPE + 12 + 4) * 4096,   // layer-1 Wps
            wt + (C_WPE + 12 + 8) * 4096,   // layer-1 Wpr
            l == 0);
    }
    out_k<<<nblk, 512, SMEMB>>>(h, wt + C_WOUT * 4096, mlp_out_b, mlp_out_g,
                                mlp_out_beta, proj_w, proj_b, out);
}

// round 8
// speedup vs baseline: 2.0284x; 2.0284x over previous
#include <cuda_runtime.h>
#include <cstdint>

#define NNODES 20000
#define NEDGES 320000
#define DM 128
#define PREDL 24

// ---------------- device scratch ----------------------------------------------
__device__ float g_h[NNODES * DM];
__device__ float g_e[(size_t)NEDGES * DM];
__device__ float g_agg[NNODES * DM];
__device__ float g_cnt[NNODES];
__device__ float g_hs[NNODES * DM];     // (h @ Ws0) permuted, current layer
__device__ float g_hr[NNODES * DM];     // (h @ Wr0) permuted
#define CWL 82176
__device__ float g_cw[2 * CWL];         // composed weights (fp32)
__device__ float g_wt[69 * 4096];       // fragment-layout weights (tf32)

// g_wt chunk offsets
#define W_E0(l)  ((l) * 4)        // e  proj*mlp0 composed   4 chunks
#define W_M1E(l) (8 + (l) * 4)    // edge mlp1               4
#define W_N0(l)  (16 + (l) * 8)   // node proj*mlp0 composed 8
#define W_M1N(l) (32 + (l) * 4)   // node mlp1               4
#define W_S0(l)  (40 + (l) * 8)   // sender  proj*mlp0       4
#define W_R0(l)  (44 + (l) * 8)   // receiver proj*mlp0      4
#define W_OUT    56
#define W_EMB    60               // 9 chunks

// ---------------- smem float offsets -------------------------------------------
#define F_SUM 256
#define F_SQ  768
#define F_PAR 1280
#define F_SW  2176              // 2 x 4096 W double buffer
#define F_SG  (F_SW + 8192)     // 2 x 4096 gather double buffer (node/emb/out)
#define F_ET  (F_SG + 8192)     // 4 x 4096 residual tile (exact f32)
#define F_XT  (F_ET + 16384)    // 4 x 4096 activation tile
#define SMEMB ((F_XT + 16384) * 4)

// ---------------- helpers ------------------------------------------------------
__device__ __forceinline__ uint32_t tfr(float x) {
    uint32_t r;
    asm("cvt.rna.tf32.f32 %0, %1;" : "=r"(r) : "f"(x));
    return r;
}
__device__ __forceinline__ float tff(float x) { return __uint_as_float(tfr(x)); }

__device__ __forceinline__ uint32_t smem_u32(const void* p) {
    uint32_t a;
    asm("{ .reg .u64 t; cvta.to.shared.u64 t, %1; cvt.u32.u64 %0, t; }"
        : "=r"(a) : "l"(p));
    return a;
}

__device__ __forceinline__ void mma8(float c[4], uint32_t a0, uint32_t a1,
                                     uint32_t a2, uint32_t a3,
                                     uint32_t b0, uint32_t b1) {
    asm volatile(
        "mma.sync.aligned.m16n8k8.row.col.f32.tf32.tf32.f32 "
        "{%0,%1,%2,%3}, {%4,%5,%6,%7}, {%8,%9}, {%0,%1,%2,%3};"
        : "+f"(c[0]), "+f"(c[1]), "+f"(c[2]), "+f"(c[3])
        : "r"(a0), "r"(a1), "r"(a2), "r"(a3), "r"(b0), "r"(b1));
}

__device__ __forceinline__ float geluf(float x) {
    float x3 = x * x * x;
    return 0.5f * x * (1.0f + tanhf(0.7978845608028654f * (x + 0.044715f * x3)));
}

__device__ __forceinline__ int fAg(int g) { return (g ^ (g >> 2)) & 3; }

__device__ __forceinline__ int aidx(int row, int kl) {
    int wm = row >> 5, mm = (row >> 4) & 1, r8 = (row >> 3) & 1, g = row & 7;
    int kk = kl >> 3, k4 = (kl >> 2) & 1, tig = kl & 3;
    return (((kk * 4 + wm) * 2 + mm) << 7) + ((g * 4 + (tig ^ fAg(g))) << 2)
           + r8 + (k4 << 1);
}
__device__ __forceinline__ int bidx(int kl, int n) {
    int kk = kl >> 3, k4 = (kl >> 2) & 1, tig = kl & 3;
    int wn = n >> 5, ntp = (n >> 4) & 1, ntb = (n >> 3) & 1, gq = n & 7;
    return (((kk * 4 + wn) * 2 + ntp) << 7) + ((gq * 4 + tig) << 2)
           + ntb * 2 + k4;
}

#define CP16(daddr, src) asm volatile( \
    "cp.async.cg.shared.global [%0], [%1], 16;" :: "r"(daddr), "l"(src))
#define CP_COMMIT() asm volatile("cp.async.commit_group;" ::: "memory")
#define CP_WAIT0()  asm volatile("cp.async.wait_group 0;" ::: "memory")

__device__ __forceinline__ void copy_w_async(uint32_t dsts,
                                             const float* __restrict__ src,
                                             int tid) {
    CP16(dsts + tid * 16, src + tid * 4);
    CP16(dsts + (tid + 512) * 16, src + (tid + 512) * 4);
}

__device__ __forceinline__ void chunk_mma(const float* __restrict__ sA,
                                          const float* __restrict__ sW,
                                          float C[2][4][4], int wm, int wn,
                                          int lane, int pl4) {
#pragma unroll
    for (int kk = 0; kk < 4; kk++) {
        float4 b0 = *(const float4*)(sW + (((kk * 4 + wn) * 2 + 0) << 7)
                                     + (lane << 2));
        float4 b1 = *(const float4*)(sW + (((kk * 4 + wn) * 2 + 1) << 7)
                                     + (lane << 2));
#pragma unroll
        for (int mm = 0; mm < 2; mm++) {
            float4 av = *(const float4*)(sA + (((kk * 4 + wm) * 2 + mm) << 7) + pl4);
            uint32_t a0 = __float_as_uint(av.x), a1 = __float_as_uint(av.y);
            uint32_t a2 = __float_as_uint(av.z), a3 = __float_as_uint(av.w);
            mma8(C[mm][0], a0, a1, a2, a3,
                 __float_as_uint(b0.x), __float_as_uint(b0.y));
            mma8(C[mm][1], a0, a1, a2, a3,
                 __float_as_uint(b0.z), __float_as_uint(b0.w));
            mma8(C[mm][2], a0, a1, a2, a3,
                 __float_as_uint(b1.x), __float_as_uint(b1.y));
            mma8(C[mm][3], a0, a1, a2, a3,
                 __float_as_uint(b1.z), __float_as_uint(b1.w));
        }
    }
}

__device__ __forceinline__ void stage_Af8s(float* chunk, const float* __restrict__ src,
                                           int r, int q4, float sc) {
    float4 v0 = *(const float4*)(src);
    float4 v1 = *(const float4*)(src + 4);
    chunk[aidx(r, q4 * 8 + 0)] = tff(v0.x * sc);
    chunk[aidx(r, q4 * 8 + 1)] = tff(v0.y * sc);
    chunk[aidx(r, q4 * 8 + 2)] = tff(v0.z * sc);
    chunk[aidx(r, q4 * 8 + 3)] = tff(v0.w * sc);
    chunk[aidx(r, q4 * 8 + 4)] = tff(v1.x * sc);
    chunk[aidx(r, q4 * 8 + 5)] = tff(v1.y * sc);
    chunk[aidx(r, q4 * 8 + 6)] = tff(v1.z * sc);
    chunk[aidx(r, q4 * 8 + 7)] = tff(v1.w * sc);
}
__device__ __forceinline__ void stage_Af8(float* chunk, const float* __restrict__ src,
                                          int r, int q4) {
    float4 v0 = *(const float4*)(src);
    float4 v1 = *(const float4*)(src + 4);
    chunk[aidx(r, q4 * 8 + 0)] = tff(v0.x);
    chunk[aidx(r, q4 * 8 + 1)] = tff(v0.y);
    chunk[aidx(r, q4 * 8 + 2)] = tff(v0.z);
    chunk[aidx(r, q4 * 8 + 3)] = tff(v0.w);
    chunk[aidx(r, q4 * 8 + 4)] = tff(v1.x);
    chunk[aidx(r, q4 * 8 + 5)] = tff(v1.y);
    chunk[aidx(r, q4 * 8 + 6)] = tff(v1.z);
    chunk[aidx(r, q4 * 8 + 7)] = tff(v1.w);
}

__device__ __forceinline__ void stage_E32(float* chunk, const float* __restrict__ src,
                                          int r) {
#pragma unroll
    for (int i = 0; i < 8; i++) {
        float4 v = *(const float4*)(src + i * 4);
        chunk[aidx(r, i * 4 + 0)] = v.x;
        chunk[aidx(r, i * 4 + 1)] = v.y;
        chunk[aidx(r, i * 4 + 2)] = v.z;
        chunk[aidx(r, i * 4 + 3)] = v.w;
    }
}

__device__ __forceinline__ void write_T(float C[2][4][4], float* smf, int fbase,
                                        int wm, int wn, int lane, int cvt) {
    int g = lane >> 2, q = lane & 3;
#pragma unroll
    for (int mm = 0; mm < 2; mm++)
#pragma unroll
        for (int hx = 0; hx < 2; hx++) {
            int row = wm * 32 + mm * 16 + hx * 8 + g;
#pragma unroll
            for (int nt = 0; nt < 4; nt++)
#pragma unroll
                for (int s = 0; s < 2; s++) {
                    int col = wn * 32 + nt * 8 + q * 2 + s;
                    float v = C[mm][nt][hx * 2 + s];
                    smf[fbase + (col >> 5) * 4096 + aidx(row, col & 31)] =
                        cvt ? tff(v) : v;
                }
        }
}

__device__ __forceinline__ void gelu_ln_ep(float C[2][4][4], float* smf,
                                           int wm, int wn, int lane,
                                           int pb, int pg, int pbe) {
    int g = lane >> 2, q = lane & 3;
    float* sSum = smf + F_SUM;
    float* sSq  = smf + F_SQ;
#pragma unroll
    for (int mm = 0; mm < 2; mm++)
#pragma unroll
        for (int hx = 0; hx < 2; hx++) {
            float ps = 0.f, pq = 0.f;
#pragma unroll
            for (int nt = 0; nt < 4; nt++)
#pragma unroll
                for (int s = 0; s < 2; s++) {
                    int col = wn * 32 + nt * 8 + q * 2 + s;
                    float v = geluf(C[mm][nt][hx * 2 + s] + smf[pb + col]);
                    C[mm][nt][hx * 2 + s] = v;
                    ps += v; pq += v * v;
                }
            ps += __shfl_xor_sync(0xffffffffu, ps, 1);
            ps += __shfl_xor_sync(0xffffffffu, ps, 2);
            pq += __shfl_xor_sync(0xffffffffu, pq, 1);
            pq += __shfl_xor_sync(0xffffffffu, pq, 2);
            if (q == 0) {
                int row = wm * 32 + mm * 16 + hx * 8 + g;
                sSum[row * 4 + wn] = ps;
                sSq[row * 4 + wn]  = pq;
            }
        }
    __syncthreads();
#pragma unroll
    for (int mm = 0; mm < 2; mm++)
#pragma unroll
        for (int hx = 0; hx < 2; hx++) {
            int row = wm * 32 + mm * 16 + hx * 8 + g;
            float m = (sSum[row * 4] + sSum[row * 4 + 1]
                       + sSum[row * 4 + 2] + sSum[row * 4 + 3]) * (1.0f / 128.0f);
            float qv = (sSq[row * 4] + sSq[row * 4 + 1]
                        + sSq[row * 4 + 2] + sSq[row * 4 + 3]) * (1.0f / 128.0f);
            float rs = rsqrtf(qv - m * m + 1e-5f);
#pragma unroll
            for (int nt = 0; nt < 4; nt++)
#pragma unroll
                for (int s = 0; s < 2; s++) {
                    int col = wn * 32 + nt * 8 + q * 2 + s;
                    C[mm][nt][hx * 2 + s] =
                        (C[mm][nt][hx * 2 + s] - m) * rs * smf[pg + col] + smf[pbe + col];
                }
        }
}

#define ZERO_C(C) do { \
    _Pragma("unroll") for (int _m = 0; _m < 2; _m++) \
    _Pragma("unroll") for (int _n = 0; _n < 4; _n++) \
    _Pragma("unroll") for (int _s = 0; _s < 4; _s++) (C)[_m][_n][_s] = 0.f; } while (0)

__device__ __forceinline__ void gemm_T4(float* smf, uint32_t swb,
                                        const float* __restrict__ W,
                                        float C[2][4][4], int tid, int abase,
                                        int wm, int wn, int lane, int pl4) {
    copy_w_async(swb, W, tid); CP_COMMIT();
    CP_WAIT0(); __syncthreads();
#pragma unroll 1
    for (int c = 0; c < 4; c++) {
        if (c < 3) {
            copy_w_async(swb + ((c + 1) & 1) * 16384, W + (c + 1) * 4096, tid);
            CP_COMMIT();
        }
        chunk_mma(smf + abase + c * 4096, smf + F_SW + (c & 1) * 4096,
                  C, wm, wn, lane, pl4);
        CP_WAIT0();
        __syncthreads();
    }
}

#define ROWBASE(r, rb, fg) \
    int rb = ((((r) >> 5) * 2 + (((r) >> 4) & 1)) << 7) + (((r) & 7) << 4) \
             + (((r) >> 3) & 1); \
    int fg = fAg((r) & 7)
#define AFIDX(rb, fg, j) \
    (((j) >> 3) * 1024 + (rb) + ((((j) & 3) ^ (fg)) << 2) + ((((j) >> 2) & 1) << 1))

#define RED4(p, f4) asm volatile( \
    "red.global.add.v4.f32 [%0], {%1,%2,%3,%4};" \
    :: "l"(p), "f"((f4).x), "f"((f4).y), "f"((f4).z), "f"((f4).w) : "memory")

// project XT (tf32) through W; store rows PERMUTED to gout
__device__ __forceinline__ void tail_projP(float* smf, uint32_t swb,
                                           const float* __restrict__ W,
                                           float* __restrict__ gout,
                                           int tid, int wm, int wn, int lane,
                                           int pl4, int r, int q4, int rb, int fg,
                                           int inr, int base) {
    float C[2][4][4];
    ZERO_C(C);
    gemm_T4(smf, swb, W, C, tid, F_XT, wm, wn, lane, pl4);
    write_T(C, smf, F_ET, wm, wn, lane, 0);
    __syncthreads();
    if (inr) {
        const float* E = smf + F_ET + q4 * 4096;
        float* go = gout + (size_t)(base + r) * DM + q4 * 32;
#pragma unroll
        for (int p4 = 0; p4 < 8; p4++) {
            float v[4];
#pragma unroll
            for (int u = 0; u < 4; u++) {
                int p = p4 * 4 + u;
                int q = p >> 3, t = p & 7, nt = t >> 1, s = t & 1;
                int j = nt * 8 + q * 2 + s;
                v[u] = E[AFIDX(rb, fg, j)];
            }
            float4 f4; f4.x = v[0]; f4.y = v[1]; f4.z = v[2]; f4.w = v[3];
            *(float4*)(go + p4 * 4) = f4;
        }
    }
}

// ---------------- compose: fp32 weight products --------------------------------
__global__ void compose_k(const float* __restrict__ epw, const float* __restrict__ epb,
                          const float* __restrict__ emw, const float* __restrict__ emb_b,
                          const float* __restrict__ npw, const float* __restrict__ npb,
                          const float* __restrict__ nmw, const float* __restrict__ nmb,
                          float* __restrict__ cw) {
    int bi = blockIdx.x, j = threadIdx.x;
    int l = bi / 642, rr = bi % 642;
    const float *A, *B;
    float* out;
    float extra = 0.f;
    if (rr < 384) {
        A = epw + (size_t)l * 384 * 128 + rr * 128;
        B = emw + (l * 2) * 16384;
        out = cw + l * CWL + rr * 128;
    } else if (rr < 640) {
        int r2 = rr - 384;
        A = npw + (size_t)l * 256 * 128 + r2 * 128;
        B = nmw + (l * 2) * 16384;
        out = cw + l * CWL + 49152 + r2 * 128;
    } else if (rr == 640) {
        A = epb + l * 128; B = emw + (l * 2) * 16384;
        out = cw + l * CWL + 81920;
        extra = emb_b[(l * 2) * 128 + j];
    } else {
        A = npb + l * 128; B = nmw + (l * 2) * 16384;
        out = cw + l * CWL + 82048;
        extra = nmb[(l * 2) * 128 + j];
    }
    float acc = extra;
    for (int k = 0; k < 128; k++) acc += A[k] * B[k * 128 + j];
    out[j] = acc;
}

// ---------------- prep: all weights -> B-frag chunks; zero cnt -----------------
__global__ void prep_frag(const float* __restrict__ cw,
                          const float* __restrict__ emw,
                          const float* __restrict__ nmw,
                          const float* __restrict__ mow,
                          const float* __restrict__ wemb,
                          float* __restrict__ wt, float* __restrict__ cnt) {
    int b = blockIdx.x, tid = threadIdx.x;
    if (b < 69) {
        const float* M; int c;
        if (b < 8)       { int l = b >> 2; c = b & 3; M = cw + l * CWL; }
        else if (b < 16) { int l = (b - 8) >> 2; c = (b - 8) & 3;
                           M = emw + (l * 2 + 1) * 16384; }
        else if (b < 32) { int l = (b - 16) >> 3; c = (b - 16) & 7;
                           M = cw + l * CWL + 49152; }
        else if (b < 40) { int l = (b - 32) >> 2; c = (b - 32) & 3;
                           M = nmw + (l * 2 + 1) * 16384; }
        else if (b < 56) { int l = (b - 40) >> 3; int s = (b - 40) & 7;
                           c = s & 3; M = cw + l * CWL + 16384 + (s >> 2) * 16384; }
        else if (b < 60) { c = b - 56; M = mow; }
        else             { c = b - 60; M = wemb; }
        int kl = tid >> 3, n0 = (tid & 7) * 16;
#pragma unroll
        for (int j = 0; j < 16; j++) {
            int n = n0 + j;
            wt[b * 4096 + bidx(kl, n)] = tff(M[(c * 32 + kl) * 128 + n]);
        }
    } else {
        int i = (b - 69) * 256 + tid;
        if (i < NNODES) cnt[i] = 0.f;
    }
}

__global__ void zero_agg_k(float4* __restrict__ agg4) {
    int i = blockIdx.x * 256 + threadIdx.x;
    if (i < NNODES * 32) agg4[i] = make_float4(0.f, 0.f, 0.f, 0.f);
}

// ---------------- edge kernel --------------------------------------------------
// C = hs0p[snd] + hr0p[rcv] ; C += e@We0 ; gelu_ln(+b0') ; @WM1 ; gelu_ln ; +e ; scatter
__global__ __launch_bounds__(512, 1) void edge_k(
    float* __restrict__ e,
    const int* __restrict__ snd, const int* __restrict__ rcv,
    const float* __restrict__ hs0, const float* __restrict__ hr0,
    const float* __restrict__ wE0, const float* __restrict__ b0c,
    const float* __restrict__ g0, const float* __restrict__ be0,
    const float* __restrict__ wM1, const float* __restrict__ b1,
    const float* __restrict__ g1, const float* __restrict__ be1,
    float* __restrict__ agg)
{
    extern __shared__ float smf[];
    uint32_t swb = smem_u32(smf) + F_SW * 4;
    int tid = threadIdx.x, lane = tid & 31, wid = tid >> 5;
    int wm = wid & 3, wn = wid >> 2;
    int g = lane >> 2, q = lane & 3;
    int pl4 = (g * 4 + (q ^ fAg(g))) << 2;
    int base = blockIdx.x * 128;
    int r = tid >> 2, q4 = tid & 3;
    int* sI = (int*)smf;
    if (tid < 128) sI[tid] = snd[base + tid];
    else if (tid < 256) sI[tid] = rcv[base + tid - 128];
    if (tid < 128) {
        float* p = smf + F_PAR;
        p[tid] = b0c[tid];       p[128 + tid] = g0[tid];
        p[256 + tid] = be0[tid]; p[384 + tid] = b1[tid];
        p[512 + tid] = g1[tid];  p[640 + tid] = be1[tid];
    }
    stage_E32(smf + F_ET + q4 * 4096, e + (size_t)(base + r) * DM + q4 * 32, r);
    __syncthreads();

    // C init = gathered hs0p + hr0p (coalesced 32B segments, permuted layout)
    float C[2][4][4];
#pragma unroll
    for (int mm = 0; mm < 2; mm++)
#pragma unroll
        for (int hx = 0; hx < 2; hx++) {
            int row = wm * 32 + mm * 16 + hx * 8 + g;
            const float4* hp = (const float4*)(hs0 + (size_t)sI[row] * DM
                                               + wn * 32 + q * 8);
            const float4* rp = (const float4*)(hr0 + (size_t)sI[128 + row] * DM
                                               + wn * 32 + q * 8);
            float4 a0 = hp[0], a1 = hp[1], c0 = rp[0], c1 = rp[1];
            C[0 + mm][0][hx * 2 + 0] = a0.x + c0.x;
            C[mm][0][hx * 2 + 1] = a0.y + c0.y;
            C[mm][1][hx * 2 + 0] = a0.z + c0.z;
            C[mm][1][hx * 2 + 1] = a0.w + c0.w;
            C[mm][2][hx * 2 + 0] = a1.x + c1.x;
            C[mm][2][hx * 2 + 1] = a1.y + c1.y;
            C[mm][3][hx * 2 + 0] = a1.z + c1.z;
            C[mm][3][hx * 2 + 1] = a1.w + c1.w;
        }

    gemm_T4(smf, swb, wE0, C, tid, F_ET, wm, wn, lane, pl4);   // += e @ We0
    gelu_ln_ep(C, smf, wm, wn, lane, F_PAR, F_PAR + 128, F_PAR + 256);
    write_T(C, smf, F_XT, wm, wn, lane, 1);
    ZERO_C(C);
    gemm_T4(smf, swb, wM1, C, tid, F_XT, wm, wn, lane, pl4);   // MLP layer 1
    gelu_ln_ep(C, smf, wm, wn, lane, F_PAR + 384, F_PAR + 512, F_PAR + 640);
    write_T(C, smf, F_XT, wm, wn, lane, 0);
    __syncthreads();

    // residual + store + vector scatter
    {
        ROWBASE(r, rb, fg);
        const float* X = smf + F_XT + q4 * 4096;
        const float* E = smf + F_ET + q4 * 4096;
        float* eo = e + (size_t)(base + r) * DM + q4 * 32;
        float* ag = agg + (size_t)sI[128 + r] * DM + q4 * 32;
#pragma unroll
        for (int qq = 0; qq < 8; qq++) {
            float4 f4;
            f4.x = X[AFIDX(rb, fg, qq * 4 + 0)] + E[AFIDX(rb, fg, qq * 4 + 0)];
            f4.y = X[AFIDX(rb, fg, qq * 4 + 1)] + E[AFIDX(rb, fg, qq * 4 + 1)];
            f4.z = X[AFIDX(rb, fg, qq * 4 + 2)] + E[AFIDX(rb, fg, qq * 4 + 2)];
            f4.w = X[AFIDX(rb, fg, qq * 4 + 3)] + E[AFIDX(rb, fg, qq * 4 + 3)];
            *(float4*)(eo + qq * 4) = f4;
            RED4(ag + qq * 4, f4);
        }
    }
}

// ---------------- node kernel --------------------------------------------------
__global__ __launch_bounds__(512, 1) void node_k(
    float* __restrict__ h, const float* __restrict__ agg,
    const float* __restrict__ cnt,
    const float* __restrict__ wN0, const float* __restrict__ bn0c,
    const float* __restrict__ g0, const float* __restrict__ be0,
    const float* __restrict__ wM1, const float* __restrict__ b1,
    const float* __restrict__ g1, const float* __restrict__ be1,
    float* __restrict__ hs0, float* __restrict__ hr0,
    const float* __restrict__ wS0, const float* __restrict__ wR0,
    int tail)
{
    extern __shared__ float smf[];
    uint32_t swb = smem_u32(smf) + F_SW * 4;
    int tid = threadIdx.x, lane = tid & 31, wid = tid >> 5;
    int wm = wid & 3, wn = wid >> 2;
    int g = lane >> 2, q = lane & 3;
    int pl4 = (g * 4 + (q ^ fAg(g))) << 2;
    int base = blockIdx.x * 128;
    int r = tid >> 2, q4 = tid & 3;
    if (tid < 128) {
        int n = min(base + tid, NNODES - 1);
        smf[tid] = 1.0f / fmaxf(cnt[n], 1.0f);
        float* p = smf + F_PAR;
        p[tid] = bn0c[tid];      p[128 + tid] = g0[tid];
        p[256 + tid] = be0[tid]; p[384 + tid] = b1[tid];
        p[512 + tid] = g1[tid];  p[640 + tid] = be1[tid];
    }
    int nr = min(base + r, NNODES - 1);
    stage_E32(smf + F_ET + q4 * 4096, h + (size_t)nr * DM + q4 * 32, r);

    float C[2][4][4];
    ZERO_C(C);
    // fused GEMM1: K=256 (0-3 = h from ET, 4-7 = agg/cnt staged)
    copy_w_async(swb, wN0, tid); CP_COMMIT();
    CP_WAIT0(); __syncthreads();
#pragma unroll 1
    for (int c = 0; c < 8; c++) {
        if (c < 7) {
            int cn = c + 1;
            copy_w_async(swb + (cn & 1) * 16384, wN0 + cn * 4096, tid); CP_COMMIT();
            if (cn >= 4)
                stage_Af8s(smf + F_SG + (cn & 1) * 4096,
                           agg + (size_t)nr * DM + ((cn & 3) << 5) + q4 * 8,
                           r, q4, smf[r]);
        }
        const float* As = (c < 4) ? smf + F_ET + c * 4096
                                  : smf + F_SG + (c & 1) * 4096;
        chunk_mma(As, smf + F_SW + (c & 1) * 4096, C, wm, wn, lane, pl4);
        CP_WAIT0();
        __syncthreads();
    }
    gelu_ln_ep(C, smf, wm, wn, lane, F_PAR, F_PAR + 128, F_PAR + 256);
    write_T(C, smf, F_XT, wm, wn, lane, 1);
    ZERO_C(C);
    gemm_T4(smf, swb, wM1, C, tid, F_XT, wm, wn, lane, pl4);
    gelu_ln_ep(C, smf, wm, wn, lane, F_PAR + 384, F_PAR + 512, F_PAR + 640);
    write_T(C, smf, F_XT, wm, wn, lane, 0);
    __syncthreads();

    ROWBASE(r, rb, fg);
    int inr = (base + r < NNODES);
    {
        float* X = smf + F_XT + q4 * 4096;
        const float* E = smf + F_ET + q4 * 4096;
        float* ho = h + (size_t)(base + r) * DM + q4 * 32;
#pragma unroll
        for (int qq = 0; qq < 8; qq++) {
            float4 f4;
            f4.x = X[AFIDX(rb, fg, qq * 4 + 0)] + E[AFIDX(rb, fg, qq * 4 + 0)];
            f4.y = X[AFIDX(rb, fg, qq * 4 + 1)] + E[AFIDX(rb, fg, qq * 4 + 1)];
            f4.z = X[AFIDX(rb, fg, qq * 4 + 2)] + E[AFIDX(rb, fg, qq * 4 + 2)];
            f4.w = X[AFIDX(rb, fg, qq * 4 + 3)] + E[AFIDX(rb, fg, qq * 4 + 3)];
            if (inr) *(float4*)(ho + qq * 4) = f4;
            if (tail) {
                X[AFIDX(rb, fg, qq * 4 + 0)] = tff(f4.x);
                X[AFIDX(rb, fg, qq * 4 + 1)] = tff(f4.y);
                X[AFIDX(rb, fg, qq * 4 + 2)] = tff(f4.z);
                X[AFIDX(rb, fg, qq * 4 + 3)] = tff(f4.w);
            }
        }
    }
    if (tail) {
        tail_projP(smf, swb, wS0, hs0, tid, wm, wn, lane, pl4, r, q4, rb, fg, inr, base);
        tail_projP(smf, swb, wR0, hr0, tid, wm, wn, lane, pl4, r, q4, rb, fg, inr, base);
    }
}

// ---------------- node embedding (+ permuted hs0/hr0 for layer 0) ---------------
__global__ __launch_bounds__(512, 1) void emb_k(
    const float* __restrict__ nodes, const float* __restrict__ wE,
    const float* __restrict__ bias, float* __restrict__ h,
    float* __restrict__ hs0, float* __restrict__ hr0,
    const float* __restrict__ wS0, const float* __restrict__ wR0)
{
    extern __shared__ float smf[];
    uint32_t swb = smem_u32(smf) + F_SW * 4;
    int tid = threadIdx.x, lane = tid & 31, wid = tid >> 5;
    int wm = wid & 3, wn = wid >> 2;
    int g = lane >> 2, q = lane & 3;
    int pl4 = (g * 4 + (q ^ fAg(g))) << 2;
    int base = blockIdx.x * 128;
    int r = tid >> 2, q4 = tid & 3;
    if (tid < 128) smf[F_PAR + tid] = bias[tid];
    int nr = min(base + r, NNODES - 1);
    const float* src = nodes + (size_t)nr * 288;

    float C[2][4][4];
    ZERO_C(C);
    copy_w_async(swb, wE, tid); CP_COMMIT();
    stage_Af8(smf + F_SG, src + q4 * 8, r, q4);
    CP_WAIT0(); __syncthreads();
#pragma unroll 1
    for (int c = 0; c < 9; c++) {
        if (c < 8) {
            int cn = c + 1;
            copy_w_async(swb + (cn & 1) * 16384, wE + cn * 4096, tid); CP_COMMIT();
            stage_Af8(smf + F_SG + (cn & 1) * 4096, src + cn * 32 + q4 * 8, r, q4);
        }
        chunk_mma(smf + F_SG + (c & 1) * 4096, smf + F_SW + (c & 1) * 4096,
                  C, wm, wn, lane, pl4);
        CP_WAIT0();
        __syncthreads();
    }
    write_T(C, smf, F_XT, wm, wn, lane, 0);
    __syncthreads();
    ROWBASE(r, rb, fg);
    int inr = (base + r < NNODES);
    {
        float* X = smf + F_XT + q4 * 4096;
        const float* B = smf + F_PAR + q4 * 32;
        float* ho = h + (size_t)(base + r) * DM + q4 * 32;
#pragma unroll
        for (int qq = 0; qq < 8; qq++) {
            float4 f4;
            f4.x = X[AFIDX(rb, fg, qq * 4 + 0)] + B[qq * 4 + 0];
            f4.y = X[AFIDX(rb, fg, qq * 4 + 1)] + B[qq * 4 + 1];
            f4.z = X[AFIDX(rb, fg, qq * 4 + 2)] + B[qq * 4 + 2];
            f4.w = X[AFIDX(rb, fg, qq * 4 + 3)] + B[qq * 4 + 3];
            if (inr) *(float4*)(ho + qq * 4) = f4;
            X[AFIDX(rb, fg, qq * 4 + 0)] = tff(f4.x);
            X[AFIDX(rb, fg, qq * 4 + 1)] = tff(f4.y);
            X[AFIDX(rb, fg, qq * 4 + 2)] = tff(f4.z);
            X[AFIDX(rb, fg, qq * 4 + 3)] = tff(f4.w);
        }
    }
    tail_projP(smf, swb, wS0, hs0, tid, wm, wn, lane, pl4, r, q4, rb, fg, inr, base);
    tail_projP(smf, swb, wR0, hr0, tid, wm, wn, lane, pl4, r, q4, rb, fg, inr, base);
}

// ---------------- output kernel ------------------------------------------------
__global__ __launch_bounds__(512, 1) void out_k(
    const float* __restrict__ h, const float* __restrict__ wO,
    const float* __restrict__ bias, const float* __restrict__ gg,
    const float* __restrict__ bb, const float* __restrict__ pw,
    const float* __restrict__ pb, float* __restrict__ out)
{
    extern __shared__ float smf[];
    uint32_t swb = smem_u32(smf) + F_SW * 4;
    int tid = threadIdx.x, lane = tid & 31, wid = tid >> 5;
    int wm = wid & 3, wn = wid >> 2;
    int g = lane >> 2, q = lane & 3;
    int pl4 = (g * 4 + (q ^ fAg(g))) << 2;
    int base = blockIdx.x * 128;
    int r = tid >> 2, q4 = tid & 3;
    if (tid < 128) {
        smf[F_PAR + tid] = bias[tid];
        smf[F_PAR + 128 + tid] = gg[tid];
        smf[F_PAR + 256 + tid] = bb[tid];
    }
    int nr = min(base + r, NNODES - 1);
    const float* src = h + (size_t)nr * DM;

    float C[2][4][4];
    ZERO_C(C);
    copy_w_async(swb, wO, tid); CP_COMMIT();
    stage_Af8(smf + F_SG, src + q4 * 8, r, q4);
    CP_WAIT0(); __syncthreads();
#pragma unroll 1
    for (int c = 0; c < 4; c++) {
        if (c < 3) {
            int cn = c + 1;
            copy_w_async(swb + (cn & 1) * 16384, wO + cn * 4096, tid); CP_COMMIT();
            stage_Af8(smf + F_SG + (cn & 1) * 4096, src + cn * 32 + q4 * 8, r, q4);
        }
        chunk_mma(smf + F_SG + (c & 1) * 4096, smf + F_SW + (c & 1) * 4096,
                  C, wm, wn, lane, pl4);
        CP_WAIT0();
        __syncthreads();
    }
    gelu_ln_ep(C, smf, wm, wn, lane, F_PAR, F_PAR + 128, F_PAR + 256);
    write_T(C, smf, F_XT, wm, wn, lane, 0);
    float* sPw = smf + F_ET;
    for (int i = tid; i < 128 * PREDL; i += 512) sPw[i] = pw[i];
    if (tid < PREDL) smf[F_ET + 128 * PREDL + tid] = pb[tid];
    __syncthreads();

    if (base + r < NNODES) {
        ROWBASE(r, rb, fg);
        float acc[6];
#pragma unroll
        for (int j = 0; j < 6; j++) acc[j] = smf[F_ET + 128 * PREDL + q4 * 6 + j];
#pragma unroll 1
        for (int ch = 0; ch < 4; ch++) {
            const float* X = smf + F_XT + ch * 4096;
#pragma unroll
            for (int j = 0; j < 32; j++) {
                float xv = X[AFIDX(rb, fg, j)];
                const float* pr = sPw + (ch * 32 + j) * PREDL + q4 * 6;
#pragma unroll
                for (int o = 0; o < 6; o++) acc[o] = fmaf(xv, pr[o], acc[o]);
            }
        }
        float* op = out + (size_t)(base + r) * PREDL + q4 * 6;
#pragma unroll
        for (int j = 0; j < 6; j++) op[j] = acc[j];
    }
}

// ---------------- edge embedding + in-degree count ------------------------------
__global__ void emb_edge_kernel(const float* __restrict__ edges,
                                const float* __restrict__ W,
                                const float* __restrict__ bias,
                                const int* __restrict__ rcv,
                                float* __restrict__ cnt,
                                float* __restrict__ e)
{
    int idx = blockIdx.x * 256 + threadIdx.x;
    if (idx >= NEDGES * 32) return;
    int ei = idx >> 5, c4 = idx & 31;
    float x0 = edges[2 * ei], x1 = edges[2 * ei + 1];
    float4 w0 = *(const float4*)(W + c4 * 4);
    float4 w1 = *(const float4*)(W + DM + c4 * 4);
    float4 b  = *(const float4*)(bias + c4 * 4);
    float4 o;
    o.x = fmaf(x0, w0.x, fmaf(x1, w1.x, b.x));
    o.y = fmaf(x0, w0.y, fmaf(x1, w1.y, b.y));
    o.z = fmaf(x0, w0.z, fmaf(x1, w1.z, b.z));
    o.w = fmaf(x0, w0.w, fmaf(x1, w1.w, b.w));
    *(float4*)(e + (size_t)ei * DM + c4 * 4) = o;
    if (c4 == 0) atomicAdd(cnt + rcv[ei], 1.0f);
}

// ---------------- launch ------------------------------------------------------
extern "C" void kernel_launch(void* const* d_in, const int* in_sizes, int n_in,
                              void* d_out, int out_size)
{
    const float* nodes        = (const float*)d_in[0];
    const float* edges        = (const float*)d_in[1];
    const int*   senders      = (const int*)d_in[2];
    const int*   receivers    = (const int*)d_in[3];
    const float* w_node_emb   = (const float*)d_in[4];
    const float* b_node_emb   = (const float*)d_in[5];
    const float* w_edge_emb   = (const float*)d_in[6];
    const float* b_edge_emb   = (const float*)d_in[7];
    const float* edge_proj_w  = (const float*)d_in[8];
    const float* edge_proj_b  = (const float*)d_in[9];
    const float* node_proj_w  = (const float*)d_in[10];
    const float* node_proj_b  = (const float*)d_in[11];
    const float* edge_mlp_w   = (const float*)d_in[12];
    const float* edge_mlp_b   = (const float*)d_in[13];
    const float* edge_ln_g    = (const float*)d_in[14];
    const float* edge_ln_b    = (const float*)d_in[15];
    const float* node_mlp_w   = (const float*)d_in[16];
    const float* node_mlp_b   = (const float*)d_in[17];
    const float* node_ln_g    = (const float*)d_in[18];
    const float* node_ln_b    = (const float*)d_in[19];
    const float* mlp_out_w    = (const float*)d_in[20];
    const float* mlp_out_b    = (const float*)d_in[21];
    const float* mlp_out_g    = (const float*)d_in[22];
    const float* mlp_out_beta = (const float*)d_in[23];
    const float* proj_w       = (const float*)d_in[24];
    const float* proj_b       = (const float*)d_in[25];
    float* out = (float*)d_out;

    float *h, *e, *agg, *cnt, *wt, *hs, *hr, *cw;
    cudaGetSymbolAddress((void**)&h,   g_h);
    cudaGetSymbolAddress((void**)&e,   g_e);
    cudaGetSymbolAddress((void**)&agg, g_agg);
    cudaGetSymbolAddress((void**)&cnt, g_cnt);
    cudaGetSymbolAddress((void**)&wt,  g_wt);
    cudaGetSymbolAddress((void**)&hs,  g_hs);
    cudaGetSymbolAddress((void**)&hr,  g_hr);
    cudaGetSymbolAddress((void**)&cw,  g_cw);

    cudaFuncSetAttribute(edge_k, cudaFuncAttributeMaxDynamicSharedMemorySize, SMEMB);
    cudaFuncSetAttribute(node_k, cudaFuncAttributeMaxDynamicSharedMemorySize, SMEMB);
    cudaFuncSetAttribute(emb_k,  cudaFuncAttributeMaxDynamicSharedMemorySize, SMEMB);
    cudaFuncSetAttribute(out_k,  cudaFuncAttributeMaxDynamicSharedMemorySize, SMEMB);

    int nblk = (NNODES + 127) / 128;  // 157

    // [0] compose fp32 weight products
    compose_k<<<1284, 128>>>(edge_proj_w, edge_proj_b, edge_mlp_w, edge_mlp_b,
                             node_proj_w, node_proj_b, node_mlp_w, node_mlp_b, cw);
    // [1] fragment conversion + cnt zero
    prep_frag<<<148, 256>>>(cw, edge_mlp_w, node_mlp_w, mlp_out_w, w_node_emb,
                            wt, cnt);
    // [2] zero agg
    zero_agg_k<<<2500, 256>>>((float4*)agg);
    // [3] node embedding + layer-0 hs0/hr0 tails
    emb_k<<<nblk, 512, SMEMB>>>(nodes, wt + W_EMB * 4096, b_node_emb, h,
                                hs, hr, wt + W_S0(0) * 4096, wt + W_R0(0) * 4096);
    // [4] edge embedding + in-degree count
    emb_edge_kernel<<<NEDGES * 32 / 256, 256>>>(edges, w_edge_emb, b_edge_emb,
                                                receivers, cnt, e);
    for (int l = 0; l < 2; l++) {
        // [5]/[8] edge update
        edge_k<<<NEDGES / 128, 512, SMEMB>>>(
            e, senders, receivers, hs, hr,
            wt + W_E0(l) * 4096, cw + l * CWL + 81920,
            edge_ln_g + (l * 2 + 0) * 128, edge_ln_b + (l * 2 + 0) * 128,
            wt + W_M1E(l) * 4096, edge_mlp_b + (l * 2 + 1) * 128,
            edge_ln_g + (l * 2 + 1) * 128, edge_ln_b + (l * 2 + 1) * 128,
            agg);
        // [6]/[9] node update (+ next-layer hs0/hr0 tails when l==0)
        node_k<<<nblk, 512, SMEMB>>>(
            h, agg, cnt,
            wt + W_N0(l) * 4096, cw + l * CWL + 82048,
            node_ln_g + (l * 2 + 0) * 128, node_ln_b + (l * 2 + 0) * 128,
            wt + W_M1N(l) * 4096, node_mlp_b + (l * 2 + 1) * 128,
            node_ln_g + (l * 2 + 1) * 128, node_ln_b + (l * 2 + 1) * 128,
            hs, hr, wt + W_S0(1) * 4096, wt + W_R0(1) * 4096, l == 0);
        // [7] re-zero agg between layers
        if (l == 0) zero_agg_k<<<2500, 256>>>((float4*)agg);
    }
    out_k<<<nblk, 512, SMEMB>>>(h, wt + W_OUT * 4096, mlp_out_b, mlp_out_g,
                                mlp_out_beta, proj_w, proj_b, out);
}

// round 9
// speedup vs baseline: 2.3920x; 1.1792x over previous
#include <cuda_runtime.h>
#include <cstdint>

#define NNODES 20000
#define NEDGES 320000
#define DM 128
#define PREDL 24

// ---------------- device scratch ----------------------------------------------
__device__ float g_h[NNODES * DM];
__device__ float g_e[(size_t)NEDGES * DM];
__device__ float g_agg[NNODES * DM];
__device__ float g_cnt[NNODES];
__device__ float g_hs[NNODES * DM];     // (h @ Ws0) permuted, current layer
__device__ float g_hr[NNODES * DM];     // (h @ Wr0) permuted
#define CWL 82176
__device__ float g_cw[2 * CWL];         // composed weights (fp32)
__device__ float g_wt[69 * 4096];       // fragment-layout weights (tf32)

// g_wt chunk offsets
#define W_E0(l)  ((l) * 4)
#define W_M1E(l) (8 + (l) * 4)
#define W_N0(l)  (16 + (l) * 8)
#define W_M1N(l) (32 + (l) * 4)
#define W_S0(l)  (40 + (l) * 8)
#define W_R0(l)  (44 + (l) * 8)
#define W_OUT    56
#define W_EMB    60

// ---------------- smem float offsets -------------------------------------------
#define F_SUM 256
#define F_SQ  768
#define F_PAR 1280
#define F_W1  2176               // 16384 floats (64KB)
#define F_W2  (F_W1 + 16384)     // 16384
#define F_T   (F_W2 + 16384)     // 16384 (A tile, aliased as X tile)
#define SMEMB ((F_T + 16384) * 4)

// ---------------- helpers ------------------------------------------------------
__device__ __forceinline__ uint32_t tfr(float x) {
    uint32_t r;
    asm("cvt.rna.tf32.f32 %0, %1;" : "=r"(r) : "f"(x));
    return r;
}
__device__ __forceinline__ float tff(float x) { return __uint_as_float(tfr(x)); }

__device__ __forceinline__ uint32_t smem_u32(const void* p) {
    uint32_t a;
    asm("{ .reg .u64 t; cvta.to.shared.u64 t, %1; cvt.u32.u64 %0, t; }"
        : "=r"(a) : "l"(p));
    return a;
}

__device__ __forceinline__ void mma8(float c[4], uint32_t a0, uint32_t a1,
                                     uint32_t a2, uint32_t a3,
                                     uint32_t b0, uint32_t b1) {
    asm volatile(
        "mma.sync.aligned.m16n8k8.row.col.f32.tf32.tf32.f32 "
        "{%0,%1,%2,%3}, {%4,%5,%6,%7}, {%8,%9}, {%0,%1,%2,%3};"
        : "+f"(c[0]), "+f"(c[1]), "+f"(c[2]), "+f"(c[3])
        : "r"(a0), "r"(a1), "r"(a2), "r"(a3), "r"(b0), "r"(b1));
}

__device__ __forceinline__ float geluf(float x) {
    float x3 = x * x * x;
    return 0.5f * x * (1.0f + tanhf(0.7978845608028654f * (x + 0.044715f * x3)));
}

__device__ __forceinline__ int fAg(int g) { return (g ^ (g >> 2)) & 3; }

__device__ __forceinline__ int aidx(int row, int kl) {
    int wm = row >> 5, mm = (row >> 4) & 1, r8 = (row >> 3) & 1, g = row & 7;
    int kk = kl >> 3, k4 = (kl >> 2) & 1, tig = kl & 3;
    return (((kk * 4 + wm) * 2 + mm) << 7) + ((g * 4 + (tig ^ fAg(g))) << 2)
           + r8 + (k4 << 1);
}
__device__ __forceinline__ int bidx(int kl, int n) {
    int kk = kl >> 3, k4 = (kl >> 2) & 1, tig = kl & 3;
    int wn = n >> 5, ntp = (n >> 4) & 1, ntb = (n >> 3) & 1, gq = n & 7;
    return (((kk * 4 + wn) * 2 + ntp) << 7) + ((gq * 4 + tig) << 2)
           + ntb * 2 + k4;
}

#define CP16(daddr, src) asm volatile( \
    "cp.async.cg.shared.global [%0], [%1], 16;" :: "r"(daddr), "l"(src))
#define CP_COMMIT() asm volatile("cp.async.commit_group;" ::: "memory")
#define CP_WAIT0()  asm volatile("cp.async.wait_group 0;" ::: "memory")
#define CP_WAIT1()  asm volatile("cp.async.wait_group 1;" ::: "memory")

// one 16KB chunk via cp.async (512 threads)
__device__ __forceinline__ void copy_w_async(uint32_t dsts,
                                             const float* __restrict__ src,
                                             int tid) {
    CP16(dsts + tid * 16, src + tid * 4);
    CP16(dsts + (tid + 512) * 16, src + (tid + 512) * 4);
}
// four chunks (64KB)
__device__ __forceinline__ void copy_w4(uint32_t dsts,
                                        const float* __restrict__ src, int tid) {
#pragma unroll
    for (int i = 0; i < 4; i++) {
        CP16(dsts + i * 16384 + tid * 16, src + i * 4096 + tid * 4);
        CP16(dsts + i * 16384 + (tid + 512) * 16, src + i * 4096 + (tid + 512) * 4);
    }
}

__device__ __forceinline__ void chunk_mma(const float* __restrict__ sA,
                                          const float* __restrict__ sW,
                                          float C[2][4][4], int wm, int wn,
                                          int lane, int pl4) {
#pragma unroll
    for (int kk = 0; kk < 4; kk++) {
        float4 b0 = *(const float4*)(sW + (((kk * 4 + wn) * 2 + 0) << 7)
                                     + (lane << 2));
        float4 b1 = *(const float4*)(sW + (((kk * 4 + wn) * 2 + 1) << 7)
                                     + (lane << 2));
#pragma unroll
        for (int mm = 0; mm < 2; mm++) {
            float4 av = *(const float4*)(sA + (((kk * 4 + wm) * 2 + mm) << 7) + pl4);
            uint32_t a0 = __float_as_uint(av.x), a1 = __float_as_uint(av.y);
            uint32_t a2 = __float_as_uint(av.z), a3 = __float_as_uint(av.w);
            mma8(C[mm][0], a0, a1, a2, a3,
                 __float_as_uint(b0.x), __float_as_uint(b0.y));
            mma8(C[mm][1], a0, a1, a2, a3,
                 __float_as_uint(b0.z), __float_as_uint(b0.w));
            mma8(C[mm][2], a0, a1, a2, a3,
                 __float_as_uint(b1.x), __float_as_uint(b1.y));
            mma8(C[mm][3], a0, a1, a2, a3,
                 __float_as_uint(b1.z), __float_as_uint(b1.w));
        }
    }
}

// K=128 GEMM, A tile + W region both RESIDENT (no syncs inside)
__device__ __forceinline__ void gemm4(const float* smf, int tbase, int wbase,
                                      float C[2][4][4], int wm, int wn,
                                      int lane, int pl4) {
#pragma unroll 1
    for (int c = 0; c < 4; c++)
        chunk_mma(smf + tbase + c * 4096, smf + wbase + c * 4096,
                  C, wm, wn, lane, pl4);
}

__device__ __forceinline__ void stage_Af8(float* chunk, const float* __restrict__ src,
                                          int r, int q4) {
    float4 v0 = *(const float4*)(src);
    float4 v1 = *(const float4*)(src + 4);
    chunk[aidx(r, q4 * 8 + 0)] = tff(v0.x);
    chunk[aidx(r, q4 * 8 + 1)] = tff(v0.y);
    chunk[aidx(r, q4 * 8 + 2)] = tff(v0.z);
    chunk[aidx(r, q4 * 8 + 3)] = tff(v0.w);
    chunk[aidx(r, q4 * 8 + 4)] = tff(v1.x);
    chunk[aidx(r, q4 * 8 + 5)] = tff(v1.y);
    chunk[aidx(r, q4 * 8 + 6)] = tff(v1.z);
    chunk[aidx(r, q4 * 8 + 7)] = tff(v1.w);
}
__device__ __forceinline__ void stage_Af8s(float* chunk, const float* __restrict__ src,
                                           int r, int q4, float sc) {
    float4 v0 = *(const float4*)(src);
    float4 v1 = *(const float4*)(src + 4);
    chunk[aidx(r, q4 * 8 + 0)] = tff(v0.x * sc);
    chunk[aidx(r, q4 * 8 + 1)] = tff(v0.y * sc);
    chunk[aidx(r, q4 * 8 + 2)] = tff(v0.z * sc);
    chunk[aidx(r, q4 * 8 + 3)] = tff(v0.w * sc);
    chunk[aidx(r, q4 * 8 + 4)] = tff(v1.x * sc);
    chunk[aidx(r, q4 * 8 + 5)] = tff(v1.y * sc);
    chunk[aidx(r, q4 * 8 + 6)] = tff(v1.z * sc);
    chunk[aidx(r, q4 * 8 + 7)] = tff(v1.w * sc);
}

__device__ __forceinline__ void stage_E32(float* chunk, const float* __restrict__ src,
                                          int r) {
#pragma unroll
    for (int i = 0; i < 8; i++) {
        float4 v = *(const float4*)(src + i * 4);
        chunk[aidx(r, i * 4 + 0)] = v.x;
        chunk[aidx(r, i * 4 + 1)] = v.y;
        chunk[aidx(r, i * 4 + 2)] = v.z;
        chunk[aidx(r, i * 4 + 3)] = v.w;
    }
}

__device__ __forceinline__ void write_T(float C[2][4][4], float* smf, int fbase,
                                        int wm, int wn, int lane, int cvt) {
    int g = lane >> 2, q = lane & 3;
#pragma unroll
    for (int mm = 0; mm < 2; mm++)
#pragma unroll
        for (int hx = 0; hx < 2; hx++) {
            int row = wm * 32 + mm * 16 + hx * 8 + g;
#pragma unroll
            for (int nt = 0; nt < 4; nt++)
#pragma unroll
                for (int s = 0; s < 2; s++) {
                    int col = wn * 32 + nt * 8 + q * 2 + s;
                    float v = C[mm][nt][hx * 2 + s];
                    smf[fbase + (col >> 5) * 4096 + aidx(row, col & 31)] =
                        cvt ? tff(v) : v;
                }
        }
}

__device__ __forceinline__ void gelu_ln_ep(float C[2][4][4], float* smf,
                                           int wm, int wn, int lane,
                                           int pb, int pg, int pbe) {
    int g = lane >> 2, q = lane & 3;
    float* sSum = smf + F_SUM;
    float* sSq  = smf + F_SQ;
#pragma unroll
    for (int mm = 0; mm < 2; mm++)
#pragma unroll
        for (int hx = 0; hx < 2; hx++) {
            float ps = 0.f, pq = 0.f;
#pragma unroll
            for (int nt = 0; nt < 4; nt++)
#pragma unroll
                for (int s = 0; s < 2; s++) {
                    int col = wn * 32 + nt * 8 + q * 2 + s;
                    float v = geluf(C[mm][nt][hx * 2 + s] + smf[pb + col]);
                    C[mm][nt][hx * 2 + s] = v;
                    ps += v; pq += v * v;
                }
            ps += __shfl_xor_sync(0xffffffffu, ps, 1);
            ps += __shfl_xor_sync(0xffffffffu, ps, 2);
            pq += __shfl_xor_sync(0xffffffffu, pq, 1);
            pq += __shfl_xor_sync(0xffffffffu, pq, 2);
            if (q == 0) {
                int row = wm * 32 + mm * 16 + hx * 8 + g;
                sSum[row * 4 + wn] = ps;
                sSq[row * 4 + wn]  = pq;
            }
        }
    __syncthreads();
#pragma unroll
    for (int mm = 0; mm < 2; mm++)
#pragma unroll
        for (int hx = 0; hx < 2; hx++) {
            int row = wm * 32 + mm * 16 + hx * 8 + g;
            float m = (sSum[row * 4] + sSum[row * 4 + 1]
                       + sSum[row * 4 + 2] + sSum[row * 4 + 3]) * (1.0f / 128.0f);
            float qv = (sSq[row * 4] + sSq[row * 4 + 1]
                        + sSq[row * 4 + 2] + sSq[row * 4 + 3]) * (1.0f / 128.0f);
            float rs = rsqrtf(qv - m * m + 1e-5f);
#pragma unroll
            for (int nt = 0; nt < 4; nt++)
#pragma unroll
                for (int s = 0; s < 2; s++) {
                    int col = wn * 32 + nt * 8 + q * 2 + s;
                    C[mm][nt][hx * 2 + s] =
                        (C[mm][nt][hx * 2 + s] - m) * rs * smf[pg + col] + smf[pbe + col];
                }
        }
}

#define ZERO_C(C) do { \
    _Pragma("unroll") for (int _m = 0; _m < 2; _m++) \
    _Pragma("unroll") for (int _n = 0; _n < 4; _n++) \
    _Pragma("unroll") for (int _s = 0; _s < 4; _s++) (C)[_m][_n][_s] = 0.f; } while (0)

// streamed K=128 GEMM: A = T (resident), W double-buffered through F_W1
__device__ __forceinline__ void gemm_T4s(float* smf, uint32_t sb,
                                         const float* __restrict__ W,
                                         float C[2][4][4], int tid,
                                         int wm, int wn, int lane, int pl4) {
    copy_w_async(sb + F_W1 * 4, W, tid); CP_COMMIT();
    CP_WAIT0(); __syncthreads();
#pragma unroll 1
    for (int c = 0; c < 4; c++) {
        if (c < 3) {
            copy_w_async(sb + F_W1 * 4 + ((c + 1) & 1) * 16384, W + (c + 1) * 4096, tid);
            CP_COMMIT();
        }
        chunk_mma(smf + F_T + c * 4096, smf + F_W1 + (c & 1) * 4096,
                  C, wm, wn, lane, pl4);
        CP_WAIT0();
        __syncthreads();
    }
}

#define ROWBASE(r, rb, fg) \
    int rb = ((((r) >> 5) * 2 + (((r) >> 4) & 1)) << 7) + (((r) & 7) << 4) \
             + (((r) >> 3) & 1); \
    int fg = fAg((r) & 7)
#define AFIDX(rb, fg, j) \
    (((j) >> 3) * 1024 + (rb) + ((((j) & 3) ^ (fg)) << 2) + ((((j) >> 2) & 1) << 1))

#define RED2(p, a, b) asm volatile( \
    "red.global.add.v2.f32 [%0], {%1,%2};" :: "l"(p), "f"(a), "f"(b) : "memory")

// direct permuted store of C fragments to gout (matches edge gather layout)
__device__ __forceinline__ void store_perm(const float C[2][4][4],
                                           float* __restrict__ gout, int base,
                                           int wm, int wn, int g, int q) {
#pragma unroll
    for (int mm = 0; mm < 2; mm++)
#pragma unroll
        for (int hx = 0; hx < 2; hx++) {
            int row = wm * 32 + mm * 16 + hx * 8 + g;
            if (base + row >= NNODES) continue;
            float* go = gout + (size_t)(base + row) * DM + wn * 32 + q * 8;
            float4 f0, f1;
            f0.x = C[mm][0][hx * 2 + 0]; f0.y = C[mm][0][hx * 2 + 1];
            f0.z = C[mm][1][hx * 2 + 0]; f0.w = C[mm][1][hx * 2 + 1];
            f1.x = C[mm][2][hx * 2 + 0]; f1.y = C[mm][2][hx * 2 + 1];
            f1.z = C[mm][3][hx * 2 + 0]; f1.w = C[mm][3][hx * 2 + 1];
            *(float4*)go = f0;
            *(float4*)(go + 4) = f1;
        }
}

// ---------------- compose: fp32 weight products --------------------------------
__global__ void compose_k(const float* __restrict__ epw, const float* __restrict__ epb,
                          const float* __restrict__ emw, const float* __restrict__ emb_b,
                          const float* __restrict__ npw, const float* __restrict__ npb,
                          const float* __restrict__ nmw, const float* __restrict__ nmb,
                          float* __restrict__ cw) {
    int bi = blockIdx.x, j = threadIdx.x;
    int l = bi / 642, rr = bi % 642;
    const float *A, *B;
    float* out;
    float extra = 0.f;
    if (rr < 384) {
        A = epw + (size_t)l * 384 * 128 + rr * 128;
        B = emw + (l * 2) * 16384;
        out = cw + l * CWL + rr * 128;
    } else if (rr < 640) {
        int r2 = rr - 384;
        A = npw + (size_t)l * 256 * 128 + r2 * 128;
        B = nmw + (l * 2) * 16384;
        out = cw + l * CWL + 49152 + r2 * 128;
    } else if (rr == 640) {
        A = epb + l * 128; B = emw + (l * 2) * 16384;
        out = cw + l * CWL + 81920;
        extra = emb_b[(l * 2) * 128 + j];
    } else {
        A = npb + l * 128; B = nmw + (l * 2) * 16384;
        out = cw + l * CWL + 82048;
        extra = nmb[(l * 2) * 128 + j];
    }
    float acc = extra;
    for (int k = 0; k < 128; k++) acc += A[k] * B[k * 128 + j];
    out[j] = acc;
}

// ---------------- prep: all weights -> B-frag chunks; zero cnt -----------------
__global__ void prep_frag(const float* __restrict__ cw,
                          const float* __restrict__ emw,
                          const float* __restrict__ nmw,
                          const float* __restrict__ mow,
                          const float* __restrict__ wemb,
                          float* __restrict__ wt, float* __restrict__ cnt) {
    int b = blockIdx.x, tid = threadIdx.x;
    if (b < 69) {
        const float* M; int c;
        if (b < 8)       { int l = b >> 2; c = b & 3; M = cw + l * CWL; }
        else if (b < 16) { int l = (b - 8) >> 2; c = (b - 8) & 3;
                           M = emw + (l * 2 + 1) * 16384; }
        else if (b < 32) { int l = (b - 16) >> 3; c = (b - 16) & 7;
                           M = cw + l * CWL + 49152; }
        else if (b < 40) { int l = (b - 32) >> 2; c = (b - 32) & 3;
                           M = nmw + (l * 2 + 1) * 16384; }
        else if (b < 56) { int l = (b - 40) >> 3; int s = (b - 40) & 7;
                           c = s & 3; M = cw + l * CWL + 16384 + (s >> 2) * 16384; }
        else if (b < 60) { c = b - 56; M = mow; }
        else             { c = b - 60; M = wemb; }
        int kl = tid >> 3, n0 = (tid & 7) * 16;
#pragma unroll
        for (int j = 0; j < 16; j++) {
            int n = n0 + j;
            wt[b * 4096 + bidx(kl, n)] = tff(M[(c * 32 + kl) * 128 + n]);
        }
    } else {
        int i = (b - 69) * 256 + tid;
        if (i < NNODES) cnt[i] = 0.f;
    }
}

__global__ void zero_agg_k(float4* __restrict__ agg4) {
    int i = blockIdx.x * 256 + threadIdx.x;
    if (i < NNODES * 32) agg4[i] = make_float4(0.f, 0.f, 0.f, 0.f);
}

// ---------------- edge kernel --------------------------------------------------
__global__ __launch_bounds__(512, 1) void edge_k(
    float* __restrict__ e,
    const int* __restrict__ snd, const int* __restrict__ rcv,
    const float* __restrict__ hs0, const float* __restrict__ hr0,
    const float* __restrict__ wE0, const float* __restrict__ b0c,
    const float* __restrict__ g0, const float* __restrict__ be0,
    const float* __restrict__ wM1, const float* __restrict__ b1,
    const float* __restrict__ g1, const float* __restrict__ be1,
    float* __restrict__ agg)
{
    extern __shared__ float smf[];
    uint32_t sb = smem_u32(smf);
    int tid = threadIdx.x, lane = tid & 31, wid = tid >> 5;
    int wm = wid & 3, wn = wid >> 2;
    int g = lane >> 2, q = lane & 3;
    int pl4 = (g * 4 + (q ^ fAg(g))) << 2;
    int base = blockIdx.x * 128;
    int r = tid >> 2, q4 = tid & 3;

    // preload BOTH weight sets (async), stage e tile, one barrier
    copy_w4(sb + F_W1 * 4, wE0, tid); CP_COMMIT();
    copy_w4(sb + F_W2 * 4, wM1, tid); CP_COMMIT();
    int* sI = (int*)smf;
    if (tid < 128) sI[tid] = snd[base + tid];
    else if (tid < 256) sI[tid] = rcv[base + tid - 128];
    if (tid < 128) {
        float* p = smf + F_PAR;
        p[tid] = b0c[tid];       p[128 + tid] = g0[tid];
        p[256 + tid] = be0[tid]; p[384 + tid] = b1[tid];
        p[512 + tid] = g1[tid];  p[640 + tid] = be1[tid];
    }
    stage_E32(smf + F_T + q4 * 4096, e + (size_t)(base + r) * DM + q4 * 32, r);
    CP_WAIT1();
    __syncthreads();                               // [1] W1 + T + sI ready

    // C init = gathered hs0p + hr0p
    float C[2][4][4];
#pragma unroll
    for (int mm = 0; mm < 2; mm++)
#pragma unroll
        for (int hx = 0; hx < 2; hx++) {
            int row = wm * 32 + mm * 16 + hx * 8 + g;
            const float4* hp = (const float4*)(hs0 + (size_t)sI[row] * DM
                                               + wn * 32 + q * 8);
            const float4* rp = (const float4*)(hr0 + (size_t)sI[128 + row] * DM
                                               + wn * 32 + q * 8);
            float4 a0 = hp[0], a1 = hp[1], c0 = rp[0], c1 = rp[1];
            C[mm][0][hx * 2 + 0] = a0.x + c0.x;
            C[mm][0][hx * 2 + 1] = a0.y + c0.y;
            C[mm][1][hx * 2 + 0] = a0.z + c0.z;
            C[mm][1][hx * 2 + 1] = a0.w + c0.w;
            C[mm][2][hx * 2 + 0] = a1.x + c1.x;
            C[mm][2][hx * 2 + 1] = a1.y + c1.y;
            C[mm][3][hx * 2 + 0] = a1.z + c1.z;
            C[mm][3][hx * 2 + 1] = a1.w + c1.w;
        }

    gemm4(smf, F_T, F_W1, C, wm, wn, lane, pl4);   // e @ We0, no internal syncs
    gelu_ln_ep(C, smf, wm, wn, lane, F_PAR, F_PAR + 128, F_PAR + 256);  // [2]
    write_T(C, smf, F_T, wm, wn, lane, 1);         // X over e tile
    CP_WAIT0();
    __syncthreads();                               // [3] X + W2 ready
    ZERO_C(C);
    gemm4(smf, F_T, F_W2, C, wm, wn, lane, pl4);   // MLP layer 1
    gelu_ln_ep(C, smf, wm, wn, lane, F_PAR + 384, F_PAR + 512, F_PAR + 640); // [4]

    // direct epilogue: residual re-read from L2, store e, scatter agg
#pragma unroll
    for (int mm = 0; mm < 2; mm++)
#pragma unroll
        for (int hx = 0; hx < 2; hx++) {
            int row = wm * 32 + mm * 16 + hx * 8 + g;
            float* eo = e + (size_t)(base + row) * DM;
            float* ag = agg + (size_t)sI[128 + row] * DM;
#pragma unroll
            for (int nt = 0; nt < 4; nt++) {
                int col = wn * 32 + nt * 8 + q * 2;
                float2 er = *(const float2*)(eo + col);
                float v0 = C[mm][nt][hx * 2 + 0] + er.x;
                float v1 = C[mm][nt][hx * 2 + 1] + er.y;
                *(float2*)(eo + col) = make_float2(v0, v1);
                RED2(ag + col, v0, v1);
            }
        }
}

// ---------------- node kernel --------------------------------------------------
__global__ __launch_bounds__(512, 1) void node_k(
    float* __restrict__ h, const float* __restrict__ agg,
    const float* __restrict__ cnt,
    const float* __restrict__ wN0, const float* __restrict__ bn0c,
    const float* __restrict__ g0, const float* __restrict__ be0,
    const float* __restrict__ wM1, const float* __restrict__ b1,
    const float* __restrict__ g1, const float* __restrict__ be1,
    float* __restrict__ hs0, float* __restrict__ hr0,
    const float* __restrict__ wS0, const float* __restrict__ wR0,
    int tail)
{
    extern __shared__ float smf[];
    uint32_t sb = smem_u32(smf);
    int tid = threadIdx.x, lane = tid & 31, wid = tid >> 5;
    int wm = wid & 3, wn = wid >> 2;
    int g = lane >> 2, q = lane & 3;
    int pl4 = (g * 4 + (q ^ fAg(g))) << 2;
    int base = blockIdx.x * 128;
    int r = tid >> 2, q4 = tid & 3;

    copy_w4(sb + F_W1 * 4, wN0, tid); CP_COMMIT();            // g0: Wn0 lo
    copy_w4(sb + F_W2 * 4, wN0 + 4 * 4096, tid); CP_COMMIT(); // g1: Wn0 hi
    if (tid < 128) {
        int n = min(base + tid, NNODES - 1);
        smf[tid] = 1.0f / fmaxf(cnt[n], 1.0f);
        float* p = smf + F_PAR;
        p[tid] = bn0c[tid];      p[128 + tid] = g0[tid];
        p[256 + tid] = be0[tid]; p[384 + tid] = b1[tid];
        p[512 + tid] = g1[tid];  p[640 + tid] = be1[tid];
    }
    int nr = min(base + r, NNODES - 1);
    stage_E32(smf + F_T + q4 * 4096, h + (size_t)nr * DM + q4 * 32, r);
    CP_WAIT1();
    __syncthreads();

    float C[2][4][4];
    ZERO_C(C);
    gemm4(smf, F_T, F_W1, C, wm, wn, lane, pl4);   // h half of GEMM1
    __syncthreads();                               // done reading T(h), W1
    copy_w4(sb + F_W1 * 4, wM1, tid); CP_COMMIT(); // g2
    {
        float inv = smf[r];
#pragma unroll
        for (int c2 = 0; c2 < 4; c2++)
            stage_Af8s(smf + F_T + c2 * 4096,
                       agg + (size_t)nr * DM + c2 * 32 + q4 * 8, r, q4, inv);
    }
    CP_WAIT1();
    __syncthreads();                               // T(agg) + W2 ready
    gemm4(smf, F_T, F_W2, C, wm, wn, lane, pl4);   // agg half accumulates
    gelu_ln_ep(C, smf, wm, wn, lane, F_PAR, F_PAR + 128, F_PAR + 256);
    write_T(C, smf, F_T, wm, wn, lane, 1);
    CP_WAIT0();
    __syncthreads();                               // X + WM1 ready
    ZERO_C(C);
    gemm4(smf, F_T, F_W1, C, wm, wn, lane, pl4);   // MLP layer 1
    gelu_ln_ep(C, smf, wm, wn, lane, F_PAR + 384, F_PAR + 512, F_PAR + 640);

    // direct epilogue: h_new = C + h (L2 re-read); keep h_new in C for tails
#pragma unroll
    for (int mm = 0; mm < 2; mm++)
#pragma unroll
        for (int hx = 0; hx < 2; hx++) {
            int row = wm * 32 + mm * 16 + hx * 8 + g;
            if (base + row >= NNODES) continue;
            float* ho = h + (size_t)(base + row) * DM;
#pragma unroll
            for (int nt = 0; nt < 4; nt++) {
                int col = wn * 32 + nt * 8 + q * 2;
                float2 hv = *(const float2*)(ho + col);
                float v0 = C[mm][nt][hx * 2 + 0] + hv.x;
                float v1 = C[mm][nt][hx * 2 + 1] + hv.y;
                *(float2*)(ho + col) = make_float2(v0, v1);
                C[mm][nt][hx * 2 + 0] = v0;
                C[mm][nt][hx * 2 + 1] = v1;
            }
        }

    if (tail) {
        write_T(C, smf, F_T, wm, wn, lane, 1);     // X = tf32(h_new)
        copy_w4(sb + F_W2 * 4, wS0, tid); CP_COMMIT();  // g3
        copy_w4(sb + F_W1 * 4, wR0, tid); CP_COMMIT();  // g4
        __syncthreads();
        CP_WAIT1();
        __syncthreads();                           // X + wS0 ready
        ZERO_C(C);
        gemm4(smf, F_T, F_W2, C, wm, wn, lane, pl4);
        store_perm(C, hs0, base, wm, wn, g, q);
        CP_WAIT0();
        __syncthreads();                           // wR0 ready
        ZERO_C(C);
        gemm4(smf, F_T, F_W1, C, wm, wn, lane, pl4);
        store_perm(C, hr0, base, wm, wn, g, q);
    }
}

// ---------------- node embedding (+ permuted hs0/hr0 for layer 0) ---------------
__global__ __launch_bounds__(512, 1) void emb_k(
    const float* __restrict__ nodes, const float* __restrict__ wE,
    const float* __restrict__ bias, float* __restrict__ h,
    float* __restrict__ hs0, float* __restrict__ hr0,
    const float* __restrict__ wS0, const float* __restrict__ wR0)
{
    extern __shared__ float smf[];
    uint32_t sb = smem_u32(smf);
    int tid = threadIdx.x, lane = tid & 31, wid = tid >> 5;
    int wm = wid & 3, wn = wid >> 2;
    int g = lane >> 2, q = lane & 3;
    int pl4 = (g * 4 + (q ^ fAg(g))) << 2;
    int base = blockIdx.x * 128;
    int r = tid >> 2, q4 = tid & 3;
    if (tid < 128) smf[F_PAR + tid] = bias[tid];
    int nr = min(base + r, NNODES - 1);
    const float* src = nodes + (size_t)nr * 288;

    // streamed GEMM over K=288: W double @ F_W1, A double @ F_W2
    float C[2][4][4];
    ZERO_C(C);
    copy_w_async(sb + F_W1 * 4, wE, tid); CP_COMMIT();
    stage_Af8(smf + F_W2, src + q4 * 8, r, q4);
    CP_WAIT0(); __syncthreads();
#pragma unroll 1
    for (int c = 0; c < 9; c++) {
        if (c < 8) {
            int cn = c + 1;
            copy_w_async(sb + F_W1 * 4 + (cn & 1) * 16384, wE + cn * 4096, tid);
            CP_COMMIT();
            stage_Af8(smf + F_W2 + (cn & 1) * 4096, src + cn * 32 + q4 * 8, r, q4);
        }
        chunk_mma(smf + F_W2 + (c & 1) * 4096, smf + F_W1 + (c & 1) * 4096,
                  C, wm, wn, lane, pl4);
        CP_WAIT0();
        __syncthreads();
    }
    write_T(C, smf, F_T, wm, wn, lane, 0);
    __syncthreads();
    ROWBASE(r, rb, fg);
    int inr = (base + r < NNODES);
    {
        float* X = smf + F_T + q4 * 4096;
        const float* B = smf + F_PAR + q4 * 32;
        float* ho = h + (size_t)(base + r) * DM + q4 * 32;
#pragma unroll
        for (int qq = 0; qq < 8; qq++) {
            float4 f4;
            f4.x = X[AFIDX(rb, fg, qq * 4 + 0)] + B[qq * 4 + 0];
            f4.y = X[AFIDX(rb, fg, qq * 4 + 1)] + B[qq * 4 + 1];
            f4.z = X[AFIDX(rb, fg, qq * 4 + 2)] + B[qq * 4 + 2];
            f4.w = X[AFIDX(rb, fg, qq * 4 + 3)] + B[qq * 4 + 3];
            if (inr) *(float4*)(ho + qq * 4) = f4;
            X[AFIDX(rb, fg, qq * 4 + 0)] = tff(f4.x);
            X[AFIDX(rb, fg, qq * 4 + 1)] = tff(f4.y);
            X[AFIDX(rb, fg, qq * 4 + 2)] = tff(f4.z);
            X[AFIDX(rb, fg, qq * 4 + 3)] = tff(f4.w);
        }
    }
    __syncthreads();
    ZERO_C(C);
    gemm_T4s(smf, sb, wS0, C, tid, wm, wn, lane, pl4);
    store_perm(C, hs0, base, wm, wn, g, q);
    ZERO_C(C);
    gemm_T4s(smf, sb, wR0, C, tid, wm, wn, lane, pl4);
    store_perm(C, hr0, base, wm, wn, g, q);
}

// ---------------- output kernel ------------------------------------------------
__global__ __launch_bounds__(512, 1) void out_k(
    const float* __restrict__ h, const float* __restrict__ wO,
    const float* __restrict__ bias, const float* __restrict__ gg,
    const float* __restrict__ bb, const float* __restrict__ pw,
    const float* __restrict__ pb, float* __restrict__ out)
{
    extern __shared__ float smf[];
    uint32_t sb = smem_u32(smf);
    int tid = threadIdx.x, lane = tid & 31, wid = tid >> 5;
    int wm = wid & 3, wn = wid >> 2;
    int g = lane >> 2, q = lane & 3;
    int pl4 = (g * 4 + (q ^ fAg(g))) << 2;
    int base = blockIdx.x * 128;
    int r = tid >> 2, q4 = tid & 3;
    if (tid < 128) {
        smf[F_PAR + tid] = bias[tid];
        smf[F_PAR + 128 + tid] = gg[tid];
        smf[F_PAR + 256 + tid] = bb[tid];
    }
    int nr = min(base + r, NNODES - 1);
    const float* src = h + (size_t)nr * DM;

    float C[2][4][4];
    ZERO_C(C);
    copy_w4(sb + F_W1 * 4, wO, tid); CP_COMMIT();
    stage_E32(smf + F_T + q4 * 4096, src + q4 * 32, r);  // exact; HW truncates
    CP_WAIT0(); __syncthreads();
    gemm4(smf, F_T, F_W1, C, wm, wn, lane, pl4);
    gelu_ln_ep(C, smf, wm, wn, lane, F_PAR, F_PAR + 128, F_PAR + 256);
    write_T(C, smf, F_T, wm, wn, lane, 0);
    float* sPw = smf + F_W2;
    for (int i = tid; i < 128 * PREDL; i += 512) sPw[i] = pw[i];
    if (tid < PREDL) smf[F_W2 + 128 * PREDL + tid] = pb[tid];
    __syncthreads();

    if (base + r < NNODES) {
        ROWBASE(r, rb, fg);
        float acc[6];
#pragma unroll
        for (int j = 0; j < 6; j++) acc[j] = smf[F_W2 + 128 * PREDL + q4 * 6 + j];
#pragma unroll 1
        for (int ch = 0; ch < 4; ch++) {
            const float* X = smf + F_T + ch * 4096;
#pragma unroll
            for (int j = 0; j < 32; j++) {
                float xv = X[AFIDX(rb, fg, j)];
                const float* pr = sPw + (ch * 32 + j) * PREDL + q4 * 6;
#pragma unroll
                for (int o = 0; o < 6; o++) acc[o] = fmaf(xv, pr[o], acc[o]);
            }
        }
        float* op = out + (size_t)(base + r) * PREDL + q4 * 6;
#pragma unroll
        for (int j = 0; j < 6; j++) op[j] = acc[j];
    }
}

// ---------------- edge embedding + in-degree count ------------------------------
__global__ void emb_edge_kernel(const float* __restrict__ edges,
                                const float* __restrict__ W,
                                const float* __restrict__ bias,
                                const int* __restrict__ rcv,
                                float* __restrict__ cnt,
                                float* __restrict__ e)
{
    int idx = blockIdx.x * 256 + threadIdx.x;
    if (idx >= NEDGES * 32) return;
    int ei = idx >> 5, c4 = idx & 31;
    float x0 = edges[2 * ei], x1 = edges[2 * ei + 1];
    float4 w0 = *(const float4*)(W + c4 * 4);
    float4 w1 = *(const float4*)(W + DM + c4 * 4);
    float4 b  = *(const float4*)(bias + c4 * 4);
    float4 o;
    o.x = fmaf(x0, w0.x, fmaf(x1, w1.x, b.x));
    o.y = fmaf(x0, w0.y, fmaf(x1, w1.y, b.y));
    o.z = fmaf(x0, w0.z, fmaf(x1, w1.z, b.z));
    o.w = fmaf(x0, w0.w, fmaf(x1, w1.w, b.w));
    *(float4*)(e + (size_t)ei * DM + c4 * 4) = o;
    if (c4 == 0) atomicAdd(cnt + rcv[ei], 1.0f);
}

// ---------------- launch ------------------------------------------------------
extern "C" void kernel_launch(void* const* d_in, const int* in_sizes, int n_in,
                              void* d_out, int out_size)
{
    const float* nodes        = (const float*)d_in[0];
    const float* edges        = (const float*)d_in[1];
    const int*   senders      = (const int*)d_in[2];
    const int*   receivers    = (const int*)d_in[3];
    const float* w_node_emb   = (const float*)d_in[4];
    const float* b_node_emb   = (const float*)d_in[5];
    const float* w_edge_emb   = (const float*)d_in[6];
    const float* b_edge_emb   = (const float*)d_in[7];
    const float* edge_proj_w  = (const float*)d_in[8];
    const float* edge_proj_b  = (const float*)d_in[9];
    const float* node_proj_w  = (const float*)d_in[10];
    const float* node_proj_b  = (const float*)d_in[11];
    const float* edge_mlp_w   = (const float*)d_in[12];
    const float* edge_mlp_b   = (const float*)d_in[13];
    const float* edge_ln_g    = (const float*)d_in[14];
    const float* edge_ln_b    = (const float*)d_in[15];
    const float* node_mlp_w   = (const float*)d_in[16];
    const float* node_mlp_b   = (const float*)d_in[17];
    const float* node_ln_g    = (const float*)d_in[18];
    const float* node_ln_b    = (const float*)d_in[19];
    const float* mlp_out_w    = (const float*)d_in[20];
    const float* mlp_out_b    = (const float*)d_in[21];
    const float* mlp_out_g    = (const float*)d_in[22];
    const float* mlp_out_beta = (const float*)d_in[23];
    const float* proj_w       = (const float*)d_in[24];
    const float* proj_b       = (const float*)d_in[25];
    float* out = (float*)d_out;

    float *h, *e, *agg, *cnt, *wt, *hs, *hr, *cw;
    cudaGetSymbolAddress((void**)&h,   g_h);
    cudaGetSymbolAddress((void**)&e,   g_e);
    cudaGetSymbolAddress((void**)&agg, g_agg);
    cudaGetSymbolAddress((void**)&cnt, g_cnt);
    cudaGetSymbolAddress((void**)&wt,  g_wt);
    cudaGetSymbolAddress((void**)&hs,  g_hs);
    cudaGetSymbolAddress((void**)&hr,  g_hr);
    cudaGetSymbolAddress((void**)&cw,  g_cw);

    cudaFuncSetAttribute(edge_k, cudaFuncAttributeMaxDynamicSharedMemorySize, SMEMB);
    cudaFuncSetAttribute(node_k, cudaFuncAttributeMaxDynamicSharedMemorySize, SMEMB);
    cudaFuncSetAttribute(emb_k,  cudaFuncAttributeMaxDynamicSharedMemorySize, SMEMB);
    cudaFuncSetAttribute(out_k,  cudaFuncAttributeMaxDynamicSharedMemorySize, SMEMB);

    int nblk = (NNODES + 127) / 128;  // 157

    compose_k<<<1284, 128>>>(edge_proj_w, edge_proj_b, edge_mlp_w, edge_mlp_b,
                             node_proj_w, node_proj_b, node_mlp_w, node_mlp_b, cw);
    prep_frag<<<148, 256>>>(cw, edge_mlp_w, node_mlp_w, mlp_out_w, w_node_emb,
                            wt, cnt);
    zero_agg_k<<<2500, 256>>>((float4*)agg);
    emb_k<<<nblk, 512, SMEMB>>>(nodes, wt + W_EMB * 4096, b_node_emb, h,
                                hs, hr, wt + W_S0(0) * 4096, wt + W_R0(0) * 4096);
    emb_edge_kernel<<<NEDGES * 32 / 256, 256>>>(edges, w_edge_emb, b_edge_emb,
                                                receivers, cnt, e);
    for (int l = 0; l < 2; l++) {
        edge_k<<<NEDGES / 128, 512, SMEMB>>>(
            e, senders, receivers, hs, hr,
            wt + W_E0(l) * 4096, cw + l * CWL + 81920,
            edge_ln_g + (l * 2 + 0) * 128, edge_ln_b + (l * 2 + 0) * 128,
            wt + W_M1E(l) * 4096, edge_mlp_b + (l * 2 + 1) * 128,
            edge_ln_g + (l * 2 + 1) * 128, edge_ln_b + (l * 2 + 1) * 128,
            agg);
        node_k<<<nblk, 512, SMEMB>>>(
            h, agg, cnt,
            wt + W_N0(l) * 4096, cw + l * CWL + 82048,
            node_ln_g + (l * 2 + 0) * 128, node_ln_b + (l * 2 + 0) * 128,
            wt + W_M1N(l) * 4096, node_mlp_b + (l * 2 + 1) * 128,
            node_ln_g + (l * 2 + 1) * 128, node_ln_b + (l * 2 + 1) * 128,
            hs, hr, wt + W_S0(1) * 4096, wt + W_R0(1) * 4096, l == 0);
        if (l == 0) zero_agg_k<<<2500, 256>>>((float4*)agg);
    }
    out_k<<<nblk, 512, SMEMB>>>(h, wt + W_OUT * 4096, mlp_out_b, mlp_out_g,
                                mlp_out_beta, proj_w, proj_b, out);
}

// round 10
// speedup vs baseline: 2.8667x; 1.1985x over previous
#include <cuda_runtime.h>
#include <cstdint>

#define NNODES 20000
#define NEDGES 320000
#define DM 128
#define PREDL 24

// ---------------- device scratch ----------------------------------------------
__device__ float g_h[NNODES * DM];
__device__ float g_e[(size_t)NEDGES * DM];
__device__ float g_agg[NNODES * DM];
__device__ float g_cnt[NNODES];
__device__ float g_hs[NNODES * DM];     // (h @ Ws0) permuted
__device__ float g_hr[NNODES * DM];     // (h @ Wr0) permuted
#define CWL 82176
__device__ float g_cw[2 * CWL];         // composed weights (fp32)
__device__ float g_wt[69 * 4096];       // fragment-layout weights (tf32)

// g_wt chunk offsets
#define W_E0(l)  ((l) * 4)
#define W_M1E(l) (8 + (l) * 4)
#define W_N0(l)  (16 + (l) * 8)
#define W_M1N(l) (32 + (l) * 4)
#define W_S0(l)  (40 + (l) * 8)
#define W_R0(l)  (44 + (l) * 8)
#define W_OUT    56
#define W_EMB    60

// ---------------- smem float offsets (M=64 tile) --------------------------------
// [0..127]  sI (edge) / inv (node)
#define F_SUM 128               // 256
#define F_SQ  384               // 256
#define F_PAR 640               // 896
#define F_W   1536              // 2 x 4096 W double buffer
#define F_SG  (F_W + 8192)      // 2 x 2048 A-stage double buffer
#define F_T   (F_SG + 4096)     // 4 x 2048 activation tile
#define SMEMB ((F_T + 8192) * 4)   // 88064 B -> 2 CTAs/SM

// ---------------- helpers ------------------------------------------------------
__device__ __forceinline__ uint32_t tfr(float x) {
    uint32_t r;
    asm("cvt.rna.tf32.f32 %0, %1;" : "=r"(r) : "f"(x));
    return r;
}
__device__ __forceinline__ float tff(float x) { return __uint_as_float(tfr(x)); }

__device__ __forceinline__ uint32_t smem_u32(const void* p) {
    uint32_t a;
    asm("{ .reg .u64 t; cvta.to.shared.u64 t, %1; cvt.u32.u64 %0, t; }"
        : "=r"(a) : "l"(p));
    return a;
}

__device__ __forceinline__ void mma8(float c[4], uint32_t a0, uint32_t a1,
                                     uint32_t a2, uint32_t a3,
                                     uint32_t b0, uint32_t b1) {
    asm volatile(
        "mma.sync.aligned.m16n8k8.row.col.f32.tf32.tf32.f32 "
        "{%0,%1,%2,%3}, {%4,%5,%6,%7}, {%8,%9}, {%0,%1,%2,%3};"
        : "+f"(c[0]), "+f"(c[1]), "+f"(c[2]), "+f"(c[3])
        : "r"(a0), "r"(a1), "r"(a2), "r"(a3), "r"(b0), "r"(b1));
}

__device__ __forceinline__ float geluf(float x) {
    float x3 = x * x * x;
    return 0.5f * x * (1.0f + tanhf(0.7978845608028654f * (x + 0.044715f * x3)));
}

__device__ __forceinline__ int fAg(int g) { return (g ^ (g >> 2)) & 3; }

// A-fragment index in a 2048-float chunk (64 rows x 32 k)
__device__ __forceinline__ int aidx(int row, int kl) {
    int wm = row >> 5, mm = (row >> 4) & 1, r8 = (row >> 3) & 1, g = row & 7;
    int kk = kl >> 3, k4 = (kl >> 2) & 1, tig = kl & 3;
    return (((kk * 2 + wm) * 2 + mm) << 7) + ((g * 4 + (tig ^ fAg(g))) << 2)
           + r8 + (k4 << 1);
}
// B-fragment index in a 4096-float chunk (unchanged vs R9; g_wt layout identical)
__device__ __forceinline__ int bidx(int kl, int n) {
    int kk = kl >> 3, k4 = (kl >> 2) & 1, tig = kl & 3;
    int wn = n >> 5, ntp = (n >> 4) & 1, ntb = (n >> 3) & 1, gq = n & 7;
    return (((kk * 4 + wn) * 2 + ntp) << 7) + ((gq * 4 + tig) << 2)
           + ntb * 2 + k4;
}

#define CP16(daddr, src) asm volatile( \
    "cp.async.cg.shared.global [%0], [%1], 16;" :: "r"(daddr), "l"(src))
#define CP_COMMIT() asm volatile("cp.async.commit_group;" ::: "memory")
#define CP_WAIT0()  asm volatile("cp.async.wait_group 0;" ::: "memory")

// one 4096-float W chunk via cp.async (256 threads x 4 x 16B)
__device__ __forceinline__ void copy_w_async(uint32_t dsts,
                                             const float* __restrict__ src,
                                             int tid) {
    CP16(dsts + tid * 16, src + tid * 4);
    CP16(dsts + (tid + 256) * 16, src + (tid + 256) * 4);
    CP16(dsts + (tid + 512) * 16, src + (tid + 512) * 4);
    CP16(dsts + (tid + 768) * 16, src + (tid + 768) * 4);
}

// one 32-wide K chunk; warp covers 32 rows x 32 cols (A chunk = 2048 floats)
__device__ __forceinline__ void chunk_mma(const float* __restrict__ sA,
                                          const float* __restrict__ sW,
                                          float C[2][4][4], int wm, int wn,
                                          int lane, int pl4) {
#pragma unroll
    for (int kk = 0; kk < 4; kk++) {
        float4 b0 = *(const float4*)(sW + (((kk * 4 + wn) * 2 + 0) << 7)
                                     + (lane << 2));
        float4 b1 = *(const float4*)(sW + (((kk * 4 + wn) * 2 + 1) << 7)
                                     + (lane << 2));
#pragma unroll
        for (int mm = 0; mm < 2; mm++) {
            float4 av = *(const float4*)(sA + (((kk * 2 + wm) * 2 + mm) << 7) + pl4);
            uint32_t a0 = __float_as_uint(av.x), a1 = __float_as_uint(av.y);
            uint32_t a2 = __float_as_uint(av.z), a3 = __float_as_uint(av.w);
            mma8(C[mm][0], a0, a1, a2, a3,
                 __float_as_uint(b0.x), __float_as_uint(b0.y));
            mma8(C[mm][1], a0, a1, a2, a3,
                 __float_as_uint(b0.z), __float_as_uint(b0.w));
            mma8(C[mm][2], a0, a1, a2, a3,
                 __float_as_uint(b1.x), __float_as_uint(b1.y));
            mma8(C[mm][3], a0, a1, a2, a3,
                 __float_as_uint(b1.z), __float_as_uint(b1.w));
        }
    }
}

__device__ __forceinline__ void stage_Af8(float* chunk, const float* __restrict__ src,
                                          int r, int q4) {
    float4 v0 = *(const float4*)(src);
    float4 v1 = *(const float4*)(src + 4);
    chunk[aidx(r, q4 * 8 + 0)] = tff(v0.x);
    chunk[aidx(r, q4 * 8 + 1)] = tff(v0.y);
    chunk[aidx(r, q4 * 8 + 2)] = tff(v0.z);
    chunk[aidx(r, q4 * 8 + 3)] = tff(v0.w);
    chunk[aidx(r, q4 * 8 + 4)] = tff(v1.x);
    chunk[aidx(r, q4 * 8 + 5)] = tff(v1.y);
    chunk[aidx(r, q4 * 8 + 6)] = tff(v1.z);
    chunk[aidx(r, q4 * 8 + 7)] = tff(v1.w);
}
__device__ __forceinline__ void stage_Af8s(float* chunk, const float* __restrict__ src,
                                           int r, int q4, float sc) {
    float4 v0 = *(const float4*)(src);
    float4 v1 = *(const float4*)(src + 4);
    chunk[aidx(r, q4 * 8 + 0)] = tff(v0.x * sc);
    chunk[aidx(r, q4 * 8 + 1)] = tff(v0.y * sc);
    chunk[aidx(r, q4 * 8 + 2)] = tff(v0.z * sc);
    chunk[aidx(r, q4 * 8 + 3)] = tff(v0.w * sc);
    chunk[aidx(r, q4 * 8 + 4)] = tff(v1.x * sc);
    chunk[aidx(r, q4 * 8 + 5)] = tff(v1.y * sc);
    chunk[aidx(r, q4 * 8 + 6)] = tff(v1.z * sc);
    chunk[aidx(r, q4 * 8 + 7)] = tff(v1.w * sc);
}

// stage 32 cols of a row EXACT into A-frag chunk (thread owns row r, chunk q4)
__device__ __forceinline__ void stage_E32(float* chunk, const float* __restrict__ src,
                                          int r) {
#pragma unroll
    for (int i = 0; i < 8; i++) {
        float4 v = *(const float4*)(src + i * 4);
        chunk[aidx(r, i * 4 + 0)] = v.x;
        chunk[aidx(r, i * 4 + 1)] = v.y;
        chunk[aidx(r, i * 4 + 2)] = v.z;
        chunk[aidx(r, i * 4 + 3)] = v.w;
    }
}

__device__ __forceinline__ void write_T(float C[2][4][4], float* smf, int fbase,
                                        int wm, int wn, int lane, int cvt) {
    int g = lane >> 2, q = lane & 3;
#pragma unroll
    for (int mm = 0; mm < 2; mm++)
#pragma unroll
        for (int hx = 0; hx < 2; hx++) {
            int row = wm * 32 + mm * 16 + hx * 8 + g;
#pragma unroll
            for (int nt = 0; nt < 4; nt++)
#pragma unroll
                for (int s = 0; s < 2; s++) {
                    int col = wn * 32 + nt * 8 + q * 2 + s;
                    float v = C[mm][nt][hx * 2 + s];
                    smf[fbase + (col >> 5) * 2048 + aidx(row, col & 31)] =
                        cvt ? tff(v) : v;
                }
        }
}

__device__ __forceinline__ void gelu_ln_ep(float C[2][4][4], float* smf,
                                           int wm, int wn, int lane,
                                           int pb, int pg, int pbe) {
    int g = lane >> 2, q = lane & 3;
    float* sSum = smf + F_SUM;
    float* sSq  = smf + F_SQ;
#pragma unroll
    for (int mm = 0; mm < 2; mm++)
#pragma unroll
        for (int hx = 0; hx < 2; hx++) {
            float ps = 0.f, pq = 0.f;
#pragma unroll
            for (int nt = 0; nt < 4; nt++)
#pragma unroll
                for (int s = 0; s < 2; s++) {
                    int col = wn * 32 + nt * 8 + q * 2 + s;
                    float v = geluf(C[mm][nt][hx * 2 + s] + smf[pb + col]);
                    C[mm][nt][hx * 2 + s] = v;
                    ps += v; pq += v * v;
                }
            ps += __shfl_xor_sync(0xffffffffu, ps, 1);
            ps += __shfl_xor_sync(0xffffffffu, ps, 2);
            pq += __shfl_xor_sync(0xffffffffu, pq, 1);
            pq += __shfl_xor_sync(0xffffffffu, pq, 2);
            if (q == 0) {
                int row = wm * 32 + mm * 16 + hx * 8 + g;
                sSum[row * 4 + wn] = ps;
                sSq[row * 4 + wn]  = pq;
            }
        }
    __syncthreads();
#pragma unroll
    for (int mm = 0; mm < 2; mm++)
#pragma unroll
        for (int hx = 0; hx < 2; hx++) {
            int row = wm * 32 + mm * 16 + hx * 8 + g;
            float m = (sSum[row * 4] + sSum[row * 4 + 1]
                       + sSum[row * 4 + 2] + sSum[row * 4 + 3]) * (1.0f / 128.0f);
            float qv = (sSq[row * 4] + sSq[row * 4 + 1]
                        + sSq[row * 4 + 2] + sSq[row * 4 + 3]) * (1.0f / 128.0f);
            float rs = rsqrtf(qv - m * m + 1e-5f);
#pragma unroll
            for (int nt = 0; nt < 4; nt++)
#pragma unroll
                for (int s = 0; s < 2; s++) {
                    int col = wn * 32 + nt * 8 + q * 2 + s;
                    C[mm][nt][hx * 2 + s] =
                        (C[mm][nt][hx * 2 + s] - m) * rs * smf[pg + col] + smf[pbe + col];
                }
        }
}

#define ZERO_C(C) do { \
    _Pragma("unroll") for (int _m = 0; _m < 2; _m++) \
    _Pragma("unroll") for (int _n = 0; _n < 4; _n++) \
    _Pragma("unroll") for (int _s = 0; _s < 4; _s++) (C)[_m][_n][_s] = 0.f; } while (0)

// streamed K=128 GEMM: A resident in T chunks, W double-buffered
__device__ __forceinline__ void gemm_T4s(float* smf, uint32_t sb,
                                         const float* __restrict__ W,
                                         float C[2][4][4], int tid,
                                         int wm, int wn, int lane, int pl4) {
    copy_w_async(sb + F_W * 4, W, tid); CP_COMMIT();
    CP_WAIT0(); __syncthreads();
#pragma unroll 1
    for (int c = 0; c < 4; c++) {
        if (c < 3) {
            copy_w_async(sb + F_W * 4 + ((c + 1) & 1) * 16384, W + (c + 1) * 4096, tid);
            CP_COMMIT();
        }
        chunk_mma(smf + F_T + c * 2048, smf + F_W + (c & 1) * 4096,
                  C, wm, wn, lane, pl4);
        CP_WAIT0();
        __syncthreads();
    }
}

#define ROWBASE(r, rb, fg) \
    int rb = (((r) >> 5) * 2 + (((r) >> 4) & 1)) * 128 + ((r) & 7) * 16 \
             + (((r) >> 3) & 1); \
    int fg = fAg((r) & 7)
#define AFIDX(rb, fg, j) \
    (((j) >> 3) * 512 + (rb) + ((((j) & 3) ^ (fg)) << 2) + ((((j) >> 2) & 1) << 1))

#define RED2(p, a, b) asm volatile( \
    "red.global.add.v2.f32 [%0], {%1,%2};" :: "l"(p), "f"(a), "f"(b) : "memory")

// direct permuted store of C fragments to gout (matches edge gather layout)
__device__ __forceinline__ void store_perm(const float C[2][4][4],
                                           float* __restrict__ gout, int base,
                                           int wm, int wn, int g, int q) {
#pragma unroll
    for (int mm = 0; mm < 2; mm++)
#pragma unroll
        for (int hx = 0; hx < 2; hx++) {
            int row = wm * 32 + mm * 16 + hx * 8 + g;
            if (base + row >= NNODES) continue;
            float* go = gout + (size_t)(base + row) * DM + wn * 32 + q * 8;
            float4 f0, f1;
            f0.x = C[mm][0][hx * 2 + 0]; f0.y = C[mm][0][hx * 2 + 1];
            f0.z = C[mm][1][hx * 2 + 0]; f0.w = C[mm][1][hx * 2 + 1];
            f1.x = C[mm][2][hx * 2 + 0]; f1.y = C[mm][2][hx * 2 + 1];
            f1.z = C[mm][3][hx * 2 + 0]; f1.w = C[mm][3][hx * 2 + 1];
            *(float4*)go = f0;
            *(float4*)(go + 4) = f1;
        }
}

// ---------------- compose: fp32 weight products --------------------------------
__global__ void compose_k(const float* __restrict__ epw, const float* __restrict__ epb,
                          const float* __restrict__ emw, const float* __restrict__ emb_b,
                          const float* __restrict__ npw, const float* __restrict__ npb,
                          const float* __restrict__ nmw, const float* __restrict__ nmb,
                          float* __restrict__ cw) {
    int bi = blockIdx.x, j = threadIdx.x;
    int l = bi / 642, rr = bi % 642;
    const float *A, *B;
    float* out;
    float extra = 0.f;
    if (rr < 384) {
        A = epw + (size_t)l * 384 * 128 + rr * 128;
        B = emw + (l * 2) * 16384;
        out = cw + l * CWL + rr * 128;
    } else if (rr < 640) {
        int r2 = rr - 384;
        A = npw + (size_t)l * 256 * 128 + r2 * 128;
        B = nmw + (l * 2) * 16384;
        out = cw + l * CWL + 49152 + r2 * 128;
    } else if (rr == 640) {
        A = epb + l * 128; B = emw + (l * 2) * 16384;
        out = cw + l * CWL + 81920;
        extra = emb_b[(l * 2) * 128 + j];
    } else {
        A = npb + l * 128; B = nmw + (l * 2) * 16384;
        out = cw + l * CWL + 82048;
        extra = nmb[(l * 2) * 128 + j];
    }
    float acc = extra;
    for (int k = 0; k < 128; k++) acc += A[k] * B[k * 128 + j];
    out[j] = acc;
}

// ---------------- prep: all weights -> B-frag chunks; zero cnt -----------------
__global__ void prep_frag(const float* __restrict__ cw,
                          const float* __restrict__ emw,
                          const float* __restrict__ nmw,
                          const float* __restrict__ mow,
                          const float* __restrict__ wemb,
                          float* __restrict__ wt, float* __restrict__ cnt) {
    int b = blockIdx.x, tid = threadIdx.x;
    if (b < 69) {
        const float* M; int c;
        if (b < 8)       { int l = b >> 2; c = b & 3; M = cw + l * CWL; }
        else if (b < 16) { int l = (b - 8) >> 2; c = (b - 8) & 3;
                           M = emw + (l * 2 + 1) * 16384; }
        else if (b < 32) { int l = (b - 16) >> 3; c = (b - 16) & 7;
                           M = cw + l * CWL + 49152; }
        else if (b < 40) { int l = (b - 32) >> 2; c = (b - 32) & 3;
                           M = nmw + (l * 2 + 1) * 16384; }
        else if (b < 56) { int l = (b - 40) >> 3; int s = (b - 40) & 7;
                           c = s & 3; M = cw + l * CWL + 16384 + (s >> 2) * 16384; }
        else if (b < 60) { c = b - 56; M = mow; }
        else             { c = b - 60; M = wemb; }
        int kl = tid >> 3, n0 = (tid & 7) * 16;
#pragma unroll
        for (int j = 0; j < 16; j++) {
            int n = n0 + j;
            wt[b * 4096 + bidx(kl, n)] = tff(M[(c * 32 + kl) * 128 + n]);
        }
    } else {
        int i = (b - 69) * 256 + tid;
        if (i < NNODES) cnt[i] = 0.f;
    }
}

__global__ void zero_agg_k(float4* __restrict__ agg4) {
    int i = blockIdx.x * 256 + threadIdx.x;
    if (i < NNODES * 32) agg4[i] = make_float4(0.f, 0.f, 0.f, 0.f);
}

// ---------------- edge kernel (64 edges per CTA) --------------------------------
__global__ __launch_bounds__(256, 2) void edge_k(
    float* __restrict__ e,
    const int* __restrict__ snd, const int* __restrict__ rcv,
    const float* __restrict__ hs0, const float* __restrict__ hr0,
    const float* __restrict__ wE0, const float* __restrict__ b0c,
    const float* __restrict__ g0, const float* __restrict__ be0,
    const float* __restrict__ wM1, const float* __restrict__ b1,
    const float* __restrict__ g1, const float* __restrict__ be1,
    float* __restrict__ agg)
{
    extern __shared__ float smf[];
    uint32_t sb = smem_u32(smf);
    int tid = threadIdx.x, lane = tid & 31, wid = tid >> 5;
    int wm = wid >> 2, wn = wid & 3;
    int g = lane >> 2, q = lane & 3;
    int pl4 = (g * 4 + (q ^ fAg(g))) << 2;
    int base = blockIdx.x * 64;
    int r = tid >> 2, q4 = tid & 3;
    int* sI = (int*)smf;
    if (tid < 64)        sI[tid] = snd[base + tid];
    else if (tid < 128)  sI[tid] = rcv[base + tid - 64];
    if (tid < 128) {
        float* p = smf + F_PAR;
        p[tid] = b0c[tid];       p[128 + tid] = g0[tid];
        p[256 + tid] = be0[tid]; p[384 + tid] = b1[tid];
        p[512 + tid] = g1[tid];  p[640 + tid] = be1[tid];
    }
    stage_E32(smf + F_T + q4 * 2048, e + (size_t)(base + r) * DM + q4 * 32, r);
    __syncthreads();

    // C init = gathered hs0p + hr0p (permuted layout, coalesced 32B)
    float C[2][4][4];
#pragma unroll
    for (int mm = 0; mm < 2; mm++)
#pragma unroll
        for (int hx = 0; hx < 2; hx++) {
            int row = wm * 32 + mm * 16 + hx * 8 + g;
            const float4* hp = (const float4*)(hs0 + (size_t)sI[row] * DM
                                               + wn * 32 + q * 8);
            const float4* rp = (const float4*)(hr0 + (size_t)sI[64 + row] * DM
                                               + wn * 32 + q * 8);
            float4 a0 = hp[0], a1 = hp[1], c0 = rp[0], c1 = rp[1];
            C[mm][0][hx * 2 + 0] = a0.x + c0.x;
            C[mm][0][hx * 2 + 1] = a0.y + c0.y;
            C[mm][1][hx * 2 + 0] = a0.z + c0.z;
            C[mm][1][hx * 2 + 1] = a0.w + c0.w;
            C[mm][2][hx * 2 + 0] = a1.x + c1.x;
            C[mm][2][hx * 2 + 1] = a1.y + c1.y;
            C[mm][3][hx * 2 + 0] = a1.z + c1.z;
            C[mm][3][hx * 2 + 1] = a1.w + c1.w;
        }

    gemm_T4s(smf, sb, wE0, C, tid, wm, wn, lane, pl4);   // += e @ We0
    gelu_ln_ep(C, smf, wm, wn, lane, F_PAR, F_PAR + 128, F_PAR + 256);
    write_T(C, smf, F_T, wm, wn, lane, 1);               // X over e tile
    __syncthreads();
    ZERO_C(C);
    gemm_T4s(smf, sb, wM1, C, tid, wm, wn, lane, pl4);   // MLP layer 1
    gelu_ln_ep(C, smf, wm, wn, lane, F_PAR + 384, F_PAR + 512, F_PAR + 640);

    // direct epilogue: residual re-read from L2, store e, scatter agg
#pragma unroll
    for (int mm = 0; mm < 2; mm++)
#pragma unroll
        for (int hx = 0; hx < 2; hx++) {
            int row = wm * 32 + mm * 16 + hx * 8 + g;
            float* eo = e + (size_t)(base + row) * DM;
            float* ag = agg + (size_t)sI[64 + row] * DM;
#pragma unroll
            for (int nt = 0; nt < 4; nt++) {
                int col = wn * 32 + nt * 8 + q * 2;
                float2 er = *(const float2*)(eo + col);
                float v0 = C[mm][nt][hx * 2 + 0] + er.x;
                float v1 = C[mm][nt][hx * 2 + 1] + er.y;
                *(float2*)(eo + col) = make_float2(v0, v1);
                RED2(ag + col, v0, v1);
            }
        }
}

// ---------------- node kernel (64 nodes per CTA) --------------------------------
__global__ __launch_bounds__(256, 2) void node_k(
    float* __restrict__ h, const float* __restrict__ agg,
    const float* __restrict__ cnt,
    const float* __restrict__ wN0, const float* __restrict__ bn0c,
    const float* __restrict__ g0, const float* __restrict__ be0,
    const float* __restrict__ wM1, const float* __restrict__ b1,
    const float* __restrict__ g1, const float* __restrict__ be1,
    float* __restrict__ hs0, float* __restrict__ hr0,
    const float* __restrict__ wS0, const float* __restrict__ wR0,
    int tail)
{
    extern __shared__ float smf[];
    uint32_t sb = smem_u32(smf);
    int tid = threadIdx.x, lane = tid & 31, wid = tid >> 5;
    int wm = wid >> 2, wn = wid & 3;
    int g = lane >> 2, q = lane & 3;
    int pl4 = (g * 4 + (q ^ fAg(g))) << 2;
    int base = blockIdx.x * 64;
    int r = tid >> 2, q4 = tid & 3;
    if (tid < 64) {
        int n = min(base + tid, NNODES - 1);
        smf[tid] = 1.0f / fmaxf(cnt[n], 1.0f);
    }
    if (tid < 128) {
        float* p = smf + F_PAR;
        p[tid] = bn0c[tid];      p[128 + tid] = g0[tid];
        p[256 + tid] = be0[tid]; p[384 + tid] = b1[tid];
        p[512 + tid] = g1[tid];  p[640 + tid] = be1[tid];
    }
    int nr = min(base + r, NNODES - 1);
    stage_E32(smf + F_T + q4 * 2048, h + (size_t)nr * DM + q4 * 32, r);

    // GEMM1: K=256 streamed (chunks 0-3 = h resident, 4-7 = agg/cnt staged)
    float C[2][4][4];
    ZERO_C(C);
    copy_w_async(sb + F_W * 4, wN0, tid); CP_COMMIT();
    CP_WAIT0(); __syncthreads();
#pragma unroll 1
    for (int c = 0; c < 8; c++) {
        if (c < 7) {
            int cn = c + 1;
            copy_w_async(sb + F_W * 4 + (cn & 1) * 16384, wN0 + cn * 4096, tid);
            CP_COMMIT();
            if (cn >= 4)
                stage_Af8s(smf + F_SG + (cn & 1) * 2048,
                           agg + (size_t)nr * DM + ((cn & 3) << 5) + q4 * 8,
                           r, q4, smf[r]);
        }
        const float* As = (c < 4) ? smf + F_T + c * 2048
                                  : smf + F_SG + (c & 1) * 2048;
        chunk_mma(As, smf + F_W + (c & 1) * 4096, C, wm, wn, lane, pl4);
        CP_WAIT0();
        __syncthreads();
    }
    gelu_ln_ep(C, smf, wm, wn, lane, F_PAR, F_PAR + 128, F_PAR + 256);
    write_T(C, smf, F_T, wm, wn, lane, 1);
    __syncthreads();
    ZERO_C(C);
    gemm_T4s(smf, sb, wM1, C, tid, wm, wn, lane, pl4);   // MLP layer 1
    gelu_ln_ep(C, smf, wm, wn, lane, F_PAR + 384, F_PAR + 512, F_PAR + 640);

    // direct epilogue: h_new = C + h (L2 re-read); keep h_new in C for tails
#pragma unroll
    for (int mm = 0; mm < 2; mm++)
#pragma unroll
        for (int hx = 0; hx < 2; hx++) {
            int row = wm * 32 + mm * 16 + hx * 8 + g;
            if (base + row >= NNODES) continue;
            float* ho = h + (size_t)(base + row) * DM;
#pragma unroll
            for (int nt = 0; nt < 4; nt++) {
                int col = wn * 32 + nt * 8 + q * 2;
                float2 hv = *(const float2*)(ho + col);
                float v0 = C[mm][nt][hx * 2 + 0] + hv.x;
                float v1 = C[mm][nt][hx * 2 + 1] + hv.y;
                *(float2*)(ho + col) = make_float2(v0, v1);
                C[mm][nt][hx * 2 + 0] = v0;
                C[mm][nt][hx * 2 + 1] = v1;
            }
        }

    if (tail) {
        __syncthreads();
        write_T(C, smf, F_T, wm, wn, lane, 1);     // X = tf32(h_new)
        __syncthreads();
        ZERO_C(C);
        gemm_T4s(smf, sb, wS0, C, tid, wm, wn, lane, pl4);
        store_perm(C, hs0, base, wm, wn, g, q);
        ZERO_C(C);
        gemm_T4s(smf, sb, wR0, C, tid, wm, wn, lane, pl4);
        store_perm(C, hr0, base, wm, wn, g, q);
    }
}

// ---------------- node embedding (+ permuted hs0/hr0 for layer 0) ---------------
__global__ __launch_bounds__(256, 2) void emb_k(
    const float* __restrict__ nodes, const float* __restrict__ wE,
    const float* __restrict__ bias, float* __restrict__ h,
    float* __restrict__ hs0, float* __restrict__ hr0,
    const float* __restrict__ wS0, const float* __restrict__ wR0)
{
    extern __shared__ float smf[];
    uint32_t sb = smem_u32(smf);
    int tid = threadIdx.x, lane = tid & 31, wid = tid >> 5;
    int wm = wid >> 2, wn = wid & 3;
    int g = lane >> 2, q = lane & 3;
    int pl4 = (g * 4 + (q ^ fAg(g))) << 2;
    int base = blockIdx.x * 64;
    int r = tid >> 2, q4 = tid & 3;
    if (tid < 128) smf[F_PAR + tid] = bias[tid];
    int nr = min(base + r, NNODES - 1);
    const float* src = nodes + (size_t)nr * 288;

    // streamed GEMM over K=288: W + A both double-buffered
    float C[2][4][4];
    ZERO_C(C);
    copy_w_async(sb + F_W * 4, wE, tid); CP_COMMIT();
    stage_Af8(smf + F_SG, src + q4 * 8, r, q4);
    CP_WAIT0(); __syncthreads();
#pragma unroll 1
    for (int c = 0; c < 9; c++) {
        if (c < 8) {
            int cn = c + 1;
            copy_w_async(sb + F_W * 4 + (cn & 1) * 16384, wE + cn * 4096, tid);
            CP_COMMIT();
            stage_Af8(smf + F_SG + (cn & 1) * 2048, src + cn * 32 + q4 * 8, r, q4);
        }
        chunk_mma(smf + F_SG + (c & 1) * 2048, smf + F_W + (c & 1) * 4096,
                  C, wm, wn, lane, pl4);
        CP_WAIT0();
        __syncthreads();
    }
    // h = C + bias (direct store, permuted-free row layout), keep for tails
#pragma unroll
    for (int mm = 0; mm < 2; mm++)
#pragma unroll
        for (int hx = 0; hx < 2; hx++) {
            int row = wm * 32 + mm * 16 + hx * 8 + g;
            float* ho = h + (size_t)(base + row) * DM;
#pragma unroll
            for (int nt = 0; nt < 4; nt++) {
                int col = wn * 32 + nt * 8 + q * 2;
                float v0 = C[mm][nt][hx * 2 + 0] + smf[F_PAR + col];
                float v1 = C[mm][nt][hx * 2 + 1] + smf[F_PAR + col + 1];
                if (base + row < NNODES)
                    *(float2*)(ho + col) = make_float2(v0, v1);
                C[mm][nt][hx * 2 + 0] = v0;
                C[mm][nt][hx * 2 + 1] = v1;
            }
        }
    write_T(C, smf, F_T, wm, wn, lane, 1);    // X = tf32(h)
    __syncthreads();
    ZERO_C(C);
    gemm_T4s(smf, sb, wS0, C, tid, wm, wn, lane, pl4);
    store_perm(C, hs0, base, wm, wn, g, q);
    ZERO_C(C);
    gemm_T4s(smf, sb, wR0, C, tid, wm, wn, lane, pl4);
    store_perm(C, hr0, base, wm, wn, g, q);
}

// ---------------- output kernel ------------------------------------------------
__global__ __launch_bounds__(256, 2) void out_k(
    const float* __restrict__ h, const float* __restrict__ wO,
    const float* __restrict__ bias, const float* __restrict__ gg,
    const float* __restrict__ bb, const float* __restrict__ pw,
    const float* __restrict__ pb, float* __restrict__ out)
{
    extern __shared__ float smf[];
    uint32_t sb = smem_u32(smf);
    int tid = threadIdx.x, lane = tid & 31, wid = tid >> 5;
    int wm = wid >> 2, wn = wid & 3;
    int g = lane >> 2, q = lane & 3;
    int pl4 = (g * 4 + (q ^ fAg(g))) << 2;
    int base = blockIdx.x * 64;
    int r = tid >> 2, q4 = tid & 3;
    if (tid < 128) {
        smf[F_PAR + tid] = bias[tid];
        smf[F_PAR + 128 + tid] = gg[tid];
        smf[F_PAR + 256 + tid] = bb[tid];
    }
    int nr = min(base + r, NNODES - 1);
    stage_E32(smf + F_T + q4 * 2048, h + (size_t)nr * DM + q4 * 32, r);
    __syncthreads();

    float C[2][4][4];
    ZERO_C(C);
    gemm_T4s(smf, sb, wO, C, tid, wm, wn, lane, pl4);
    gelu_ln_ep(C, smf, wm, wn, lane, F_PAR, F_PAR + 128, F_PAR + 256);
    write_T(C, smf, F_T, wm, wn, lane, 0);
    // projection weights into W region (free after gemm)
    float* sPw = smf + F_W;
    for (int i = tid; i < 128 * PREDL; i += 256) sPw[i] = pw[i];
    if (tid < PREDL) smf[F_W + 128 * PREDL + tid] = pb[tid];
    __syncthreads();

    if (base + r < NNODES) {
        ROWBASE(r, rb, fg);
        float acc[6];
#pragma unroll
        for (int j = 0; j < 6; j++) acc[j] = smf[F_W + 128 * PREDL + q4 * 6 + j];
#pragma unroll 1
        for (int ch = 0; ch < 4; ch++) {
            const float* X = smf + F_T + ch * 2048;
#pragma unroll
            for (int j = 0; j < 32; j++) {
                float xv = X[AFIDX(rb, fg, j)];
                const float* pr = sPw + (ch * 32 + j) * PREDL + q4 * 6;
#pragma unroll
                for (int o = 0; o < 6; o++) acc[o] = fmaf(xv, pr[o], acc[o]);
            }
        }
        float* op = out + (size_t)(base + r) * PREDL + q4 * 6;
#pragma unroll
        for (int j = 0; j < 6; j++) op[j] = acc[j];
    }
}

// ---------------- edge embedding + in-degree count ------------------------------
__global__ void emb_edge_kernel(const float* __restrict__ edges,
                                const float* __restrict__ W,
                                const float* __restrict__ bias,
                                const int* __restrict__ rcv,
                                float* __restrict__ cnt,
                                float* __restrict__ e)
{
    int idx = blockIdx.x * 256 + threadIdx.x;
    if (idx >= NEDGES * 32) return;
    int ei = idx >> 5, c4 = idx & 31;
    float x0 = edges[2 * ei], x1 = edges[2 * ei + 1];
    float4 w0 = *(const float4*)(W + c4 * 4);
    float4 w1 = *(const float4*)(W + DM + c4 * 4);
    float4 b  = *(const float4*)(bias + c4 * 4);
    float4 o;
    o.x = fmaf(x0, w0.x, fmaf(x1, w1.x, b.x));
    o.y = fmaf(x0, w0.y, fmaf(x1, w1.y, b.y));
    o.z = fmaf(x0, w0.z, fmaf(x1, w1.z, b.z));
    o.w = fmaf(x0, w0.w, fmaf(x1, w1.w, b.w));
    *(float4*)(e + (size_t)ei * DM + c4 * 4) = o;
    if (c4 == 0) atomicAdd(cnt + rcv[ei], 1.0f);
}

// ---------------- launch ------------------------------------------------------
extern "C" void kernel_launch(void* const* d_in, const int* in_sizes, int n_in,
                              void* d_out, int out_size)
{
    const float* nodes        = (const float*)d_in[0];
    const float* edges        = (const float*)d_in[1];
    const int*   senders      = (const int*)d_in[2];
    const int*   receivers    = (const int*)d_in[3];
    const float* w_node_emb   = (const float*)d_in[4];
    const float* b_node_emb   = (const float*)d_in[5];
    const float* w_edge_emb   = (const float*)d_in[6];
    const float* b_edge_emb   = (const float*)d_in[7];
    const float* edge_proj_w  = (const float*)d_in[8];
    const float* edge_proj_b  = (const float*)d_in[9];
    const float* node_proj_w  = (const float*)d_in[10];
    const float* node_proj_b  = (const float*)d_in[11];
    const float* edge_mlp_w   = (const float*)d_in[12];
    const float* edge_mlp_b   = (const float*)d_in[13];
    const float* edge_ln_g    = (const float*)d_in[14];
    const float* edge_ln_b    = (const float*)d_in[15];
    const float* node_mlp_w   = (const float*)d_in[16];
    const float* node_mlp_b   = (const float*)d_in[17];
    const float* node_ln_g    = (const float*)d_in[18];
    const float* node_ln_b    = (const float*)d_in[19];
    const float* mlp_out_w    = (const float*)d_in[20];
    const float* mlp_out_b    = (const float*)d_in[21];
    const float* mlp_out_g    = (const float*)d_in[22];
    const float* mlp_out_beta = (const float*)d_in[23];
    const float* proj_w       = (const float*)d_in[24];
    const float* proj_b       = (const float*)d_in[25];
    float* out = (float*)d_out;

    float *h, *e, *agg, *cnt, *wt, *hs, *hr, *cw;
    cudaGetSymbolAddress((void**)&h,   g_h);
    cudaGetSymbolAddress((void**)&e,   g_e);
    cudaGetSymbolAddress((void**)&agg, g_agg);
    cudaGetSymbolAddress((void**)&cnt, g_cnt);
    cudaGetSymbolAddress((void**)&wt,  g_wt);
    cudaGetSymbolAddress((void**)&hs,  g_hs);
    cudaGetSymbolAddress((void**)&hr,  g_hr);
    cudaGetSymbolAddress((void**)&cw,  g_cw);

    cudaFuncSetAttribute(edge_k, cudaFuncAttributeMaxDynamicSharedMemorySize, SMEMB);
    cudaFuncSetAttribute(node_k, cudaFuncAttributeMaxDynamicSharedMemorySize, SMEMB);
    cudaFuncSetAttribute(emb_k,  cudaFuncAttributeMaxDynamicSharedMemorySize, SMEMB);
    cudaFuncSetAttribute(out_k,  cudaFuncAttributeMaxDynamicSharedMemorySize, SMEMB);

    int nblk = (NNODES + 63) / 64;  // 313

    compose_k<<<1284, 128>>>(edge_proj_w, edge_proj_b, edge_mlp_w, edge_mlp_b,
                             node_proj_w, node_proj_b, node_mlp_w, node_mlp_b, cw);
    prep_frag<<<148, 256>>>(cw, edge_mlp_w, node_mlp_w, mlp_out_w, w_node_emb,
                            wt, cnt);
    zero_agg_k<<<2500, 256>>>((float4*)agg);
    emb_k<<<nblk, 256, SMEMB>>>(nodes, wt + W_EMB * 4096, b_node_emb, h,
                                hs, hr, wt + W_S0(0) * 4096, wt + W_R0(0) * 4096);
    emb_edge_kernel<<<NEDGES * 32 / 256, 256>>>(edges, w_edge_emb, b_edge_emb,
                                                receivers, cnt, e);
    for (int l = 0; l < 2; l++) {
        edge_k<<<NEDGES / 64, 256, SMEMB>>>(
            e, senders, receivers, hs, hr,
            wt + W_E0(l) * 4096, cw + l * CWL + 81920,
            edge_ln_g + (l * 2 + 0) * 128, edge_ln_b + (l * 2 + 0) * 128,
            wt + W_M1E(l) * 4096, edge_mlp_b + (l * 2 + 1) * 128,
            edge_ln_g + (l * 2 + 1) * 128, edge_ln_b + (l * 2 + 1) * 128,
            agg);
        node_k<<<nblk, 256, SMEMB>>>(
            h, agg, cnt,
            wt + W_N0(l) * 4096, cw + l * CWL + 82048,
            node_ln_g + (l * 2 + 0) * 128, node_ln_b + (l * 2 + 0) * 128,
            wt + W_M1N(l) * 4096, node_mlp_b + (l * 2 + 1) * 128,
            node_ln_g + (l * 2 + 1) * 128, node_ln_b + (l * 2 + 1) * 128,
            hs, hr, wt + W_S0(1) * 4096, wt + W_R0(1) * 4096, l == 0);
        if (l == 0) zero_agg_k<<<2500, 256>>>((float4*)agg);
    }
    out_k<<<nblk, 256, SMEMB>>>(h, wt + W_OUT * 4096, mlp_out_b, mlp_out_g,
                                mlp_out_beta, proj_w, proj_b, out);
}

// round 11
// speedup vs baseline: 3.0304x; 1.0571x over previous
#include <cuda_runtime.h>
#include <cstdint>

#define NNODES 20000
#define NEDGES 320000
#define DM 128
#define PREDL 24

// ---------------- device scratch ----------------------------------------------
__device__ float g_h[NNODES * DM];
__device__ float g_e[(size_t)NEDGES * DM];
__device__ float g_agg[NNODES * DM];
__device__ float g_cnt[NNODES];
__device__ float g_hs[NNODES * DM];     // (h @ Ws0) permuted
__device__ float g_hr[NNODES * DM];     // (h @ Wr0) permuted
#define CWL 82176
__device__ float g_cw[2 * CWL];         // composed weights (fp32)
__device__ float g_wt[69 * 4096];       // fragment-layout weights (tf32)

// g_wt chunk offsets
#define W_E0(l)  ((l) * 4)
#define W_M1E(l) (8 + (l) * 4)
#define W_N0(l)  (16 + (l) * 8)
#define W_M1N(l) (32 + (l) * 4)
#define W_S0(l)  (40 + (l) * 8)
#define W_R0(l)  (44 + (l) * 8)
#define W_OUT    56
#define W_EMB    60

// ---------------- smem float offsets (M=64 tile) --------------------------------
// [0..127]  sI (edge) / inv (node)
#define F_SUM 128               // 256
#define F_SQ  384               // 256
#define F_PAR 640               // 1152 params
#define F_W   1792              // 2 x 4096 W double buffer
#define F_T   (F_W + 8192)      // 4 x 2048 activation tile
#define SMEMB ((F_T + 8192) * 4)   // 72704 B -> 2 CTAs/SM

// ---------------- helpers ------------------------------------------------------
__device__ __forceinline__ uint32_t tfr(float x) {
    uint32_t r;
    asm("cvt.rna.tf32.f32 %0, %1;" : "=r"(r) : "f"(x));
    return r;
}
__device__ __forceinline__ float tff(float x) { return __uint_as_float(tfr(x)); }

__device__ __forceinline__ uint32_t smem_u32(const void* p) {
    uint32_t a;
    asm("{ .reg .u64 t; cvta.to.shared.u64 t, %1; cvt.u32.u64 %0, t; }"
        : "=r"(a) : "l"(p));
    return a;
}

__device__ __forceinline__ void mma8(float c[4], uint32_t a0, uint32_t a1,
                                     uint32_t a2, uint32_t a3,
                                     uint32_t b0, uint32_t b1) {
    asm volatile(
        "mma.sync.aligned.m16n8k8.row.col.f32.tf32.tf32.f32 "
        "{%0,%1,%2,%3}, {%4,%5,%6,%7}, {%8,%9}, {%0,%1,%2,%3};"
        : "+f"(c[0]), "+f"(c[1]), "+f"(c[2]), "+f"(c[3])
        : "r"(a0), "r"(a1), "r"(a2), "r"(a3), "r"(b0), "r"(b1));
}

__device__ __forceinline__ float geluf(float x) {
    float x3 = x * x * x;
    return 0.5f * x * (1.0f + tanhf(0.7978845608028654f * (x + 0.044715f * x3)));
}

__device__ __forceinline__ int fAg(int g) { return (g ^ (g >> 2)) & 3; }

// A-fragment index in a 2048-float chunk (64 rows x 32 k)
__device__ __forceinline__ int aidx(int row, int kl) {
    int wm = row >> 5, mm = (row >> 4) & 1, r8 = (row >> 3) & 1, g = row & 7;
    int kk = kl >> 3, k4 = (kl >> 2) & 1, tig = kl & 3;
    return (((kk * 2 + wm) * 2 + mm) << 7) + ((g * 4 + (tig ^ fAg(g))) << 2)
           + r8 + (k4 << 1);
}
// B-fragment index in a 4096-float chunk
__device__ __forceinline__ int bidx(int kl, int n) {
    int kk = kl >> 3, k4 = (kl >> 2) & 1, tig = kl & 3;
    int wn = n >> 5, ntp = (n >> 4) & 1, ntb = (n >> 3) & 1, gq = n & 7;
    return (((kk * 4 + wn) * 2 + ntp) << 7) + ((gq * 4 + tig) << 2)
           + ntb * 2 + k4;
}

#define CP16(daddr, src) asm volatile( \
    "cp.async.cg.shared.global [%0], [%1], 16;" :: "r"(daddr), "l"(src))
#define CP_COMMIT() asm volatile("cp.async.commit_group;" ::: "memory")
#define CP_WAIT0()  asm volatile("cp.async.wait_group 0;" ::: "memory")

// one 4096-float W chunk via cp.async (256 threads x 4 x 16B)
__device__ __forceinline__ void copy_w_async(uint32_t dsts,
                                             const float* __restrict__ src,
                                             int tid) {
    CP16(dsts + tid * 16, src + tid * 4);
    CP16(dsts + (tid + 256) * 16, src + (tid + 256) * 4);
    CP16(dsts + (tid + 512) * 16, src + (tid + 512) * 4);
    CP16(dsts + (tid + 768) * 16, src + (tid + 768) * 4);
}

// one 32-wide K chunk; warp covers 32 rows x 32 cols (A chunk = 2048 floats)
__device__ __forceinline__ void chunk_mma(const float* __restrict__ sA,
                                          const float* __restrict__ sW,
                                          float C[2][4][4], int wm, int wn,
                                          int lane, int pl4) {
#pragma unroll
    for (int kk = 0; kk < 4; kk++) {
        float4 b0 = *(const float4*)(sW + (((kk * 4 + wn) * 2 + 0) << 7)
                                     + (lane << 2));
        float4 b1 = *(const float4*)(sW + (((kk * 4 + wn) * 2 + 1) << 7)
                                     + (lane << 2));
#pragma unroll
        for (int mm = 0; mm < 2; mm++) {
            float4 av = *(const float4*)(sA + (((kk * 2 + wm) * 2 + mm) << 7) + pl4);
            uint32_t a0 = __float_as_uint(av.x), a1 = __float_as_uint(av.y);
            uint32_t a2 = __float_as_uint(av.z), a3 = __float_as_uint(av.w);
            mma8(C[mm][0], a0, a1, a2, a3,
                 __float_as_uint(b0.x), __float_as_uint(b0.y));
            mma8(C[mm][1], a0, a1, a2, a3,
                 __float_as_uint(b0.z), __float_as_uint(b0.w));
            mma8(C[mm][2], a0, a1, a2, a3,
                 __float_as_uint(b1.x), __float_as_uint(b1.y));
            mma8(C[mm][3], a0, a1, a2, a3,
                 __float_as_uint(b1.z), __float_as_uint(b1.w));
        }
    }
}

__device__ __forceinline__ void stage_Af8(float* chunk, const float* __restrict__ src,
                                          int r, int q4) {
    float4 v0 = *(const float4*)(src);
    float4 v1 = *(const float4*)(src + 4);
    chunk[aidx(r, q4 * 8 + 0)] = tff(v0.x);
    chunk[aidx(r, q4 * 8 + 1)] = tff(v0.y);
    chunk[aidx(r, q4 * 8 + 2)] = tff(v0.z);
    chunk[aidx(r, q4 * 8 + 3)] = tff(v0.w);
    chunk[aidx(r, q4 * 8 + 4)] = tff(v1.x);
    chunk[aidx(r, q4 * 8 + 5)] = tff(v1.y);
    chunk[aidx(r, q4 * 8 + 6)] = tff(v1.z);
    chunk[aidx(r, q4 * 8 + 7)] = tff(v1.w);
}
__device__ __forceinline__ void stage_Af8s(float* chunk, const float* __restrict__ src,
                                           int r, int q4, float sc) {
    float4 v0 = *(const float4*)(src);
    float4 v1 = *(const float4*)(src + 4);
    chunk[aidx(r, q4 * 8 + 0)] = tff(v0.x * sc);
    chunk[aidx(r, q4 * 8 + 1)] = tff(v0.y * sc);
    chunk[aidx(r, q4 * 8 + 2)] = tff(v0.z * sc);
    chunk[aidx(r, q4 * 8 + 3)] = tff(v0.w * sc);
    chunk[aidx(r, q4 * 8 + 4)] = tff(v1.x * sc);
    chunk[aidx(r, q4 * 8 + 5)] = tff(v1.y * sc);
    chunk[aidx(r, q4 * 8 + 6)] = tff(v1.z * sc);
    chunk[aidx(r, q4 * 8 + 7)] = tff(v1.w * sc);
}

// stage 32 cols of a row EXACT into A-frag chunk
__device__ __forceinline__ void stage_E32(float* chunk, const float* __restrict__ src,
                                          int r) {
#pragma unroll
    for (int i = 0; i < 8; i++) {
        float4 v = *(const float4*)(src + i * 4);
        chunk[aidx(r, i * 4 + 0)] = v.x;
        chunk[aidx(r, i * 4 + 1)] = v.y;
        chunk[aidx(r, i * 4 + 2)] = v.z;
        chunk[aidx(r, i * 4 + 3)] = v.w;
    }
}

__device__ __forceinline__ void write_T(float C[2][4][4], float* smf, int fbase,
                                        int wm, int wn, int lane, int cvt) {
    int g = lane >> 2, q = lane & 3;
#pragma unroll
    for (int mm = 0; mm < 2; mm++)
#pragma unroll
        for (int hx = 0; hx < 2; hx++) {
            int row = wm * 32 + mm * 16 + hx * 8 + g;
#pragma unroll
            for (int nt = 0; nt < 4; nt++)
#pragma unroll
                for (int s = 0; s < 2; s++) {
                    int col = wn * 32 + nt * 8 + q * 2 + s;
                    float v = C[mm][nt][hx * 2 + s];
                    smf[fbase + (col >> 5) * 2048 + aidx(row, col & 31)] =
                        cvt ? tff(v) : v;
                }
        }
}

__device__ __forceinline__ void gelu_ln_ep(float C[2][4][4], float* smf,
                                           int wm, int wn, int lane,
                                           int pb, int pg, int pbe) {
    int g = lane >> 2, q = lane & 3;
    float* sSum = smf + F_SUM;
    float* sSq  = smf + F_SQ;
#pragma unroll
    for (int mm = 0; mm < 2; mm++)
#pragma unroll
        for (int hx = 0; hx < 2; hx++) {
            float ps = 0.f, pq = 0.f;
#pragma unroll
            for (int nt = 0; nt < 4; nt++)
#pragma unroll
                for (int s = 0; s < 2; s++) {
                    int col = wn * 32 + nt * 8 + q * 2 + s;
                    float v = geluf(C[mm][nt][hx * 2 + s] + smf[pb + col]);
                    C[mm][nt][hx * 2 + s] = v;
                    ps += v; pq += v * v;
                }
            ps += __shfl_xor_sync(0xffffffffu, ps, 1);
            ps += __shfl_xor_sync(0xffffffffu, ps, 2);
            pq += __shfl_xor_sync(0xffffffffu, pq, 1);
            pq += __shfl_xor_sync(0xffffffffu, pq, 2);
            if (q == 0) {
                int row = wm * 32 + mm * 16 + hx * 8 + g;
                sSum[row * 4 + wn] = ps;
                sSq[row * 4 + wn]  = pq;
            }
        }
    __syncthreads();
#pragma unroll
    for (int mm = 0; mm < 2; mm++)
#pragma unroll
        for (int hx = 0; hx < 2; hx++) {
            int row = wm * 32 + mm * 16 + hx * 8 + g;
            float m = (sSum[row * 4] + sSum[row * 4 + 1]
                       + sSum[row * 4 + 2] + sSum[row * 4 + 3]) * (1.0f / 128.0f);
            float qv = (sSq[row * 4] + sSq[row * 4 + 1]
                        + sSq[row * 4 + 2] + sSq[row * 4 + 3]) * (1.0f / 128.0f);
            float rs = rsqrtf(qv - m * m + 1e-5f);
#pragma unroll
            for (int nt = 0; nt < 4; nt++)
#pragma unroll
                for (int s = 0; s < 2; s++) {
                    int col = wn * 32 + nt * 8 + q * 2 + s;
                    C[mm][nt][hx * 2 + s] =
                        (C[mm][nt][hx * 2 + s] - m) * rs * smf[pg + col] + smf[pbe + col];
                }
        }
}

#define ZERO_C(C) do { \
    _Pragma("unroll") for (int _m = 0; _m < 2; _m++) \
    _Pragma("unroll") for (int _n = 0; _n < 4; _n++) \
    _Pragma("unroll") for (int _s = 0; _s < 4; _s++) (C)[_m][_n][_s] = 0.f; } while (0)

// streamed K=128 GEMM: A resident in T chunks, W double-buffered
__device__ __forceinline__ void gemm_T4s(float* smf, uint32_t sb,
                                         const float* __restrict__ W,
                                         float C[2][4][4], int tid,
                                         int wm, int wn, int lane, int pl4) {
    copy_w_async(sb + F_W * 4, W, tid); CP_COMMIT();
    CP_WAIT0(); __syncthreads();
#pragma unroll 1
    for (int c = 0; c < 4; c++) {
        if (c < 3) {
            copy_w_async(sb + F_W * 4 + ((c + 1) & 1) * 16384, W + (c + 1) * 4096, tid);
            CP_COMMIT();
        }
        chunk_mma(smf + F_T + c * 2048, smf + F_W + (c & 1) * 4096,
                  C, wm, wn, lane, pl4);
        CP_WAIT0();
        __syncthreads();
    }
}

#define ROWBASE(r, rb, fg) \
    int rb = (((r) >> 5) * 2 + (((r) >> 4) & 1)) * 128 + ((r) & 7) * 16 \
             + (((r) >> 3) & 1); \
    int fg = fAg((r) & 7)
#define AFIDX(rb, fg, j) \
    (((j) >> 3) * 512 + (rb) + ((((j) & 3) ^ (fg)) << 2) + ((((j) >> 2) & 1) << 1))

#define RED2(p, a, b) asm volatile( \
    "red.global.add.v2.f32 [%0], {%1,%2};" :: "l"(p), "f"(a), "f"(b) : "memory")

// direct permuted store of C fragments to gout (matches edge gather layout)
__device__ __forceinline__ void store_perm(const float C[2][4][4],
                                           float* __restrict__ gout, int base,
                                           int wm, int wn, int g, int q) {
#pragma unroll
    for (int mm = 0; mm < 2; mm++)
#pragma unroll
        for (int hx = 0; hx < 2; hx++) {
            int row = wm * 32 + mm * 16 + hx * 8 + g;
            if (base + row >= NNODES) continue;
            float* go = gout + (size_t)(base + row) * DM + wn * 32 + q * 8;
            float4 f0, f1;
            f0.x = C[mm][0][hx * 2 + 0]; f0.y = C[mm][0][hx * 2 + 1];
            f0.z = C[mm][1][hx * 2 + 0]; f0.w = C[mm][1][hx * 2 + 1];
            f1.x = C[mm][2][hx * 2 + 0]; f1.y = C[mm][2][hx * 2 + 1];
            f1.z = C[mm][3][hx * 2 + 0]; f1.w = C[mm][3][hx * 2 + 1];
            *(float4*)go = f0;
            *(float4*)(go + 4) = f1;
        }
}

// ---------------- compose: fp32 weight products --------------------------------
__global__ void compose_k(const float* __restrict__ epw, const float* __restrict__ epb,
                          const float* __restrict__ emw, const float* __restrict__ emb_b,
                          const float* __restrict__ npw, const float* __restrict__ npb,
                          const float* __restrict__ nmw, const float* __restrict__ nmb,
                          float* __restrict__ cw) {
    int bi = blockIdx.x, j = threadIdx.x;
    int l = bi / 642, rr = bi % 642;
    const float *A, *B;
    float* out;
    float extra = 0.f;
    if (rr < 384) {
        A = epw + (size_t)l * 384 * 128 + rr * 128;
        B = emw + (l * 2) * 16384;
        out = cw + l * CWL + rr * 128;
    } else if (rr < 640) {
        int r2 = rr - 384;
        A = npw + (size_t)l * 256 * 128 + r2 * 128;
        B = nmw + (l * 2) * 16384;
        out = cw + l * CWL + 49152 + r2 * 128;
    } else if (rr == 640) {
        A = epb + l * 128; B = emw + (l * 2) * 16384;
        out = cw + l * CWL + 81920;
        extra = emb_b[(l * 2) * 128 + j];
    } else {
        A = npb + l * 128; B = nmw + (l * 2) * 16384;
        out = cw + l * CWL + 82048;
        extra = nmb[(l * 2) * 128 + j];
    }
    float acc = extra;
    for (int k = 0; k < 128; k++) acc += A[k] * B[k * 128 + j];
    out[j] = acc;
}

// ---------------- prep: all weights -> B-frag chunks; zero cnt -----------------
__global__ void prep_frag(const float* __restrict__ cw,
                          const float* __restrict__ emw,
                          const float* __restrict__ nmw,
                          const float* __restrict__ mow,
                          const float* __restrict__ wemb,
                          float* __restrict__ wt, float* __restrict__ cnt) {
    int b = blockIdx.x, tid = threadIdx.x;
    if (b < 69) {
        const float* M; int c;
        if (b < 8)       { int l = b >> 2; c = b & 3; M = cw + l * CWL; }
        else if (b < 16) { int l = (b - 8) >> 2; c = (b - 8) & 3;
                           M = emw + (l * 2 + 1) * 16384; }
        else if (b < 32) { int l = (b - 16) >> 3; c = (b - 16) & 7;
                           M = cw + l * CWL + 49152; }
        else if (b < 40) { int l = (b - 32) >> 2; c = (b - 32) & 3;
                           M = nmw + (l * 2 + 1) * 16384; }
        else if (b < 56) { int l = (b - 40) >> 3; int s = (b - 40) & 7;
                           c = s & 3; M = cw + l * CWL + 16384 + (s >> 2) * 16384; }
        else if (b < 60) { c = b - 56; M = mow; }
        else             { c = b - 60; M = wemb; }
        int kl = tid >> 3, n0 = (tid & 7) * 16;
#pragma unroll
        for (int j = 0; j < 16; j++) {
            int n = n0 + j;
            wt[b * 4096 + bidx(kl, n)] = tff(M[(c * 32 + kl) * 128 + n]);
        }
    } else {
        int i = (b - 69) * 256 + tid;
        if (i < NNODES) cnt[i] = 0.f;
    }
}

__global__ void count_kernel(const int* __restrict__ rcv, float* __restrict__ cnt) {
    int i = blockIdx.x * 256 + threadIdx.x;
    if (i < NEDGES) atomicAdd(cnt + rcv[i], 1.0f);
}

__global__ void zero_agg_k(float4* __restrict__ agg4) {
    int i = blockIdx.x * 256 + threadIdx.x;
    if (i < NNODES * 32) agg4[i] = make_float4(0.f, 0.f, 0.f, 0.f);
}

// ---------------- edge kernel (64 edges per CTA) --------------------------------
// layer0: e tile computed inline from edges (emb fused); stores e. layer1: reads e, no store.
__global__ __launch_bounds__(256, 2) void edge_k(
    float* __restrict__ e, const float* __restrict__ edges,
    const int* __restrict__ snd, const int* __restrict__ rcv,
    const float* __restrict__ hs0, const float* __restrict__ hr0,
    const float* __restrict__ wem, const float* __restrict__ bem,
    const float* __restrict__ wE0, const float* __restrict__ b0c,
    const float* __restrict__ g0, const float* __restrict__ be0,
    const float* __restrict__ wM1, const float* __restrict__ b1,
    const float* __restrict__ g1, const float* __restrict__ be1,
    float* __restrict__ agg, int layer0)
{
    extern __shared__ float smf[];
    uint32_t sb = smem_u32(smf);
    int tid = threadIdx.x, lane = tid & 31, wid = tid >> 5;
    int wm = wid >> 2, wn = wid & 3;
    int g = lane >> 2, q = lane & 3;
    int pl4 = (g * 4 + (q ^ fAg(g))) << 2;
    int base = blockIdx.x * 64;
    int r = tid >> 2, q4 = tid & 3;
    int* sI = (int*)smf;
    if (tid < 64)        sI[tid] = snd[base + tid];
    else if (tid < 128)  sI[tid] = rcv[base + tid - 64];
    if (tid < 128) {
        float* p = smf + F_PAR;
        p[tid] = b0c[tid];       p[128 + tid] = g0[tid];
        p[256 + tid] = be0[tid]; p[384 + tid] = b1[tid];
        p[512 + tid] = g1[tid];  p[640 + tid] = be1[tid];
        if (layer0) {
            p[768 + tid]  = wem[tid];
            p[896 + tid]  = wem[128 + tid];
            p[1024 + tid] = bem[tid];
        }
    }
    if (layer0) {
        __syncthreads();   // wem/bem visible
        float2 xy = *(const float2*)(edges + 2 * (size_t)(base + r));
        const float* w0 = smf + F_PAR + 768;
        const float* w1 = smf + F_PAR + 896;
        const float* bb = smf + F_PAR + 1024;
        float* Tc = smf + F_T + q4 * 2048;
#pragma unroll
        for (int i = 0; i < 32; i++) {
            int col = q4 * 32 + i;
            Tc[aidx(r, i)] =
                tff(fmaf(xy.x, w0[col], fmaf(xy.y, w1[col], bb[col])));
        }
    } else {
        stage_E32(smf + F_T + q4 * 2048,
                  e + (size_t)(base + r) * DM + q4 * 32, r);
    }
    __syncthreads();

    // C init = gathered hs0p + hr0p (permuted layout, coalesced 32B)
    float C[2][4][4];
#pragma unroll
    for (int mm = 0; mm < 2; mm++)
#pragma unroll
        for (int hx = 0; hx < 2; hx++) {
            int row = wm * 32 + mm * 16 + hx * 8 + g;
            const float4* hp = (const float4*)(hs0 + (size_t)sI[row] * DM
                                               + wn * 32 + q * 8);
            const float4* rp = (const float4*)(hr0 + (size_t)sI[64 + row] * DM
                                               + wn * 32 + q * 8);
            float4 a0 = hp[0], a1 = hp[1], c0 = rp[0], c1 = rp[1];
            C[mm][0][hx * 2 + 0] = a0.x + c0.x;
            C[mm][0][hx * 2 + 1] = a0.y + c0.y;
            C[mm][1][hx * 2 + 0] = a0.z + c0.z;
            C[mm][1][hx * 2 + 1] = a0.w + c0.w;
            C[mm][2][hx * 2 + 0] = a1.x + c1.x;
            C[mm][2][hx * 2 + 1] = a1.y + c1.y;
            C[mm][3][hx * 2 + 0] = a1.z + c1.z;
            C[mm][3][hx * 2 + 1] = a1.w + c1.w;
        }

    gemm_T4s(smf, sb, wE0, C, tid, wm, wn, lane, pl4);   // += e @ We0
    gelu_ln_ep(C, smf, wm, wn, lane, F_PAR, F_PAR + 128, F_PAR + 256);
    write_T(C, smf, F_T, wm, wn, lane, 1);               // X over e tile
    __syncthreads();
    ZERO_C(C);
    gemm_T4s(smf, sb, wM1, C, tid, wm, wn, lane, pl4);   // MLP layer 1
    gelu_ln_ep(C, smf, wm, wn, lane, F_PAR + 384, F_PAR + 512, F_PAR + 640);

    // epilogue: residual (recomputed for layer0, re-read for layer1), scatter
    const float* w0 = smf + F_PAR + 768;
    const float* w1 = smf + F_PAR + 896;
    const float* bb = smf + F_PAR + 1024;
#pragma unroll
    for (int mm = 0; mm < 2; mm++)
#pragma unroll
        for (int hx = 0; hx < 2; hx++) {
            int row = wm * 32 + mm * 16 + hx * 8 + g;
            float ex0 = 0.f, ex1 = 0.f;
            if (layer0) {
                float2 xy = *(const float2*)(edges + 2 * (size_t)(base + row));
                ex0 = xy.x; ex1 = xy.y;
            }
            float* eo = e + (size_t)(base + row) * DM;
            float* ag = agg + (size_t)sI[64 + row] * DM;
#pragma unroll
            for (int nt = 0; nt < 4; nt++) {
                int col = wn * 32 + nt * 8 + q * 2;
                float r0v, r1v;
                if (layer0) {
                    r0v = fmaf(ex0, w0[col], fmaf(ex1, w1[col], bb[col]));
                    r1v = fmaf(ex0, w0[col + 1], fmaf(ex1, w1[col + 1], bb[col + 1]));
                } else {
                    float2 er = *(const float2*)(eo + col);
                    r0v = er.x; r1v = er.y;
                }
                float v0 = C[mm][nt][hx * 2 + 0] + r0v;
                float v1 = C[mm][nt][hx * 2 + 1] + r1v;
                if (layer0) *(float2*)(eo + col) = make_float2(v0, v1);
                RED2(ag + col, v0, v1);
            }
        }
}

// ---------------- node kernel (64 nodes per CTA) --------------------------------
// tail: emit hs0/hr0 for next layer.  do_out: fused output head (final layer).
__global__ __launch_bounds__(256, 2) void node_k(
    float* __restrict__ h, const float* __restrict__ agg,
    const float* __restrict__ cnt,
    const float* __restrict__ wN0, const float* __restrict__ bn0c,
    const float* __restrict__ g0, const float* __restrict__ be0,
    const float* __restrict__ wM1, const float* __restrict__ b1,
    const float* __restrict__ g1, const float* __restrict__ be1,
    float* __restrict__ hs0, float* __restrict__ hr0,
    const float* __restrict__ wS0, const float* __restrict__ wR0, int tail,
    const float* __restrict__ wO, const float* __restrict__ ob,
    const float* __restrict__ og, const float* __restrict__ obb,
    const float* __restrict__ pw, const float* __restrict__ pb,
    float* __restrict__ outp, int do_out)
{
    extern __shared__ float smf[];
    uint32_t sb = smem_u32(smf);
    int tid = threadIdx.x, lane = tid & 31, wid = tid >> 5;
    int wm = wid >> 2, wn = wid & 3;
    int g = lane >> 2, q = lane & 3;
    int pl4 = (g * 4 + (q ^ fAg(g))) << 2;
    int base = blockIdx.x * 64;
    int r = tid >> 2, q4 = tid & 3;
    if (tid < 64) {
        int n = min(base + tid, NNODES - 1);
        smf[tid] = 1.0f / fmaxf(cnt[n], 1.0f);
    }
    if (tid < 128) {
        float* p = smf + F_PAR;
        p[tid] = bn0c[tid];      p[128 + tid] = g0[tid];
        p[256 + tid] = be0[tid]; p[384 + tid] = b1[tid];
        p[512 + tid] = g1[tid];  p[640 + tid] = be1[tid];
        if (do_out) {
            p[768 + tid]  = ob[tid];
            p[896 + tid]  = og[tid];
            p[1024 + tid] = obb[tid];
        }
    }
    int nr = min(base + r, NNODES - 1);
    stage_E32(smf + F_T + q4 * 2048, h + (size_t)nr * DM + q4 * 32, r);

    // GEMM1: K=256, agg chunks staged in-place into consumed T slots
    float C[2][4][4];
    ZERO_C(C);
    copy_w_async(sb + F_W * 4, wN0, tid); CP_COMMIT();
    CP_WAIT0(); __syncthreads();
#pragma unroll 1
    for (int c = 0; c < 8; c++) {
        if (c < 7) {
            int cn = c + 1;
            copy_w_async(sb + F_W * 4 + (cn & 1) * 16384, wN0 + cn * 4096, tid);
            CP_COMMIT();
            if (cn >= 4)
                stage_Af8s(smf + F_T + (cn & 3) * 2048,
                           agg + (size_t)nr * DM + ((cn & 3) << 5) + q4 * 8,
                           r, q4, smf[r]);
        }
        chunk_mma(smf + F_T + (c & 3) * 2048, smf + F_W + (c & 1) * 4096,
                  C, wm, wn, lane, pl4);
        CP_WAIT0();
        __syncthreads();
    }
    gelu_ln_ep(C, smf, wm, wn, lane, F_PAR, F_PAR + 128, F_PAR + 256);
    write_T(C, smf, F_T, wm, wn, lane, 1);
    __syncthreads();
    ZERO_C(C);
    gemm_T4s(smf, sb, wM1, C, tid, wm, wn, lane, pl4);   // MLP layer 1
    gelu_ln_ep(C, smf, wm, wn, lane, F_PAR + 384, F_PAR + 512, F_PAR + 640);

    // epilogue: h_new = C + h; store h unless final layer; keep h_new in C
#pragma unroll
    for (int mm = 0; mm < 2; mm++)
#pragma unroll
        for (int hx = 0; hx < 2; hx++) {
            int row = wm * 32 + mm * 16 + hx * 8 + g;
            if (base + row >= NNODES) continue;
            float* ho = h + (size_t)(base + row) * DM;
#pragma unroll
            for (int nt = 0; nt < 4; nt++) {
                int col = wn * 32 + nt * 8 + q * 2;
                float2 hv = *(const float2*)(ho + col);
                float v0 = C[mm][nt][hx * 2 + 0] + hv.x;
                float v1 = C[mm][nt][hx * 2 + 1] + hv.y;
                if (!do_out) *(float2*)(ho + col) = make_float2(v0, v1);
                C[mm][nt][hx * 2 + 0] = v0;
                C[mm][nt][hx * 2 + 1] = v1;
            }
        }

    if (tail) {
        __syncthreads();
        write_T(C, smf, F_T, wm, wn, lane, 1);     // X = tf32(h_new)
        __syncthreads();
        ZERO_C(C);
        gemm_T4s(smf, sb, wS0, C, tid, wm, wn, lane, pl4);
        store_perm(C, hs0, base, wm, wn, g, q);
        ZERO_C(C);
        gemm_T4s(smf, sb, wR0, C, tid, wm, wn, lane, pl4);
        store_perm(C, hr0, base, wm, wn, g, q);
    }
    if (do_out) {
        __syncthreads();
        write_T(C, smf, F_T, wm, wn, lane, 0);     // exact h_new
        __syncthreads();
        ZERO_C(C);
        gemm_T4s(smf, sb, wO, C, tid, wm, wn, lane, pl4);
        gelu_ln_ep(C, smf, wm, wn, lane, F_PAR + 768, F_PAR + 896, F_PAR + 1024);
        write_T(C, smf, F_T, wm, wn, lane, 0);
        float* sPw = smf + F_W;
        for (int i = tid; i < 128 * PREDL; i += 256) sPw[i] = pw[i];
        if (tid < PREDL) smf[F_W + 128 * PREDL + tid] = pb[tid];
        __syncthreads();
        if (base + r < NNODES) {
            ROWBASE(r, rb, fg);
            float acc[6];
#pragma unroll
            for (int j = 0; j < 6; j++)
                acc[j] = smf[F_W + 128 * PREDL + q4 * 6 + j];
#pragma unroll 1
            for (int ch = 0; ch < 4; ch++) {
                const float* X = smf + F_T + ch * 2048;
#pragma unroll
                for (int j = 0; j < 32; j++) {
                    float xv = X[AFIDX(rb, fg, j)];
                    const float* pr = sPw + (ch * 32 + j) * PREDL + q4 * 6;
#pragma unroll
                    for (int o = 0; o < 6; o++) acc[o] = fmaf(xv, pr[o], acc[o]);
                }
            }
            float* op = outp + (size_t)(base + r) * PREDL + q4 * 6;
#pragma unroll
            for (int j = 0; j < 6; j++) op[j] = acc[j];
        }
    }
}

// ---------------- node embedding (+ permuted hs0/hr0 for layer 0) ---------------
__global__ __launch_bounds__(256, 2) void emb_k(
    const float* __restrict__ nodes, const float* __restrict__ wE,
    const float* __restrict__ bias, float* __restrict__ h,
    float* __restrict__ hs0, float* __restrict__ hr0,
    const float* __restrict__ wS0, const float* __restrict__ wR0)
{
    extern __shared__ float smf[];
    uint32_t sb = smem_u32(smf);
    int tid = threadIdx.x, lane = tid & 31, wid = tid >> 5;
    int wm = wid >> 2, wn = wid & 3;
    int g = lane >> 2, q = lane & 3;
    int pl4 = (g * 4 + (q ^ fAg(g))) << 2;
    int base = blockIdx.x * 64;
    int r = tid >> 2, q4 = tid & 3;
    if (tid < 128) smf[F_PAR + tid] = bias[tid];
    int nr = min(base + r, NNODES - 1);
    const float* src = nodes + (size_t)nr * 288;

    // streamed GEMM over K=288: A streams through T[0]/T[1]
    float C[2][4][4];
    ZERO_C(C);
    copy_w_async(sb + F_W * 4, wE, tid); CP_COMMIT();
    stage_Af8(smf + F_T, src + q4 * 8, r, q4);
    CP_WAIT0(); __syncthreads();
#pragma unroll 1
    for (int c = 0; c < 9; c++) {
        if (c < 8) {
            int cn = c + 1;
            copy_w_async(sb + F_W * 4 + (cn & 1) * 16384, wE + cn * 4096, tid);
            CP_COMMIT();
            stage_Af8(smf + F_T + (cn & 1) * 2048, src + cn * 32 + q4 * 8, r, q4);
        }
        chunk_mma(smf + F_T + (c & 1) * 2048, smf + F_W + (c & 1) * 4096,
                  C, wm, wn, lane, pl4);
        CP_WAIT0();
        __syncthreads();
    }
    // h = C + bias (direct store), keep h in C for tails
#pragma unroll
    for (int mm = 0; mm < 2; mm++)
#pragma unroll
        for (int hx = 0; hx < 2; hx++) {
            int row = wm * 32 + mm * 16 + hx * 8 + g;
            float* ho = h + (size_t)(base + row) * DM;
#pragma unroll
            for (int nt = 0; nt < 4; nt++) {
                int col = wn * 32 + nt * 8 + q * 2;
                float v0 = C[mm][nt][hx * 2 + 0] + smf[F_PAR + col];
                float v1 = C[mm][nt][hx * 2 + 1] + smf[F_PAR + col + 1];
                if (base + row < NNODES)
                    *(float2*)(ho + col) = make_float2(v0, v1);
                C[mm][nt][hx * 2 + 0] = v0;
                C[mm][nt][hx * 2 + 1] = v1;
            }
        }
    write_T(C, smf, F_T, wm, wn, lane, 1);    // X = tf32(h)
    __syncthreads();
    ZERO_C(C);
    gemm_T4s(smf, sb, wS0, C, tid, wm, wn, lane, pl4);
    store_perm(C, hs0, base, wm, wn, g, q);
    ZERO_C(C);
    gemm_T4s(smf, sb, wR0, C, tid, wm, wn, lane, pl4);
    store_perm(C, hr0, base, wm, wn, g, q);
}

// ---------------- launch ------------------------------------------------------
extern "C" void kernel_launch(void* const* d_in, const int* in_sizes, int n_in,
                              void* d_out, int out_size)
{
    const float* nodes        = (const float*)d_in[0];
    const float* edges        = (const float*)d_in[1];
    const int*   senders      = (const int*)d_in[2];
    const int*   receivers    = (const int*)d_in[3];
    const float* w_node_emb   = (const float*)d_in[4];
    const float* b_node_emb   = (const float*)d_in[5];
    const float* w_edge_emb   = (const float*)d_in[6];
    const float* b_edge_emb   = (const float*)d_in[7];
    const float* edge_proj_w  = (const float*)d_in[8];
    const float* edge_proj_b  = (const float*)d_in[9];
    const float* node_proj_w  = (const float*)d_in[10];
    const float* node_proj_b  = (const float*)d_in[11];
    const float* edge_mlp_w   = (const float*)d_in[12];
    const float* edge_mlp_b   = (const float*)d_in[13];
    const float* edge_ln_g    = (const float*)d_in[14];
    const float* edge_ln_b    = (const float*)d_in[15];
    const float* node_mlp_w   = (const float*)d_in[16];
    const float* node_mlp_b   = (const float*)d_in[17];
    const float* node_ln_g    = (const float*)d_in[18];
    const float* node_ln_b    = (const float*)d_in[19];
    const float* mlp_out_w    = (const float*)d_in[20];
    const float* mlp_out_b    = (const float*)d_in[21];
    const float* mlp_out_g    = (const float*)d_in[22];
    const float* mlp_out_beta = (const float*)d_in[23];
    const float* proj_w       = (const float*)d_in[24];
    const float* proj_b       = (const float*)d_in[25];
    float* out = (float*)d_out;

    float *h, *e, *agg, *cnt, *wt, *hs, *hr, *cw;
    cudaGetSymbolAddress((void**)&h,   g_h);
    cudaGetSymbolAddress((void**)&e,   g_e);
    cudaGetSymbolAddress((void**)&agg, g_agg);
    cudaGetSymbolAddress((void**)&cnt, g_cnt);
    cudaGetSymbolAddress((void**)&wt,  g_wt);
    cudaGetSymbolAddress((void**)&hs,  g_hs);
    cudaGetSymbolAddress((void**)&hr,  g_hr);
    cudaGetSymbolAddress((void**)&cw,  g_cw);

    cudaFuncSetAttribute(edge_k, cudaFuncAttributeMaxDynamicSharedMemorySize, SMEMB);
    cudaFuncSetAttribute(node_k, cudaFuncAttributeMaxDynamicSharedMemorySize, SMEMB);
    cudaFuncSetAttribute(emb_k,  cudaFuncAttributeMaxDynamicSharedMemorySize, SMEMB);

    int nblk = (NNODES + 63) / 64;  // 313

    compose_k<<<1284, 128>>>(edge_proj_w, edge_proj_b, edge_mlp_w, edge_mlp_b,
                             node_proj_w, node_proj_b, node_mlp_w, node_mlp_b, cw);
    prep_frag<<<148, 256>>>(cw, edge_mlp_w, node_mlp_w, mlp_out_w, w_node_emb,
                            wt, cnt);
    count_kernel<<<(NEDGES + 255) / 256, 256>>>(receivers, cnt);
    zero_agg_k<<<2500, 256>>>((float4*)agg);
    emb_k<<<nblk, 256, SMEMB>>>(nodes, wt + W_EMB * 4096, b_node_emb, h,
                                hs, hr, wt + W_S0(0) * 4096, wt + W_R0(0) * 4096);
    for (int l = 0; l < 2; l++) {
        edge_k<<<NEDGES / 64, 256, SMEMB>>>(
            e, edges, senders, receivers, hs, hr,
            w_edge_emb, b_edge_emb,
            wt + W_E0(l) * 4096, cw + l * CWL + 81920,
            edge_ln_g + (l * 2 + 0) * 128, edge_ln_b + (l * 2 + 0) * 128,
            wt + W_M1E(l) * 4096, edge_mlp_b + (l * 2 + 1) * 128,
            edge_ln_g + (l * 2 + 1) * 128, edge_ln_b + (l * 2 + 1) * 128,
            agg, l == 0);
        node_k<<<nblk, 256, SMEMB>>>(
            h, agg, cnt,
            wt + W_N0(l) * 4096, cw + l * CWL + 82048,
            node_ln_g + (l * 2 + 0) * 128, node_ln_b + (l * 2 + 0) * 128,
            wt + W_M1N(l) * 4096, node_mlp_b + (l * 2 + 1) * 128,
            node_ln_g + (l * 2 + 1) * 128, node_ln_b + (l * 2 + 1) * 128,
            hs, hr, wt + W_S0(1) * 4096, wt + W_R0(1) * 4096, l == 0,
            wt + W_OUT * 4096, mlp_out_b, mlp_out_g, mlp_out_beta,
            proj_w, proj_b, out, l == 1);
        if (l == 0) zero_agg_k<<<2500, 256>>>((float4*)agg);
    }
}

// round 12
// speedup vs baseline: 3.2390x; 1.0688x over previous
#include <cuda_runtime.h>
#include <cstdint>

#define NNODES 20000
#define NEDGES 320000
#define DM 128
#define PREDL 24

// ---------------- device scratch ----------------------------------------------
__device__ float g_h[NNODES * DM];
__device__ float g_e[(size_t)NEDGES * DM];
__device__ float g_agg[NNODES * DM];
__device__ float g_cnt[NNODES];
__device__ float g_hs[NNODES * DM];     // (h @ Ws0) permuted
__device__ float g_hr[NNODES * DM];     // (h @ Wr0) permuted
#define CWL 82176
__device__ float g_cw[2 * CWL];         // composed weights (fp32)
__device__ float g_wt[69 * 4096];       // fragment-layout weights (tf32)

// g_wt chunk offsets
#define W_E0(l)  ((l) * 4)
#define W_M1E(l) (8 + (l) * 4)
#define W_N0(l)  (16 + (l) * 8)
#define W_M1N(l) (32 + (l) * 4)
#define W_S0(l)  (40 + (l) * 8)
#define W_R0(l)  (44 + (l) * 8)
#define W_OUT    56
#define W_EMB    60

// ---------------- smem float offsets (M=64 tile) --------------------------------
#define F_SUM 128               // 256
#define F_SQ  384               // 256
#define F_PAR 640               // 1152 params
#define F_W   1792              // 2 x 4096 W double buffer
#define F_T   (F_W + 8192)      // 4 x 2048 activation tile
#define SMEMB ((F_T + 8192) * 4)   // 72704 B -> 2 CTAs/SM

// ---------------- helpers ------------------------------------------------------
__device__ __forceinline__ uint32_t tfr(float x) {
    uint32_t r;
    asm("cvt.rna.tf32.f32 %0, %1;" : "=r"(r) : "f"(x));
    return r;
}
__device__ __forceinline__ float tff(float x) { return __uint_as_float(tfr(x)); }

__device__ __forceinline__ uint32_t smem_u32(const void* p) {
    uint32_t a;
    asm("{ .reg .u64 t; cvta.to.shared.u64 t, %1; cvt.u32.u64 %0, t; }"
        : "=r"(a) : "l"(p));
    return a;
}

__device__ __forceinline__ void mma8(float c[4], uint32_t a0, uint32_t a1,
                                     uint32_t a2, uint32_t a3,
                                     uint32_t b0, uint32_t b1) {
    asm volatile(
        "mma.sync.aligned.m16n8k8.row.col.f32.tf32.tf32.f32 "
        "{%0,%1,%2,%3}, {%4,%5,%6,%7}, {%8,%9}, {%0,%1,%2,%3};"
        : "+f"(c[0]), "+f"(c[1]), "+f"(c[2]), "+f"(c[3])
        : "r"(a0), "r"(a1), "r"(a2), "r"(a3), "r"(b0), "r"(b1));
}

// HW tanh (MUFU, sm_75+): max err ~1e-5, far below tf32 noise + 1e-3 budget
__device__ __forceinline__ float tanh_hw(float x) {
    float r;
    asm("tanh.approx.f32 %0, %1;" : "=f"(r) : "f"(x));
    return r;
}
__device__ __forceinline__ float geluf(float x) {
    float x3 = x * x * x;
    return 0.5f * x * (1.0f + tanh_hw(fmaf(0.044715f * 0.7978845608028654f, x3,
                                           0.7978845608028654f * x)));
}

__device__ __forceinline__ int fAg(int g) { return (g ^ (g >> 2)) & 3; }

// A-fragment index in a 2048-float chunk (64 rows x 32 k)
__device__ __forceinline__ int aidx(int row, int kl) {
    int wm = row >> 5, mm = (row >> 4) & 1, r8 = (row >> 3) & 1, g = row & 7;
    int kk = kl >> 3, k4 = (kl >> 2) & 1, tig = kl & 3;
    return (((kk * 2 + wm) * 2 + mm) << 7) + ((g * 4 + (tig ^ fAg(g))) << 2)
           + r8 + (k4 << 1);
}
// B-fragment index in a 4096-float chunk
__device__ __forceinline__ int bidx(int kl, int n) {
    int kk = kl >> 3, k4 = (kl >> 2) & 1, tig = kl & 3;
    int wn = n >> 5, ntp = (n >> 4) & 1, ntb = (n >> 3) & 1, gq = n & 7;
    return (((kk * 4 + wn) * 2 + ntp) << 7) + ((gq * 4 + tig) << 2)
           + ntb * 2 + k4;
}

#define CP16(daddr, src) asm volatile( \
    "cp.async.cg.shared.global [%0], [%1], 16;" :: "r"(daddr), "l"(src))
#define CP_COMMIT() asm volatile("cp.async.commit_group;" ::: "memory")
#define CP_WAIT0()  asm volatile("cp.async.wait_group 0;" ::: "memory")

// one 4096-float W chunk via cp.async (256 threads x 4 x 16B)
__device__ __forceinline__ void copy_w_async(uint32_t dsts,
                                             const float* __restrict__ src,
                                             int tid) {
    CP16(dsts + tid * 16, src + tid * 4);
    CP16(dsts + (tid + 256) * 16, src + (tid + 256) * 4);
    CP16(dsts + (tid + 512) * 16, src + (tid + 512) * 4);
    CP16(dsts + (tid + 768) * 16, src + (tid + 768) * 4);
}

// one 32-wide K chunk; warp covers 32 rows x 32 cols (A chunk = 2048 floats)
__device__ __forceinline__ void chunk_mma(const float* __restrict__ sA,
                                          const float* __restrict__ sW,
                                          float C[2][4][4], int wm, int wn,
                                          int lane, int pl4) {
#pragma unroll
    for (int kk = 0; kk < 4; kk++) {
        float4 b0 = *(const float4*)(sW + (((kk * 4 + wn) * 2 + 0) << 7)
                                     + (lane << 2));
        float4 b1 = *(const float4*)(sW + (((kk * 4 + wn) * 2 + 1) << 7)
                                     + (lane << 2));
#pragma unroll
        for (int mm = 0; mm < 2; mm++) {
            float4 av = *(const float4*)(sA + (((kk * 2 + wm) * 2 + mm) << 7) + pl4);
            uint32_t a0 = __float_as_uint(av.x), a1 = __float_as_uint(av.y);
            uint32_t a2 = __float_as_uint(av.z), a3 = __float_as_uint(av.w);
            mma8(C[mm][0], a0, a1, a2, a3,
                 __float_as_uint(b0.x), __float_as_uint(b0.y));
            mma8(C[mm][1], a0, a1, a2, a3,
                 __float_as_uint(b0.z), __float_as_uint(b0.w));
            mma8(C[mm][2], a0, a1, a2, a3,
                 __float_as_uint(b1.x), __float_as_uint(b1.y));
            mma8(C[mm][3], a0, a1, a2, a3,
                 __float_as_uint(b1.z), __float_as_uint(b1.w));
        }
    }
}

__device__ __forceinline__ void stage_Af8(float* chunk, const float* __restrict__ src,
                                          int r, int q4) {
    float4 v0 = *(const float4*)(src);
    float4 v1 = *(const float4*)(src + 4);
    chunk[aidx(r, q4 * 8 + 0)] = tff(v0.x);
    chunk[aidx(r, q4 * 8 + 1)] = tff(v0.y);
    chunk[aidx(r, q4 * 8 + 2)] = tff(v0.z);
    chunk[aidx(r, q4 * 8 + 3)] = tff(v0.w);
    chunk[aidx(r, q4 * 8 + 4)] = tff(v1.x);
    chunk[aidx(r, q4 * 8 + 5)] = tff(v1.y);
    chunk[aidx(r, q4 * 8 + 6)] = tff(v1.z);
    chunk[aidx(r, q4 * 8 + 7)] = tff(v1.w);
}
__device__ __forceinline__ void stage_Af8s(float* chunk, const float* __restrict__ src,
                                           int r, int q4, float sc) {
    float4 v0 = *(const float4*)(src);
    float4 v1 = *(const float4*)(src + 4);
    chunk[aidx(r, q4 * 8 + 0)] = tff(v0.x * sc);
    chunk[aidx(r, q4 * 8 + 1)] = tff(v0.y * sc);
    chunk[aidx(r, q4 * 8 + 2)] = tff(v0.z * sc);
    chunk[aidx(r, q4 * 8 + 3)] = tff(v0.w * sc);
    chunk[aidx(r, q4 * 8 + 4)] = tff(v1.x * sc);
    chunk[aidx(r, q4 * 8 + 5)] = tff(v1.y * sc);
    chunk[aidx(r, q4 * 8 + 6)] = tff(v1.z * sc);
    chunk[aidx(r, q4 * 8 + 7)] = tff(v1.w * sc);
}

// stage 32 cols of a row EXACT into A-frag chunk
__device__ __forceinline__ void stage_E32(float* chunk, const float* __restrict__ src,
                                          int r) {
#pragma unroll
    for (int i = 0; i < 8; i++) {
        float4 v = *(const float4*)(src + i * 4);
        chunk[aidx(r, i * 4 + 0)] = v.x;
        chunk[aidx(r, i * 4 + 1)] = v.y;
        chunk[aidx(r, i * 4 + 2)] = v.z;
        chunk[aidx(r, i * 4 + 3)] = v.w;
    }
}

__device__ __forceinline__ void write_T(float C[2][4][4], float* smf, int fbase,
                                        int wm, int wn, int lane, int cvt) {
    int g = lane >> 2, q = lane & 3;
#pragma unroll
    for (int mm = 0; mm < 2; mm++)
#pragma unroll
        for (int hx = 0; hx < 2; hx++) {
            int row = wm * 32 + mm * 16 + hx * 8 + g;
#pragma unroll
            for (int nt = 0; nt < 4; nt++)
#pragma unroll
                for (int s = 0; s < 2; s++) {
                    int col = wn * 32 + nt * 8 + q * 2 + s;
                    float v = C[mm][nt][hx * 2 + s];
                    smf[fbase + (col >> 5) * 2048 + aidx(row, col & 31)] =
                        cvt ? tff(v) : v;
                }
        }
}

__device__ __forceinline__ void gelu_ln_ep(float C[2][4][4], float* smf,
                                           int wm, int wn, int lane,
                                           int pb, int pg, int pbe) {
    int g = lane >> 2, q = lane & 3;
    float* sSum = smf + F_SUM;
    float* sSq  = smf + F_SQ;
#pragma unroll
    for (int mm = 0; mm < 2; mm++)
#pragma unroll
        for (int hx = 0; hx < 2; hx++) {
            float ps = 0.f, pq = 0.f;
#pragma unroll
            for (int nt = 0; nt < 4; nt++)
#pragma unroll
                for (int s = 0; s < 2; s++) {
                    int col = wn * 32 + nt * 8 + q * 2 + s;
                    float v = geluf(C[mm][nt][hx * 2 + s] + smf[pb + col]);
                    C[mm][nt][hx * 2 + s] = v;
                    ps += v; pq += v * v;
                }
            ps += __shfl_xor_sync(0xffffffffu, ps, 1);
            ps += __shfl_xor_sync(0xffffffffu, ps, 2);
            pq += __shfl_xor_sync(0xffffffffu, pq, 1);
            pq += __shfl_xor_sync(0xffffffffu, pq, 2);
            if (q == 0) {
                int row = wm * 32 + mm * 16 + hx * 8 + g;
                sSum[row * 4 + wn] = ps;
                sSq[row * 4 + wn]  = pq;
            }
        }
    __syncthreads();
#pragma unroll
    for (int mm = 0; mm < 2; mm++)
#pragma unroll
        for (int hx = 0; hx < 2; hx++) {
            int row = wm * 32 + mm * 16 + hx * 8 + g;
            float m = (sSum[row * 4] + sSum[row * 4 + 1]
                       + sSum[row * 4 + 2] + sSum[row * 4 + 3]) * (1.0f / 128.0f);
            float qv = (sSq[row * 4] + sSq[row * 4 + 1]
                        + sSq[row * 4 + 2] + sSq[row * 4 + 3]) * (1.0f / 128.0f);
            float rs = rsqrtf(qv - m * m + 1e-5f);
#pragma unroll
            for (int nt = 0; nt < 4; nt++)
#pragma unroll
                for (int s = 0; s < 2; s++) {
                    int col = wn * 32 + nt * 8 + q * 2 + s;
                    C[mm][nt][hx * 2 + s] =
                        (C[mm][nt][hx * 2 + s] - m) * rs * smf[pg + col] + smf[pbe + col];
                }
        }
}

#define ZERO_C(C) do { \
    _Pragma("unroll") for (int _m = 0; _m < 2; _m++) \
    _Pragma("unroll") for (int _n = 0; _n < 4; _n++) \
    _Pragma("unroll") for (int _s = 0; _s < 4; _s++) (C)[_m][_n][_s] = 0.f; } while (0)

// streamed K=128 GEMM: A resident in T chunks, W double-buffered
__device__ __forceinline__ void gemm_T4s(float* smf, uint32_t sb,
                                         const float* __restrict__ W,
                                         float C[2][4][4], int tid,
                                         int wm, int wn, int lane, int pl4) {
    copy_w_async(sb + F_W * 4, W, tid); CP_COMMIT();
    CP_WAIT0(); __syncthreads();
#pragma unroll 1
    for (int c = 0; c < 4; c++) {
        if (c < 3) {
            copy_w_async(sb + F_W * 4 + ((c + 1) & 1) * 16384, W + (c + 1) * 4096, tid);
            CP_COMMIT();
        }
        chunk_mma(smf + F_T + c * 2048, smf + F_W + (c & 1) * 4096,
                  C, wm, wn, lane, pl4);
        CP_WAIT0();
        __syncthreads();
    }
}

#define ROWBASE(r, rb, fg) \
    int rb = (((r) >> 5) * 2 + (((r) >> 4) & 1)) * 128 + ((r) & 7) * 16 \
             + (((r) >> 3) & 1); \
    int fg = fAg((r) & 7)
#define AFIDX(rb, fg, j) \
    (((j) >> 3) * 512 + (rb) + ((((j) & 3) ^ (fg)) << 2) + ((((j) >> 2) & 1) << 1))

#define RED2(p, a, b) asm volatile( \
    "red.global.add.v2.f32 [%0], {%1,%2};" :: "l"(p), "f"(a), "f"(b) : "memory")

// direct permuted store of C fragments to gout (matches edge gather layout)
__device__ __forceinline__ void store_perm(const float C[2][4][4],
                                           float* __restrict__ gout, int base,
                                           int wm, int wn, int g, int q) {
#pragma unroll
    for (int mm = 0; mm < 2; mm++)
#pragma unroll
        for (int hx = 0; hx < 2; hx++) {
            int row = wm * 32 + mm * 16 + hx * 8 + g;
            if (base + row >= NNODES) continue;
            float* go = gout + (size_t)(base + row) * DM + wn * 32 + q * 8;
            float4 f0, f1;
            f0.x = C[mm][0][hx * 2 + 0]; f0.y = C[mm][0][hx * 2 + 1];
            f0.z = C[mm][1][hx * 2 + 0]; f0.w = C[mm][1][hx * 2 + 1];
            f1.x = C[mm][2][hx * 2 + 0]; f1.y = C[mm][2][hx * 2 + 1];
            f1.z = C[mm][3][hx * 2 + 0]; f1.w = C[mm][3][hx * 2 + 1];
            *(float4*)go = f0;
            *(float4*)(go + 4) = f1;
        }
}

// ---------------- compose: fp32 weight products --------------------------------
__global__ void compose_k(const float* __restrict__ epw, const float* __restrict__ epb,
                          const float* __restrict__ emw, const float* __restrict__ emb_b,
                          const float* __restrict__ npw, const float* __restrict__ npb,
                          const float* __restrict__ nmw, const float* __restrict__ nmb,
                          float* __restrict__ cw) {
    int bi = blockIdx.x, j = threadIdx.x;
    int l = bi / 642, rr = bi % 642;
    const float *A, *B;
    float* out;
    float extra = 0.f;
    if (rr < 384) {
        A = epw + (size_t)l * 384 * 128 + rr * 128;
        B = emw + (l * 2) * 16384;
        out = cw + l * CWL + rr * 128;
    } else if (rr < 640) {
        int r2 = rr - 384;
        A = npw + (size_t)l * 256 * 128 + r2 * 128;
        B = nmw + (l * 2) * 16384;
        out = cw + l * CWL + 49152 + r2 * 128;
    } else if (rr == 640) {
        A = epb + l * 128; B = emw + (l * 2) * 16384;
        out = cw + l * CWL + 81920;
        extra = emb_b[(l * 2) * 128 + j];
    } else {
        A = npb + l * 128; B = nmw + (l * 2) * 16384;
        out = cw + l * CWL + 82048;
        extra = nmb[(l * 2) * 128 + j];
    }
    float acc = extra;
    for (int k = 0; k < 128; k++) acc += A[k] * B[k * 128 + j];
    out[j] = acc;
}

// ---------------- prep: all weights -> B-frag chunks; zero cnt -----------------
__global__ void prep_frag(const float* __restrict__ cw,
                          const float* __restrict__ emw,
                          const float* __restrict__ nmw,
                          const float* __restrict__ mow,
                          const float* __restrict__ wemb,
                          float* __restrict__ wt, float* __restrict__ cnt) {
    int b = blockIdx.x, tid = threadIdx.x;
    if (b < 69) {
        const float* M; int c;
        if (b < 8)       { int l = b >> 2; c = b & 3; M = cw + l * CWL; }
        else if (b < 16) { int l = (b - 8) >> 2; c = (b - 8) & 3;
                           M = emw + (l * 2 + 1) * 16384; }
        else if (b < 32) { int l = (b - 16) >> 3; c = (b - 16) & 7;
                           M = cw + l * CWL + 49152; }
        else if (b < 40) { int l = (b - 32) >> 2; c = (b - 32) & 3;
                           M = nmw + (l * 2 + 1) * 16384; }
        else if (b < 56) { int l = (b - 40) >> 3; int s = (b - 40) & 7;
                           c = s & 3; M = cw + l * CWL + 16384 + (s >> 2) * 16384; }
        else if (b < 60) { c = b - 56; M = mow; }
        else             { c = b - 60; M = wemb; }
        int kl = tid >> 3, n0 = (tid & 7) * 16;
#pragma unroll
        for (int j = 0; j < 16; j++) {
            int n = n0 + j;
            wt[b * 4096 + bidx(kl, n)] = tff(M[(c * 32 + kl) * 128 + n]);
        }
    } else {
        int i = (b - 69) * 256 + tid;
        if (i < NNODES) cnt[i] = 0.f;
    }
}

__global__ void count_kernel(const int* __restrict__ rcv, float* __restrict__ cnt) {
    int i = blockIdx.x * 256 + threadIdx.x;
    if (i < NEDGES) atomicAdd(cnt + rcv[i], 1.0f);
}

__global__ void zero_agg_k(float4* __restrict__ agg4) {
    int i = blockIdx.x * 256 + threadIdx.x;
    if (i < NNODES * 32) agg4[i] = make_float4(0.f, 0.f, 0.f, 0.f);
}

// ---------------- edge kernel (64 edges per CTA) --------------------------------
__global__ __launch_bounds__(256, 2) void edge_k(
    float* __restrict__ e, const float* __restrict__ edges,
    const int* __restrict__ snd, const int* __restrict__ rcv,
    const float* __restrict__ hs0, const float* __restrict__ hr0,
    const float* __restrict__ wem, const float* __restrict__ bem,
    const float* __restrict__ wE0, const float* __restrict__ b0c,
    const float* __restrict__ g0, const float* __restrict__ be0,
    const float* __restrict__ wM1, const float* __restrict__ b1,
    const float* __restrict__ g1, const float* __restrict__ be1,
    float* __restrict__ agg, int layer0)
{
    extern __shared__ float smf[];
    uint32_t sb = smem_u32(smf);
    int tid = threadIdx.x, lane = tid & 31, wid = tid >> 5;
    int wm = wid >> 2, wn = wid & 3;
    int g = lane >> 2, q = lane & 3;
    int pl4 = (g * 4 + (q ^ fAg(g))) << 2;
    int base = blockIdx.x * 64;
    int r = tid >> 2, q4 = tid & 3;
    int* sI = (int*)smf;
    if (tid < 64)        sI[tid] = snd[base + tid];
    else if (tid < 128)  sI[tid] = rcv[base + tid - 64];
    if (tid < 128) {
        float* p = smf + F_PAR;
        p[tid] = b0c[tid];       p[128 + tid] = g0[tid];
        p[256 + tid] = be0[tid]; p[384 + tid] = b1[tid];
        p[512 + tid] = g1[tid];  p[640 + tid] = be1[tid];
        if (layer0) {
            p[768 + tid]  = wem[tid];
            p[896 + tid]  = wem[128 + tid];
            p[1024 + tid] = bem[tid];
        }
    }
    if (layer0) {
        __syncthreads();   // wem/bem visible
        float2 xy = *(const float2*)(edges + 2 * (size_t)(base + r));
        const float* w0 = smf + F_PAR + 768;
        const float* w1 = smf + F_PAR + 896;
        const float* bb = smf + F_PAR + 1024;
        float* Tc = smf + F_T + q4 * 2048;
#pragma unroll
        for (int i = 0; i < 32; i++) {
            int col = q4 * 32 + i;
            Tc[aidx(r, i)] =
                tff(fmaf(xy.x, w0[col], fmaf(xy.y, w1[col], bb[col])));
        }
    } else {
        stage_E32(smf + F_T + q4 * 2048,
                  e + (size_t)(base + r) * DM + q4 * 32, r);
    }
    __syncthreads();

    // C init = gathered hs0p + hr0p (permuted layout, coalesced 32B)
    float C[2][4][4];
#pragma unroll
    for (int mm = 0; mm < 2; mm++)
#pragma unroll
        for (int hx = 0; hx < 2; hx++) {
            int row = wm * 32 + mm * 16 + hx * 8 + g;
            const float4* hp = (const float4*)(hs0 + (size_t)sI[row] * DM
                                               + wn * 32 + q * 8);
            const float4* rp = (const float4*)(hr0 + (size_t)sI[64 + row] * DM
                                               + wn * 32 + q * 8);
            float4 a0 = hp[0], a1 = hp[1], c0 = rp[0], c1 = rp[1];
            C[mm][0][hx * 2 + 0] = a0.x + c0.x;
            C[mm][0][hx * 2 + 1] = a0.y + c0.y;
            C[mm][1][hx * 2 + 0] = a0.z + c0.z;
            C[mm][1][hx * 2 + 1] = a0.w + c0.w;
            C[mm][2][hx * 2 + 0] = a1.x + c1.x;
            C[mm][2][hx * 2 + 1] = a1.y + c1.y;
            C[mm][3][hx * 2 + 0] = a1.z + c1.z;
            C[mm][3][hx * 2 + 1] = a1.w + c1.w;
        }

    gemm_T4s(smf, sb, wE0, C, tid, wm, wn, lane, pl4);   // += e @ We0
    gelu_ln_ep(C, smf, wm, wn, lane, F_PAR, F_PAR + 128, F_PAR + 256);
    write_T(C, smf, F_T, wm, wn, lane, 1);               // X over e tile
    __syncthreads();
    ZERO_C(C);
    gemm_T4s(smf, sb, wM1, C, tid, wm, wn, lane, pl4);   // MLP layer 1
    gelu_ln_ep(C, smf, wm, wn, lane, F_PAR + 384, F_PAR + 512, F_PAR + 640);

    // epilogue: residual (recomputed for layer0, re-read for layer1), scatter
    const float* w0 = smf + F_PAR + 768;
    const float* w1 = smf + F_PAR + 896;
    const float* bb = smf + F_PAR + 1024;
#pragma unroll
    for (int mm = 0; mm < 2; mm++)
#pragma unroll
        for (int hx = 0; hx < 2; hx++) {
            int row = wm * 32 + mm * 16 + hx * 8 + g;
            float ex0 = 0.f, ex1 = 0.f;
            if (layer0) {
                float2 xy = *(const float2*)(edges + 2 * (size_t)(base + row));
                ex0 = xy.x; ex1 = xy.y;
            }
            float* eo = e + (size_t)(base + row) * DM;
            float* ag = agg + (size_t)sI[64 + row] * DM;
#pragma unroll
            for (int nt = 0; nt < 4; nt++) {
                int col = wn * 32 + nt * 8 + q * 2;
                float r0v, r1v;
                if (layer0) {
                    r0v = fmaf(ex0, w0[col], fmaf(ex1, w1[col], bb[col]));
                    r1v = fmaf(ex0, w0[col + 1], fmaf(ex1, w1[col + 1], bb[col + 1]));
                } else {
                    float2 er = *(const float2*)(eo + col);
                    r0v = er.x; r1v = er.y;
                }
                float v0 = C[mm][nt][hx * 2 + 0] + r0v;
                float v1 = C[mm][nt][hx * 2 + 1] + r1v;
                if (layer0) *(float2*)(eo + col) = make_float2(v0, v1);
                RED2(ag + col, v0, v1);
            }
        }
}

// ---------------- node kernel (64 nodes per CTA) --------------------------------
__global__ __launch_bounds__(256, 2) void node_k(
    float* __restrict__ h, const float* __restrict__ agg,
    const float* __restrict__ cnt,
    const float* __restrict__ wN0, const float* __restrict__ bn0c,
    const float* __restrict__ g0, const float* __restrict__ be0,
    const float* __restrict__ wM1, const float* __restrict__ b1,
    const float* __restrict__ g1, const float* __restrict__ be1,
    float* __restrict__ hs0, float* __restrict__ hr0,
    const float* __restrict__ wS0, const float* __restrict__ wR0, int tail,
    const float* __restrict__ wO, const float* __restrict__ ob,
    const float* __restrict__ og, const float* __restrict__ obb,
    const float* __restrict__ pw, const float* __restrict__ pb,
    float* __restrict__ outp, int do_out)
{
    extern __shared__ float smf[];
    uint32_t sb = smem_u32(smf);
    int tid = threadIdx.x, lane = tid & 31, wid = tid >> 5;
    int wm = wid >> 2, wn = wid & 3;
    int g = lane >> 2, q = lane & 3;
    int pl4 = (g * 4 + (q ^ fAg(g))) << 2;
    int base = blockIdx.x * 64;
    int r = tid >> 2, q4 = tid & 3;
    if (tid < 64) {
        int n = min(base + tid, NNODES - 1);
        smf[tid] = 1.0f / fmaxf(cnt[n], 1.0f);
    }
    if (tid < 128) {
        float* p = smf + F_PAR;
        p[tid] = bn0c[tid];      p[128 + tid] = g0[tid];
        p[256 + tid] = be0[tid]; p[384 + tid] = b1[tid];
        p[512 + tid] = g1[tid];  p[640 + tid] = be1[tid];
        if (do_out) {
            p[768 + tid]  = ob[tid];
            p[896 + tid]  = og[tid];
            p[1024 + tid] = obb[tid];
        }
    }
    int nr = min(base + r, NNODES - 1);
    stage_E32(smf + F_T + q4 * 2048, h + (size_t)nr * DM + q4 * 32, r);

    // GEMM1: K=256, agg chunks staged in-place into consumed T slots
    float C[2][4][4];
    ZERO_C(C);
    copy_w_async(sb + F_W * 4, wN0, tid); CP_COMMIT();
    CP_WAIT0(); __syncthreads();
#pragma unroll 1
    for (int c = 0; c < 8; c++) {
        if (c < 7) {
            int cn = c + 1;
            copy_w_async(sb + F_W * 4 + (cn & 1) * 16384, wN0 + cn * 4096, tid);
            CP_COMMIT();
            if (cn >= 4)
                stage_Af8s(smf + F_T + (cn & 3) * 2048,
                           agg + (size_t)nr * DM + ((cn & 3) << 5) + q4 * 8,
                           r, q4, smf[r]);
        }
        chunk_mma(smf + F_T + (c & 3) * 2048, smf + F_W + (c & 1) * 4096,
                  C, wm, wn, lane, pl4);
        CP_WAIT0();
        __syncthreads();
    }
    gelu_ln_ep(C, smf, wm, wn, lane, F_PAR, F_PAR + 128, F_PAR + 256);
    write_T(C, smf, F_T, wm, wn, lane, 1);
    __syncthreads();
    ZERO_C(C);
    gemm_T4s(smf, sb, wM1, C, tid, wm, wn, lane, pl4);   // MLP layer 1
    gelu_ln_ep(C, smf, wm, wn, lane, F_PAR + 384, F_PAR + 512, F_PAR + 640);

    // epilogue: h_new = C + h; store h unless final layer; keep h_new in C
#pragma unroll
    for (int mm = 0; mm < 2; mm++)
#pragma unroll
        for (int hx = 0; hx < 2; hx++) {
            int row = wm * 32 + mm * 16 + hx * 8 + g;
            if (base + row >= NNODES) continue;
            float* ho = h + (size_t)(base + row) * DM;
#pragma unroll
            for (int nt = 0; nt < 4; nt++) {
                int col = wn * 32 + nt * 8 + q * 2;
                float2 hv = *(const float2*)(ho + col);
                float v0 = C[mm][nt][hx * 2 + 0] + hv.x;
                float v1 = C[mm][nt][hx * 2 + 1] + hv.y;
                if (!do_out) *(float2*)(ho + col) = make_float2(v0, v1);
                C[mm][nt][hx * 2 + 0] = v0;
                C[mm][nt][hx * 2 + 1] = v1;
            }
        }

    if (tail) {
        __syncthreads();
        write_T(C, smf, F_T, wm, wn, lane, 1);     // X = tf32(h_new)
        __syncthreads();
        ZERO_C(C);
        gemm_T4s(smf, sb, wS0, C, tid, wm, wn, lane, pl4);
        store_perm(C, hs0, base, wm, wn, g, q);
        ZERO_C(C);
        gemm_T4s(smf, sb, wR0, C, tid, wm, wn, lane, pl4);
        store_perm(C, hr0, base, wm, wn, g, q);
    }
    if (do_out) {
        __syncthreads();
        write_T(C, smf, F_T, wm, wn, lane, 0);     // exact h_new
        __syncthreads();
        ZERO_C(C);
        gemm_T4s(smf, sb, wO, C, tid, wm, wn, lane, pl4);
        gelu_ln_ep(C, smf, wm, wn, lane, F_PAR + 768, F_PAR + 896, F_PAR + 1024);
        write_T(C, smf, F_T, wm, wn, lane, 0);
        float* sPw = smf + F_W;
        for (int i = tid; i < 128 * PREDL; i += 256) sPw[i] = pw[i];
        if (tid < PREDL) smf[F_W + 128 * PREDL + tid] = pb[tid];
        __syncthreads();
        if (base + r < NNODES) {
            ROWBASE(r, rb, fg);
            float acc[6];
#pragma unroll
            for (int j = 0; j < 6; j++)
                acc[j] = smf[F_W + 128 * PREDL + q4 * 6 + j];
#pragma unroll 1
            for (int ch = 0; ch < 4; ch++) {
                const float* X = smf + F_T + ch * 2048;
#pragma unroll
                for (int j = 0; j < 32; j++) {
                    float xv = X[AFIDX(rb, fg, j)];
                    const float* pr = sPw + (ch * 32 + j) * PREDL + q4 * 6;
#pragma unroll
                    for (int o = 0; o < 6; o++) acc[o] = fmaf(xv, pr[o], acc[o]);
                }
            }
            float* op = outp + (size_t)(base + r) * PREDL + q4 * 6;
#pragma unroll
            for (int j = 0; j < 6; j++) op[j] = acc[j];
        }
    }
}

// ---------------- node embedding (+ permuted hs0/hr0 for layer 0) ---------------
__global__ __launch_bounds__(256, 2) void emb_k(
    const float* __restrict__ nodes, const float* __restrict__ wE,
    const float* __restrict__ bias, float* __restrict__ h,
    float* __restrict__ hs0, float* __restrict__ hr0,
    const float* __restrict__ wS0, const float* __restrict__ wR0)
{
    extern __shared__ float smf[];
    uint32_t sb = smem_u32(smf);
    int tid = threadIdx.x, lane = tid & 31, wid = tid >> 5;
    int wm = wid >> 2, wn = wid & 3;
    int g = lane >> 2, q = lane & 3;
    int pl4 = (g * 4 + (q ^ fAg(g))) << 2;
    int base = blockIdx.x * 64;
    int r = tid >> 2, q4 = tid & 3;
    if (tid < 128) smf[F_PAR + tid] = bias[tid];
    int nr = min(base + r, NNODES - 1);
    const float* src = nodes + (size_t)nr * 288;

    // streamed GEMM over K=288: A streams through T[0]/T[1]
    float C[2][4][4];
    ZERO_C(C);
    copy_w_async(sb + F_W * 4, wE, tid); CP_COMMIT();
    stage_Af8(smf + F_T, src + q4 * 8, r, q4);
    CP_WAIT0(); __syncthreads();
#pragma unroll 1
    for (int c = 0; c < 9; c++) {
        if (c < 8) {
            int cn = c + 1;
            copy_w_async(sb + F_W * 4 + (cn & 1) * 16384, wE + cn * 4096, tid);
            CP_COMMIT();
            stage_Af8(smf + F_T + (cn & 1) * 2048, src + cn * 32 + q4 * 8, r, q4);
        }
        chunk_mma(smf + F_T + (c & 1) * 2048, smf + F_W + (c & 1) * 4096,
                  C, wm, wn, lane, pl4);
        CP_WAIT0();
        __syncthreads();
    }
    // h = C + bias (direct store), keep h in C for tails
#pragma unroll
    for (int mm = 0; mm < 2; mm++)
#pragma unroll
        for (int hx = 0; hx < 2; hx++) {
            int row = wm * 32 + mm * 16 + hx * 8 + g;
            float* ho = h + (size_t)(base + row) * DM;
#pragma unroll
            for (int nt = 0; nt < 4; nt++) {
                int col = wn * 32 + nt * 8 + q * 2;
                float v0 = C[mm][nt][hx * 2 + 0] + smf[F_PAR + col];
                float v1 = C[mm][nt][hx * 2 + 1] + smf[F_PAR + col + 1];
                if (base + row < NNODES)
                    *(float2*)(ho + col) = make_float2(v0, v1);
                C[mm][nt][hx * 2 + 0] = v0;
                C[mm][nt][hx * 2 + 1] = v1;
            }
        }
    write_T(C, smf, F_T, wm, wn, lane, 1);    // X = tf32(h)
    __syncthreads();
    ZERO_C(C);
    gemm_T4s(smf, sb, wS0, C, tid, wm, wn, lane, pl4);
    store_perm(C, hs0, base, wm, wn, g, q);
    ZERO_C(C);
    gemm_T4s(smf, sb, wR0, C, tid, wm, wn, lane, pl4);
    store_perm(C, hr0, base, wm, wn, g, q);
}

// ---------------- launch ------------------------------------------------------
extern "C" void kernel_launch(void* const* d_in, const int* in_sizes, int n_in,
                              void* d_out, int out_size)
{
    const float* nodes        = (const float*)d_in[0];
    const float* edges        = (const float*)d_in[1];
    const int*   senders      = (const int*)d_in[2];
    const int*   receivers    = (const int*)d_in[3];
    const float* w_node_emb   = (const float*)d_in[4];
    const float* b_node_emb   = (const float*)d_in[5];
    const float* w_edge_emb   = (const float*)d_in[6];
    const float* b_edge_emb   = (const float*)d_in[7];
    const float* edge_proj_w  = (const float*)d_in[8];
    const float* edge_proj_b  = (const float*)d_in[9];
    const float* node_proj_w  = (const float*)d_in[10];
    const float* node_proj_b  = (const float*)d_in[11];
    const float* edge_mlp_w   = (const float*)d_in[12];
    const float* edge_mlp_b   = (const float*)d_in[13];
    const float* edge_ln_g    = (const float*)d_in[14];
    const float* edge_ln_b    = (const float*)d_in[15];
    const float* node_mlp_w   = (const float*)d_in[16];
    const float* node_mlp_b   = (const float*)d_in[17];
    const float* node_ln_g    = (const float*)d_in[18];
    const float* node_ln_b    = (const float*)d_in[19];
    const float* mlp_out_w    = (const float*)d_in[20];
    const float* mlp_out_b    = (const float*)d_in[21];
    const float* mlp_out_g    = (const float*)d_in[22];
    const float* mlp_out_beta = (const float*)d_in[23];
    const float* proj_w       = (const float*)d_in[24];
    const float* proj_b       = (const float*)d_in[25];
    float* out = (float*)d_out;

    float *h, *e, *agg, *cnt, *wt, *hs, *hr, *cw;
    cudaGetSymbolAddress((void**)&h,   g_h);
    cudaGetSymbolAddress((void**)&e,   g_e);
    cudaGetSymbolAddress((void**)&agg, g_agg);
    cudaGetSymbolAddress((void**)&cnt, g_cnt);
    cudaGetSymbolAddress((void**)&wt,  g_wt);
    cudaGetSymbolAddress((void**)&hs,  g_hs);
    cudaGetSymbolAddress((void**)&hr,  g_hr);
    cudaGetSymbolAddress((void**)&cw,  g_cw);

    cudaFuncSetAttribute(edge_k, cudaFuncAttributeMaxDynamicSharedMemorySize, SMEMB);
    cudaFuncSetAttribute(node_k, cudaFuncAttributeMaxDynamicSharedMemorySize, SMEMB);
    cudaFuncSetAttribute(emb_k,  cudaFuncAttributeMaxDynamicSharedMemorySize, SMEMB);

    int nblk = (NNODES + 63) / 64;  // 313

    compose_k<<<1284, 128>>>(edge_proj_w, edge_proj_b, edge_mlp_w, edge_mlp_b,
                             node_proj_w, node_proj_b, node_mlp_w, node_mlp_b, cw);
    prep_frag<<<148, 256>>>(cw, edge_mlp_w, node_mlp_w, mlp_out_w, w_node_emb,
                            wt, cnt);
    count_kernel<<<(NEDGES + 255) / 256, 256>>>(receivers, cnt);
    zero_agg_k<<<2500, 256>>>((float4*)agg);
    emb_k<<<nblk, 256, SMEMB>>>(nodes, wt + W_EMB * 4096, b_node_emb, h,
                                hs, hr, wt + W_S0(0) * 4096, wt + W_R0(0) * 4096);
    for (int l = 0; l < 2; l++) {
        edge_k<<<NEDGES / 64, 256, SMEMB>>>(
            e, edges, senders, receivers, hs, hr,
            w_edge_emb, b_edge_emb,
            wt + W_E0(l) * 4096, cw + l * CWL + 81920,
            edge_ln_g + (l * 2 + 0) * 128, edge_ln_b + (l * 2 + 0) * 128,
            wt + W_M1E(l) * 4096, edge_mlp_b + (l * 2 + 1) * 128,
            edge_ln_g + (l * 2 + 1) * 128, edge_ln_b + (l * 2 + 1) * 128,
            agg, l == 0);
        node_k<<<nblk, 256, SMEMB>>>(
            h, agg, cnt,
            wt + W_N0(l) * 4096, cw + l * CWL + 82048,
            node_ln_g + (l * 2 + 0) * 128, node_ln_b + (l * 2 + 0) * 128,
            wt + W_M1N(l) * 4096, node_mlp_b + (l * 2 + 1) * 128,
            node_ln_g + (l * 2 + 1) * 128, node_ln_b + (l * 2 + 1) * 128,
            hs, hr, wt + W_S0(1) * 4096, wt + W_R0(1) * 4096, l == 0,
            wt + W_OUT * 4096, mlp_out_b, mlp_out_g, mlp_out_beta,
            proj_w, proj_b, out, l == 1);
        if (l == 0) zero_agg_k<<<2500, 256>>>((float4*)agg);
    }
}

// round 13
// speedup vs baseline: 3.4975x; 1.0798x over previous
#include <cuda_runtime.h>
#include <cstdint>

#define NNODES 20000
#define NEDGES 320000
#define DM 128
#define PREDL 24

// ---------------- device scratch ----------------------------------------------
__device__ float g_h[NNODES * DM];
__device__ float g_e[(size_t)NEDGES * DM];
__device__ float g_agg[NNODES * DM];
__device__ float g_cnt[NNODES];
__device__ float g_hs[NNODES * DM];     // (h @ Ws0) permuted
__device__ float g_hr[NNODES * DM];     // (h @ Wr0) permuted
#define CWL 82176
__device__ float g_cw[2 * CWL];         // composed weights (fp32)
__device__ float g_wt[69 * 4096];       // fragment-layout weights (tf32)

// g_wt chunk offsets
#define W_E0(l)  ((l) * 4)
#define W_M1E(l) (8 + (l) * 4)
#define W_N0(l)  (16 + (l) * 8)
#define W_M1N(l) (32 + (l) * 4)
#define W_S0(l)  (40 + (l) * 8)
#define W_R0(l)  (44 + (l) * 8)
#define W_OUT    56
#define W_EMB    60

// ---------------- smem float offsets (M=64 tile) --------------------------------
#define F_SUM 128               // 256
#define F_SQ  384               // 256
#define F_PAR 640               // 1152 params
#define F_W   1792              // 2 x 4096 W double buffer
#define F_T   (F_W + 8192)      // 4 x 2048 activation tile
#define SMEMB ((F_T + 8192) * 4)   // 72704 B -> 3 CTAs/SM (218KB < 228KB)

// ---------------- helpers ------------------------------------------------------
__device__ __forceinline__ uint32_t tfr(float x) {
    uint32_t r;
    asm("cvt.rna.tf32.f32 %0, %1;" : "=r"(r) : "f"(x));
    return r;
}
__device__ __forceinline__ float tff(float x) { return __uint_as_float(tfr(x)); }

__device__ __forceinline__ uint32_t smem_u32(const void* p) {
    uint32_t a;
    asm("{ .reg .u64 t; cvta.to.shared.u64 t, %1; cvt.u32.u64 %0, t; }"
        : "=r"(a) : "l"(p));
    return a;
}

__device__ __forceinline__ void mma8(float c[4], uint32_t a0, uint32_t a1,
                                     uint32_t a2, uint32_t a3,
                                     uint32_t b0, uint32_t b1) {
    asm volatile(
        "mma.sync.aligned.m16n8k8.row.col.f32.tf32.tf32.f32 "
        "{%0,%1,%2,%3}, {%4,%5,%6,%7}, {%8,%9}, {%0,%1,%2,%3};"
        : "+f"(c[0]), "+f"(c[1]), "+f"(c[2]), "+f"(c[3])
        : "r"(a0), "r"(a1), "r"(a2), "r"(a3), "r"(b0), "r"(b1));
}

// HW tanh (MUFU, sm_75+)
__device__ __forceinline__ float tanh_hw(float x) {
    float r;
    asm("tanh.approx.f32 %0, %1;" : "=f"(r) : "f"(x));
    return r;
}
__device__ __forceinline__ float geluf(float x) {
    float x3 = x * x * x;
    return 0.5f * x * (1.0f + tanh_hw(fmaf(0.044715f * 0.7978845608028654f, x3,
                                           0.7978845608028654f * x)));
}

__device__ __forceinline__ int fAg(int g) { return (g ^ (g >> 2)) & 3; }

// A-fragment index in a 2048-float chunk (64 rows x 32 k)
__device__ __forceinline__ int aidx(int row, int kl) {
    int wm = row >> 5, mm = (row >> 4) & 1, r8 = (row >> 3) & 1, g = row & 7;
    int kk = kl >> 3, k4 = (kl >> 2) & 1, tig = kl & 3;
    return (((kk * 2 + wm) * 2 + mm) << 7) + ((g * 4 + (tig ^ fAg(g))) << 2)
           + r8 + (k4 << 1);
}
// B-fragment index in a 4096-float chunk
__device__ __forceinline__ int bidx(int kl, int n) {
    int kk = kl >> 3, k4 = (kl >> 2) & 1, tig = kl & 3;
    int wn = n >> 5, ntp = (n >> 4) & 1, ntb = (n >> 3) & 1, gq = n & 7;
    return (((kk * 4 + wn) * 2 + ntp) << 7) + ((gq * 4 + tig) << 2)
           + ntb * 2 + k4;
}

#define CP16(daddr, src) asm volatile( \
    "cp.async.cg.shared.global [%0], [%1], 16;" :: "r"(daddr), "l"(src))
#define CP_COMMIT() asm volatile("cp.async.commit_group;" ::: "memory")
#define CP_WAIT0()  asm volatile("cp.async.wait_group 0;" ::: "memory")

// one 4096-float W chunk via cp.async (256 threads x 4 x 16B)
__device__ __forceinline__ void copy_w_async(uint32_t dsts,
                                             const float* __restrict__ src,
                                             int tid) {
    CP16(dsts + tid * 16, src + tid * 4);
    CP16(dsts + (tid + 256) * 16, src + (tid + 256) * 4);
    CP16(dsts + (tid + 512) * 16, src + (tid + 512) * 4);
    CP16(dsts + (tid + 768) * 16, src + (tid + 768) * 4);
}

// one 32-wide K chunk; warp covers 32 rows x 32 cols (A chunk = 2048 floats)
__device__ __forceinline__ void chunk_mma(const float* __restrict__ sA,
                                          const float* __restrict__ sW,
                                          float C[2][4][4], int wm, int wn,
                                          int lane, int pl4) {
#pragma unroll
    for (int kk = 0; kk < 4; kk++) {
        float4 b0 = *(const float4*)(sW + (((kk * 4 + wn) * 2 + 0) << 7)
                                     + (lane << 2));
        float4 b1 = *(const float4*)(sW + (((kk * 4 + wn) * 2 + 1) << 7)
                                     + (lane << 2));
#pragma unroll
        for (int mm = 0; mm < 2; mm++) {
            float4 av = *(const float4*)(sA + (((kk * 2 + wm) * 2 + mm) << 7) + pl4);
            uint32_t a0 = __float_as_uint(av.x), a1 = __float_as_uint(av.y);
            uint32_t a2 = __float_as_uint(av.z), a3 = __float_as_uint(av.w);
            mma8(C[mm][0], a0, a1, a2, a3,
                 __float_as_uint(b0.x), __float_as_uint(b0.y));
            mma8(C[mm][1], a0, a1, a2, a3,
                 __float_as_uint(b0.z), __float_as_uint(b0.w));
            mma8(C[mm][2], a0, a1, a2, a3,
                 __float_as_uint(b1.x), __float_as_uint(b1.y));
            mma8(C[mm][3], a0, a1, a2, a3,
                 __float_as_uint(b1.z), __float_as_uint(b1.w));
        }
    }
}

__device__ __forceinline__ void stage_Af8(float* chunk, const float* __restrict__ src,
                                          int r, int q4) {
    float4 v0 = *(const float4*)(src);
    float4 v1 = *(const float4*)(src + 4);
    chunk[aidx(r, q4 * 8 + 0)] = tff(v0.x);
    chunk[aidx(r, q4 * 8 + 1)] = tff(v0.y);
    chunk[aidx(r, q4 * 8 + 2)] = tff(v0.z);
    chunk[aidx(r, q4 * 8 + 3)] = tff(v0.w);
    chunk[aidx(r, q4 * 8 + 4)] = tff(v1.x);
    chunk[aidx(r, q4 * 8 + 5)] = tff(v1.y);
    chunk[aidx(r, q4 * 8 + 6)] = tff(v1.z);
    chunk[aidx(r, q4 * 8 + 7)] = tff(v1.w);
}
__device__ __forceinline__ void stage_Af8s(float* chunk, const float* __restrict__ src,
                                           int r, int q4, float sc) {
    float4 v0 = *(const float4*)(src);
    float4 v1 = *(const float4*)(src + 4);
    chunk[aidx(r, q4 * 8 + 0)] = tff(v0.x * sc);
    chunk[aidx(r, q4 * 8 + 1)] = tff(v0.y * sc);
    chunk[aidx(r, q4 * 8 + 2)] = tff(v0.z * sc);
    chunk[aidx(r, q4 * 8 + 3)] = tff(v0.w * sc);
    chunk[aidx(r, q4 * 8 + 4)] = tff(v1.x * sc);
    chunk[aidx(r, q4 * 8 + 5)] = tff(v1.y * sc);
    chunk[aidx(r, q4 * 8 + 6)] = tff(v1.z * sc);
    chunk[aidx(r, q4 * 8 + 7)] = tff(v1.w * sc);
}

// stage 32 cols of a row EXACT into A-frag chunk
__device__ __forceinline__ void stage_E32(float* chunk, const float* __restrict__ src,
                                          int r) {
#pragma unroll
    for (int i = 0; i < 8; i++) {
        float4 v = *(const float4*)(src + i * 4);
        chunk[aidx(r, i * 4 + 0)] = v.x;
        chunk[aidx(r, i * 4 + 1)] = v.y;
        chunk[aidx(r, i * 4 + 2)] = v.z;
        chunk[aidx(r, i * 4 + 3)] = v.w;
    }
}

__device__ __forceinline__ void write_T(float C[2][4][4], float* smf, int fbase,
                                        int wm, int wn, int lane, int cvt) {
    int g = lane >> 2, q = lane & 3;
#pragma unroll
    for (int mm = 0; mm < 2; mm++)
#pragma unroll
        for (int hx = 0; hx < 2; hx++) {
            int row = wm * 32 + mm * 16 + hx * 8 + g;
#pragma unroll
            for (int nt = 0; nt < 4; nt++)
#pragma unroll
                for (int s = 0; s < 2; s++) {
                    int col = wn * 32 + nt * 8 + q * 2 + s;
                    float v = C[mm][nt][hx * 2 + s];
                    smf[fbase + (col >> 5) * 2048 + aidx(row, col & 31)] =
                        cvt ? tff(v) : v;
                }
        }
}

__device__ __forceinline__ void gelu_ln_ep(float C[2][4][4], float* smf,
                                           int wm, int wn, int lane,
                                           int pb, int pg, int pbe) {
    int g = lane >> 2, q = lane & 3;
    float* sSum = smf + F_SUM;
    float* sSq  = smf + F_SQ;
#pragma unroll
    for (int mm = 0; mm < 2; mm++)
#pragma unroll
        for (int hx = 0; hx < 2; hx++) {
            float ps = 0.f, pq = 0.f;
#pragma unroll
            for (int nt = 0; nt < 4; nt++)
#pragma unroll
                for (int s = 0; s < 2; s++) {
                    int col = wn * 32 + nt * 8 + q * 2 + s;
                    float v = geluf(C[mm][nt][hx * 2 + s] + smf[pb + col]);
                    C[mm][nt][hx * 2 + s] = v;
                    ps += v; pq += v * v;
                }
            ps += __shfl_xor_sync(0xffffffffu, ps, 1);
            ps += __shfl_xor_sync(0xffffffffu, ps, 2);
            pq += __shfl_xor_sync(0xffffffffu, pq, 1);
            pq += __shfl_xor_sync(0xffffffffu, pq, 2);
            if (q == 0) {
                int row = wm * 32 + mm * 16 + hx * 8 + g;
                sSum[row * 4 + wn] = ps;
                sSq[row * 4 + wn]  = pq;
            }
        }
    __syncthreads();
#pragma unroll
    for (int mm = 0; mm < 2; mm++)
#pragma unroll
        for (int hx = 0; hx < 2; hx++) {
            int row = wm * 32 + mm * 16 + hx * 8 + g;
            float m = (sSum[row * 4] + sSum[row * 4 + 1]
                       + sSum[row * 4 + 2] + sSum[row * 4 + 3]) * (1.0f / 128.0f);
            float qv = (sSq[row * 4] + sSq[row * 4 + 1]
                        + sSq[row * 4 + 2] + sSq[row * 4 + 3]) * (1.0f / 128.0f);
            float rs = rsqrtf(qv - m * m + 1e-5f);
#pragma unroll
            for (int nt = 0; nt < 4; nt++)
#pragma unroll
                for (int s = 0; s < 2; s++) {
                    int col = wn * 32 + nt * 8 + q * 2 + s;
                    C[mm][nt][hx * 2 + s] =
                        (C[mm][nt][hx * 2 + s] - m) * rs * smf[pg + col] + smf[pbe + col];
                }
        }
}

#define ZERO_C(C) do { \
    _Pragma("unroll") for (int _m = 0; _m < 2; _m++) \
    _Pragma("unroll") for (int _n = 0; _n < 4; _n++) \
    _Pragma("unroll") for (int _s = 0; _s < 4; _s++) (C)[_m][_n][_s] = 0.f; } while (0)

// streamed K=128 GEMM: A resident in T chunks, W double-buffered
__device__ __forceinline__ void gemm_T4s(float* smf, uint32_t sb,
                                         const float* __restrict__ W,
                                         float C[2][4][4], int tid,
                                         int wm, int wn, int lane, int pl4) {
    copy_w_async(sb + F_W * 4, W, tid); CP_COMMIT();
    CP_WAIT0(); __syncthreads();
#pragma unroll 1
    for (int c = 0; c < 4; c++) {
        if (c < 3) {
            copy_w_async(sb + F_W * 4 + ((c + 1) & 1) * 16384, W + (c + 1) * 4096, tid);
            CP_COMMIT();
        }
        chunk_mma(smf + F_T + c * 2048, smf + F_W + (c & 1) * 4096,
                  C, wm, wn, lane, pl4);
        CP_WAIT0();
        __syncthreads();
    }
}

#define ROWBASE(r, rb, fg) \
    int rb = (((r) >> 5) * 2 + (((r) >> 4) & 1)) * 128 + ((r) & 7) * 16 \
             + (((r) >> 3) & 1); \
    int fg = fAg((r) & 7)
#define AFIDX(rb, fg, j) \
    (((j) >> 3) * 512 + (rb) + ((((j) & 3) ^ (fg)) << 2) + ((((j) >> 2) & 1) << 1))

#define RED2(p, a, b) asm volatile( \
    "red.global.add.v2.f32 [%0], {%1,%2};" :: "l"(p), "f"(a), "f"(b) : "memory")

// direct permuted store of C fragments to gout (matches edge gather layout)
__device__ __forceinline__ void store_perm(const float C[2][4][4],
                                           float* __restrict__ gout, int base,
                                           int wm, int wn, int g, int q) {
#pragma unroll
    for (int mm = 0; mm < 2; mm++)
#pragma unroll
        for (int hx = 0; hx < 2; hx++) {
            int row = wm * 32 + mm * 16 + hx * 8 + g;
            if (base + row >= NNODES) continue;
            float* go = gout + (size_t)(base + row) * DM + wn * 32 + q * 8;
            float4 f0, f1;
            f0.x = C[mm][0][hx * 2 + 0]; f0.y = C[mm][0][hx * 2 + 1];
            f0.z = C[mm][1][hx * 2 + 0]; f0.w = C[mm][1][hx * 2 + 1];
            f1.x = C[mm][2][hx * 2 + 0]; f1.y = C[mm][2][hx * 2 + 1];
            f1.z = C[mm][3][hx * 2 + 0]; f1.w = C[mm][3][hx * 2 + 1];
            *(float4*)go = f0;
            *(float4*)(go + 4) = f1;
        }
}

// ---------------- compose: fp32 weight products --------------------------------
__global__ void compose_k(const float* __restrict__ epw, const float* __restrict__ epb,
                          const float* __restrict__ emw, const float* __restrict__ emb_b,
                          const float* __restrict__ npw, const float* __restrict__ npb,
                          const float* __restrict__ nmw, const float* __restrict__ nmb,
                          float* __restrict__ cw) {
    int bi = blockIdx.x, j = threadIdx.x;
    int l = bi / 642, rr = bi % 642;
    const float *A, *B;
    float* out;
    float extra = 0.f;
    if (rr < 384) {
        A = epw + (size_t)l * 384 * 128 + rr * 128;
        B = emw + (l * 2) * 16384;
        out = cw + l * CWL + rr * 128;
    } else if (rr < 640) {
        int r2 = rr - 384;
        A = npw + (size_t)l * 256 * 128 + r2 * 128;
        B = nmw + (l * 2) * 16384;
        out = cw + l * CWL + 49152 + r2 * 128;
    } else if (rr == 640) {
        A = epb + l * 128; B = emw + (l * 2) * 16384;
        out = cw + l * CWL + 81920;
        extra = emb_b[(l * 2) * 128 + j];
    } else {
        A = npb + l * 128; B = nmw + (l * 2) * 16384;
        out = cw + l * CWL + 82048;
        extra = nmb[(l * 2) * 128 + j];
    }
    float acc = extra;
    for (int k = 0; k < 128; k++) acc += A[k] * B[k * 128 + j];
    out[j] = acc;
}

// ---------------- prep: all weights -> B-frag chunks; zero cnt -----------------
__global__ void prep_frag(const float* __restrict__ cw,
                          const float* __restrict__ emw,
                          const float* __restrict__ nmw,
                          const float* __restrict__ mow,
                          const float* __restrict__ wemb,
                          float* __restrict__ wt, float* __restrict__ cnt) {
    int b = blockIdx.x, tid = threadIdx.x;
    if (b < 69) {
        const float* M; int c;
        if (b < 8)       { int l = b >> 2; c = b & 3; M = cw + l * CWL; }
        else if (b < 16) { int l = (b - 8) >> 2; c = (b - 8) & 3;
                           M = emw + (l * 2 + 1) * 16384; }
        else if (b < 32) { int l = (b - 16) >> 3; c = (b - 16) & 7;
                           M = cw + l * CWL + 49152; }
        else if (b < 40) { int l = (b - 32) >> 2; c = (b - 32) & 3;
                           M = nmw + (l * 2 + 1) * 16384; }
        else if (b < 56) { int l = (b - 40) >> 3; int s = (b - 40) & 7;
                           c = s & 3; M = cw + l * CWL + 16384 + (s >> 2) * 16384; }
        else if (b < 60) { c = b - 56; M = mow; }
        else             { c = b - 60; M = wemb; }
        int kl = tid >> 3, n0 = (tid & 7) * 16;
#pragma unroll
        for (int j = 0; j < 16; j++) {
            int n = n0 + j;
            wt[b * 4096 + bidx(kl, n)] = tff(M[(c * 32 + kl) * 128 + n]);
        }
    } else {
        int i = (b - 69) * 256 + tid;
        if (i < NNODES) cnt[i] = 0.f;
    }
}

// merged: zero agg (first 2500 blocks) + in-degree count (rest)
__global__ void init_k(float4* __restrict__ agg4, const int* __restrict__ rcv,
                       float* __restrict__ cnt, int do_count) {
    int b = blockIdx.x;
    if (b < 2500) {
        int i = b * 256 + threadIdx.x;
        if (i < NNODES * 32) agg4[i] = make_float4(0.f, 0.f, 0.f, 0.f);
    } else if (do_count) {
        int i = (b - 2500) * 256 + threadIdx.x;
        if (i < NEDGES) atomicAdd(cnt + rcv[i], 1.0f);
    }
}

// ---------------- edge kernel (64 edges per CTA) --------------------------------
__global__ __launch_bounds__(256, 3) void edge_k(
    float* __restrict__ e, const float* __restrict__ edges,
    const int* __restrict__ snd, const int* __restrict__ rcv,
    const float* __restrict__ hs0, const float* __restrict__ hr0,
    const float* __restrict__ wem, const float* __restrict__ bem,
    const float* __restrict__ wE0, const float* __restrict__ b0c,
    const float* __restrict__ g0, const float* __restrict__ be0,
    const float* __restrict__ wM1, const float* __restrict__ b1,
    const float* __restrict__ g1, const float* __restrict__ be1,
    float* __restrict__ agg, int layer0)
{
    extern __shared__ float smf[];
    uint32_t sb = smem_u32(smf);
    int tid = threadIdx.x, lane = tid & 31, wid = tid >> 5;
    int wm = wid >> 2, wn = wid & 3;
    int g = lane >> 2, q = lane & 3;
    int pl4 = (g * 4 + (q ^ fAg(g))) << 2;
    int base = blockIdx.x * 64;
    int r = tid >> 2, q4 = tid & 3;
    int* sI = (int*)smf;
    if (tid < 64)        sI[tid] = snd[base + tid];
    else if (tid < 128)  sI[tid] = rcv[base + tid - 64];
    if (tid < 128) {
        float* p = smf + F_PAR;
        p[tid] = b0c[tid];       p[128 + tid] = g0[tid];
        p[256 + tid] = be0[tid]; p[384 + tid] = b1[tid];
        p[512 + tid] = g1[tid];  p[640 + tid] = be1[tid];
        if (layer0) {
            p[768 + tid]  = wem[tid];
            p[896 + tid]  = wem[128 + tid];
            p[1024 + tid] = bem[tid];
        }
    }
    if (layer0) {
        __syncthreads();   // wem/bem visible
        float2 xy = *(const float2*)(edges + 2 * (size_t)(base + r));
        const float* w0 = smf + F_PAR + 768;
        const float* w1 = smf + F_PAR + 896;
        const float* bb = smf + F_PAR + 1024;
        float* Tc = smf + F_T + q4 * 2048;
#pragma unroll
        for (int i = 0; i < 32; i++) {
            int col = q4 * 32 + i;
            Tc[aidx(r, i)] =
                tff(fmaf(xy.x, w0[col], fmaf(xy.y, w1[col], bb[col])));
        }
    } else {
        stage_E32(smf + F_T + q4 * 2048,
                  e + (size_t)(base + r) * DM + q4 * 32, r);
    }
    __syncthreads();

    // C init = gathered hs0p + hr0p (permuted layout, coalesced 32B)
    float C[2][4][4];
#pragma unroll
    for (int mm = 0; mm < 2; mm++)
#pragma unroll
        for (int hx = 0; hx < 2; hx++) {
            int row = wm * 32 + mm * 16 + hx * 8 + g;
            const float4* hp = (const float4*)(hs0 + (size_t)sI[row] * DM
                                               + wn * 32 + q * 8);
            const float4* rp = (const float4*)(hr0 + (size_t)sI[64 + row] * DM
                                               + wn * 32 + q * 8);
            float4 a0 = hp[0], a1 = hp[1], c0 = rp[0], c1 = rp[1];
            C[mm][0][hx * 2 + 0] = a0.x + c0.x;
            C[mm][0][hx * 2 + 1] = a0.y + c0.y;
            C[mm][1][hx * 2 + 0] = a0.z + c0.z;
            C[mm][1][hx * 2 + 1] = a0.w + c0.w;
            C[mm][2][hx * 2 + 0] = a1.x + c1.x;
            C[mm][2][hx * 2 + 1] = a1.y + c1.y;
            C[mm][3][hx * 2 + 0] = a1.z + c1.z;
            C[mm][3][hx * 2 + 1] = a1.w + c1.w;
        }

    gemm_T4s(smf, sb, wE0, C, tid, wm, wn, lane, pl4);   // += e @ We0
    gelu_ln_ep(C, smf, wm, wn, lane, F_PAR, F_PAR + 128, F_PAR + 256);
    write_T(C, smf, F_T, wm, wn, lane, 1);               // X over e tile
    __syncthreads();
    ZERO_C(C);
    gemm_T4s(smf, sb, wM1, C, tid, wm, wn, lane, pl4);   // MLP layer 1
    gelu_ln_ep(C, smf, wm, wn, lane, F_PAR + 384, F_PAR + 512, F_PAR + 640);

    // epilogue: residual (recomputed for layer0, re-read for layer1), scatter
    const float* w0 = smf + F_PAR + 768;
    const float* w1 = smf + F_PAR + 896;
    const float* bb = smf + F_PAR + 1024;
#pragma unroll
    for (int mm = 0; mm < 2; mm++)
#pragma unroll
        for (int hx = 0; hx < 2; hx++) {
            int row = wm * 32 + mm * 16 + hx * 8 + g;
            float ex0 = 0.f, ex1 = 0.f;
            if (layer0) {
                float2 xy = *(const float2*)(edges + 2 * (size_t)(base + row));
                ex0 = xy.x; ex1 = xy.y;
            }
            float* eo = e + (size_t)(base + row) * DM;
            float* ag = agg + (size_t)sI[64 + row] * DM;
#pragma unroll
            for (int nt = 0; nt < 4; nt++) {
                int col = wn * 32 + nt * 8 + q * 2;
                float r0v, r1v;
                if (layer0) {
                    r0v = fmaf(ex0, w0[col], fmaf(ex1, w1[col], bb[col]));
                    r1v = fmaf(ex0, w0[col + 1], fmaf(ex1, w1[col + 1], bb[col + 1]));
                } else {
                    float2 er = *(const float2*)(eo + col);
                    r0v = er.x; r1v = er.y;
                }
                float v0 = C[mm][nt][hx * 2 + 0] + r0v;
                float v1 = C[mm][nt][hx * 2 + 1] + r1v;
                if (layer0) *(float2*)(eo + col) = make_float2(v0, v1);
                RED2(ag + col, v0, v1);
            }
        }
}

// ---------------- node kernel (64 nodes per CTA) --------------------------------
__global__ __launch_bounds__(256, 3) void node_k(
    float* __restrict__ h, const float* __restrict__ agg,
    const float* __restrict__ cnt,
    const float* __restrict__ wN0, const float* __restrict__ bn0c,
    const float* __restrict__ g0, const float* __restrict__ be0,
    const float* __restrict__ wM1, const float* __restrict__ b1,
    const float* __restrict__ g1, const float* __restrict__ be1,
    float* __restrict__ hs0, float* __restrict__ hr0,
    const float* __restrict__ wS0, const float* __restrict__ wR0, int tail,
    const float* __restrict__ wO, const float* __restrict__ ob,
    const float* __restrict__ og, const float* __restrict__ obb,
    const float* __restrict__ pw, const float* __restrict__ pb,
    float* __restrict__ outp, int do_out)
{
    extern __shared__ float smf[];
    uint32_t sb = smem_u32(smf);
    int tid = threadIdx.x, lane = tid & 31, wid = tid >> 5;
    int wm = wid >> 2, wn = wid & 3;
    int g = lane >> 2, q = lane & 3;
    int pl4 = (g * 4 + (q ^ fAg(g))) << 2;
    int base = blockIdx.x * 64;
    int r = tid >> 2, q4 = tid & 3;
    if (tid < 64) {
        int n = min(base + tid, NNODES - 1);
        smf[tid] = 1.0f / fmaxf(cnt[n], 1.0f);
    }
    if (tid < 128) {
        float* p = smf + F_PAR;
        p[tid] = bn0c[tid];      p[128 + tid] = g0[tid];
        p[256 + tid] = be0[tid]; p[384 + tid] = b1[tid];
        p[512 + tid] = g1[tid];  p[640 + tid] = be1[tid];
        if (do_out) {
            p[768 + tid]  = ob[tid];
            p[896 + tid]  = og[tid];
            p[1024 + tid] = obb[tid];
        }
    }
    int nr = min(base + r, NNODES - 1);
    stage_E32(smf + F_T + q4 * 2048, h + (size_t)nr * DM + q4 * 32, r);

    // GEMM1: K=256, agg chunks staged in-place into consumed T slots
    float C[2][4][4];
    ZERO_C(C);
    copy_w_async(sb + F_W * 4, wN0, tid); CP_COMMIT();
    CP_WAIT0(); __syncthreads();
#pragma unroll 1
    for (int c = 0; c < 8; c++) {
        if (c < 7) {
            int cn = c + 1;
            copy_w_async(sb + F_W * 4 + (cn & 1) * 16384, wN0 + cn * 4096, tid);
            CP_COMMIT();
            if (cn >= 4)
                stage_Af8s(smf + F_T + (cn & 3) * 2048,
                           agg + (size_t)nr * DM + ((cn & 3) << 5) + q4 * 8,
                           r, q4, smf[r]);
        }
        chunk_mma(smf + F_T + (c & 3) * 2048, smf + F_W + (c & 1) * 4096,
                  C, wm, wn, lane, pl4);
        CP_WAIT0();
        __syncthreads();
    }
    gelu_ln_ep(C, smf, wm, wn, lane, F_PAR, F_PAR + 128, F_PAR + 256);
    write_T(C, smf, F_T, wm, wn, lane, 1);
    __syncthreads();
    ZERO_C(C);
    gemm_T4s(smf, sb, wM1, C, tid, wm, wn, lane, pl4);   // MLP layer 1
    gelu_ln_ep(C, smf, wm, wn, lane, F_PAR + 384, F_PAR + 512, F_PAR + 640);

    // epilogue: h_new = C + h; store h unless final layer; keep h_new in C
#pragma unroll
    for (int mm = 0; mm < 2; mm++)
#pragma unroll
        for (int hx = 0; hx < 2; hx++) {
            int row = wm * 32 + mm * 16 + hx * 8 + g;
            if (base + row >= NNODES) continue;
            float* ho = h + (size_t)(base + row) * DM;
#pragma unroll
            for (int nt = 0; nt < 4; nt++) {
                int col = wn * 32 + nt * 8 + q * 2;
                float2 hv = *(const float2*)(ho + col);
                float v0 = C[mm][nt][hx * 2 + 0] + hv.x;
                float v1 = C[mm][nt][hx * 2 + 1] + hv.y;
                if (!do_out) *(float2*)(ho + col) = make_float2(v0, v1);
                C[mm][nt][hx * 2 + 0] = v0;
                C[mm][nt][hx * 2 + 1] = v1;
            }
        }

    if (tail) {
        __syncthreads();
        write_T(C, smf, F_T, wm, wn, lane, 1);     // X = tf32(h_new)
        __syncthreads();
        ZERO_C(C);
        gemm_T4s(smf, sb, wS0, C, tid, wm, wn, lane, pl4);
        store_perm(C, hs0, base, wm, wn, g, q);
        ZERO_C(C);
        gemm_T4s(smf, sb, wR0, C, tid, wm, wn, lane, pl4);
        store_perm(C, hr0, base, wm, wn, g, q);
    }
    if (do_out) {
        __syncthreads();
        write_T(C, smf, F_T, wm, wn, lane, 0);     // exact h_new
        __syncthreads();
        ZERO_C(C);
        gemm_T4s(smf, sb, wO, C, tid, wm, wn, lane, pl4);
        gelu_ln_ep(C, smf, wm, wn, lane, F_PAR + 768, F_PAR + 896, F_PAR + 1024);
        write_T(C, smf, F_T, wm, wn, lane, 0);
        float* sPw = smf + F_W;
        for (int i = tid; i < 128 * PREDL; i += 256) sPw[i] = pw[i];
        if (tid < PREDL) smf[F_W + 128 * PREDL + tid] = pb[tid];
        __syncthreads();
        if (base + r < NNODES) {
            ROWBASE(r, rb, fg);
            float acc[6];
#pragma unroll
            for (int j = 0; j < 6; j++)
                acc[j] = smf[F_W + 128 * PREDL + q4 * 6 + j];
#pragma unroll 1
            for (int ch = 0; ch < 4; ch++) {
                const float* X = smf + F_T + ch * 2048;
#pragma unroll
                for (int j = 0; j < 32; j++) {
                    float xv = X[AFIDX(rb, fg, j)];
                    const float* pr = sPw + (ch * 32 + j) * PREDL + q4 * 6;
#pragma unroll
                    for (int o = 0; o < 6; o++) acc[o] = fmaf(xv, pr[o], acc[o]);
                }
            }
            float* op = outp + (size_t)(base + r) * PREDL + q4 * 6;
#pragma unroll
            for (int j = 0; j < 6; j++) op[j] = acc[j];
        }
    }
}

// ---------------- node embedding (+ permuted hs0/hr0 for layer 0) ---------------
__global__ __launch_bounds__(256, 3) void emb_k(
    const float* __restrict__ nodes, const float* __restrict__ wE,
    const float* __restrict__ bias, float* __restrict__ h,
    float* __restrict__ hs0, float* __restrict__ hr0,
    const float* __restrict__ wS0, const float* __restrict__ wR0)
{
    extern __shared__ float smf[];
    uint32_t sb = smem_u32(smf);
    int tid = threadIdx.x, lane = tid & 31, wid = tid >> 5;
    int wm = wid >> 2, wn = wid & 3;
    int g = lane >> 2, q = lane & 3;
    int pl4 = (g * 4 + (q ^ fAg(g))) << 2;
    int base = blockIdx.x * 64;
    int r = tid >> 2, q4 = tid & 3;
    if (tid < 128) smf[F_PAR + tid] = bias[tid];
    int nr = min(base + r, NNODES - 1);
    const float* src = nodes + (size_t)nr * 288;

    // streamed GEMM over K=288: A streams through T[0]/T[1]
    float C[2][4][4];
    ZERO_C(C);
    copy_w_async(sb + F_W * 4, wE, tid); CP_COMMIT();
    stage_Af8(smf + F_T, src + q4 * 8, r, q4);
    CP_WAIT0(); __syncthreads();
#pragma unroll 1
    for (int c = 0; c < 9; c++) {
        if (c < 8) {
            int cn = c + 1;
            copy_w_async(sb + F_W * 4 + (cn & 1) * 16384, wE + cn * 4096, tid);
            CP_COMMIT();
            stage_Af8(smf + F_T + (cn & 1) * 2048, src + cn * 32 + q4 * 8, r, q4);
        }
        chunk_mma(smf + F_T + (c & 1) * 2048, smf + F_W + (c & 1) * 4096,
                  C, wm, wn, lane, pl4);
        CP_WAIT0();
        __syncthreads();
    }
    // h = C + bias (direct store), keep h in C for tails
#pragma unroll
    for (int mm = 0; mm < 2; mm++)
#pragma unroll
        for (int hx = 0; hx < 2; hx++) {
            int row = wm * 32 + mm * 16 + hx * 8 + g;
            float* ho = h + (size_t)(base + row) * DM;
#pragma unroll
            for (int nt = 0; nt < 4; nt++) {
                int col = wn * 32 + nt * 8 + q * 2;
                float v0 = C[mm][nt][hx * 2 + 0] + smf[F_PAR + col];
                float v1 = C[mm][nt][hx * 2 + 1] + smf[F_PAR + col + 1];
                if (base + row < NNODES)
                    *(float2*)(ho + col) = make_float2(v0, v1);
                C[mm][nt][hx * 2 + 0] = v0;
                C[mm][nt][hx * 2 + 1] = v1;
            }
        }
    write_T(C, smf, F_T, wm, wn, lane, 1);    // X = tf32(h)
    __syncthreads();
    ZERO_C(C);
    gemm_T4s(smf, sb, wS0, C, tid, wm, wn, lane, pl4);
    store_perm(C, hs0, base, wm, wn, g, q);
    ZERO_C(C);
    gemm_T4s(smf, sb, wR0, C, tid, wm, wn, lane, pl4);
    store_perm(C, hr0, base, wm, wn, g, q);
}

// ---------------- launch ------------------------------------------------------
extern "C" void kernel_launch(void* const* d_in, const int* in_sizes, int n_in,
                              void* d_out, int out_size)
{
    const float* nodes        = (const float*)d_in[0];
    const float* edges        = (const float*)d_in[1];
    const int*   senders      = (const int*)d_in[2];
    const int*   receivers    = (const int*)d_in[3];
    const float* w_node_emb   = (const float*)d_in[4];
    const float* b_node_emb   = (const float*)d_in[5];
    const float* w_edge_emb   = (const float*)d_in[6];
    const float* b_edge_emb   = (const float*)d_in[7];
    const float* edge_proj_w  = (const float*)d_in[8];
    const float* edge_proj_b  = (const float*)d_in[9];
    const float* node_proj_w  = (const float*)d_in[10];
    const float* node_proj_b  = (const float*)d_in[11];
    const float* edge_mlp_w   = (const float*)d_in[12];
    const float* edge_mlp_b   = (const float*)d_in[13];
    const float* edge_ln_g    = (const float*)d_in[14];
    const float* edge_ln_b    = (const float*)d_in[15];
    const float* node_mlp_w   = (const float*)d_in[16];
    const float* node_mlp_b   = (const float*)d_in[17];
    const float* node_ln_g    = (const float*)d_in[18];
    const float* node_ln_b    = (const float*)d_in[19];
    const float* mlp_out_w    = (const float*)d_in[20];
    const float* mlp_out_b    = (const float*)d_in[21];
    const float* mlp_out_g    = (const float*)d_in[22];
    const float* mlp_out_beta = (const float*)d_in[23];
    const float* proj_w       = (const float*)d_in[24];
    const float* proj_b       = (const float*)d_in[25];
    float* out = (float*)d_out;

    float *h, *e, *agg, *cnt, *wt, *hs, *hr, *cw;
    cudaGetSymbolAddress((void**)&h,   g_h);
    cudaGetSymbolAddress((void**)&e,   g_e);
    cudaGetSymbolAddress((void**)&agg, g_agg);
    cudaGetSymbolAddress((void**)&cnt, g_cnt);
    cudaGetSymbolAddress((void**)&wt,  g_wt);
    cudaGetSymbolAddress((void**)&hs,  g_hs);
    cudaGetSymbolAddress((void**)&hr,  g_hr);
    cudaGetSymbolAddress((void**)&cw,  g_cw);

    cudaFuncSetAttribute(edge_k, cudaFuncAttributeMaxDynamicSharedMemorySize, SMEMB);
    cudaFuncSetAttribute(node_k, cudaFuncAttributeMaxDynamicSharedMemorySize, SMEMB);
    cudaFuncSetAttribute(emb_k,  cudaFuncAttributeMaxDynamicSharedMemorySize, SMEMB);

    int nblk = (NNODES + 63) / 64;  // 313

    compose_k<<<1284, 128>>>(edge_proj_w, edge_proj_b, edge_mlp_w, edge_mlp_b,
                             node_proj_w, node_proj_b, node_mlp_w, node_mlp_b, cw);
    prep_frag<<<148, 256>>>(cw, edge_mlp_w, node_mlp_w, mlp_out_w, w_node_emb,
                            wt, cnt);
    init_k<<<2500 + (NEDGES + 255) / 256, 256>>>((float4*)agg, receivers, cnt, 1);
    emb_k<<<nblk, 256, SMEMB>>>(nodes, wt + W_EMB * 4096, b_node_emb, h,
                                hs, hr, wt + W_S0(0) * 4096, wt + W_R0(0) * 4096);
    for (int l = 0; l < 2; l++) {
        edge_k<<<NEDGES / 64, 256, SMEMB>>>(
            e, edges, senders, receivers, hs, hr,
            w_edge_emb, b_edge_emb,
            wt + W_E0(l) * 4096, cw + l * CWL + 81920,
            edge_ln_g + (l * 2 + 0) * 128, edge_ln_b + (l * 2 + 0) * 128,
            wt + W_M1E(l) * 4096, edge_mlp_b + (l * 2 + 1) * 128,
            edge_ln_g + (l * 2 + 1) * 128, edge_ln_b + (l * 2 + 1) * 128,
            agg, l == 0);
        node_k<<<nblk, 256, SMEMB>>>(
            h, agg, cnt,
            wt + W_N0(l) * 4096, cw + l * CWL + 82048,
            node_ln_g + (l * 2 + 0) * 128, node_ln_b + (l * 2 + 0) * 128,
            wt + W_M1N(l) * 4096, node_mlp_b + (l * 2 + 1) * 128,
            node_ln_g + (l * 2 + 1) * 128, node_ln_b + (l * 2 + 1) * 128,
            hs, hr, wt + W_S0(1) * 4096, wt + W_R0(1) * 4096, l == 0,
            wt + W_OUT * 4096, mlp_out_b, mlp_out_g, mlp_out_beta,
            proj_w, proj_b, out, l == 1);
        if (l == 0) init_k<<<2500, 256>>>((float4*)agg, receivers, cnt, 0);
    }
}